// round 12
// baseline (speedup 1.0000x reference)
#include <cuda_runtime.h>
#include <cuda_bf16.h>
#include <cstdint>

#define NN  50000
#define EE  800000
#define DD  512
#define KK  128
#define TJc 4
#define SSc 128
#define DD2 1024
#define EPSC 1e-5f

// ---------------- scratch (device globals) -----------------------------------
__device__ float g_xw  [(size_t)NN * DD];
__device__ float g_bufL[(size_t)NN * DD];
__device__ float g_v   [(size_t)NN * DD];
__device__ float g_bufA[(size_t)NN * DD];
__device__ float g_h   [(size_t)NN * DD];
__device__ float g_ff  [(size_t)NN * DD];
__device__ float g_evct[(size_t)NN * KK];
__device__ __nv_bfloat16 g_xb  [(size_t)NN * DD];
__device__ __nv_bfloat16 g_evcb[(size_t)NN * KK];
__device__ __nv_bfloat16 g_hb  [(size_t)NN * DD];
__device__ __nv_bfloat16 g_midb[(size_t)NN * DD2];
__device__ uint32_t g_gWbp [(DD / 2) * DD];
__device__ uint32_t g_f1Wbp[(DD / 2) * DD2];
__device__ uint32_t g_f2Wbp[(DD2 / 2) * DD];
__device__ uint32_t g_W2bp [(KK / 2) * DD];
__device__ uint32_t g_ubp  [(KK / 2) * DD];
__device__ float g_deg [NN];
__device__ int   g_degi[NN];
__device__ int   g_off [NN + 1];
__device__ int   g_cur [NN];
__device__ int   g_csrc[EE];
__device__ float g_esum[KK];
__device__ float g_xe  [KK * DD];
__device__ float g_uraw[KK * DD];
__device__ float g_u2  [KK * DD];
__device__ float g_W2  [KK * DD];
__device__ float g_stats[6 * DD];
__device__ float g_coef [6 * DD];
__device__ float g_linWp[DD * DD];
__device__ float g_fWt  [DD * DD];
__device__ int   g_is64;

// ---------------- helpers -----------------------------------------------------
__device__ __forceinline__ float tf32r(float f) {
    uint32_t u; asm("cvt.rna.tf32.f32 %0, %1;" : "=r"(u) : "f"(f));
    return __uint_as_float(u);
}
__device__ __forceinline__ uint32_t cvt_rna(uint32_t x) {
    uint32_t u; float f = __uint_as_float(x);
    asm("cvt.rna.tf32.f32 %0, %1;" : "=r"(u) : "f"(f)); return u;
}
__device__ __forceinline__ uint32_t packbf(float lo, float hi) {
    uint32_t r; asm("cvt.rn.bf16x2.f32 %0, %1, %2;" : "=r"(r) : "f"(hi), "f"(lo));
    return r;
}
__device__ __forceinline__ void mma_tf32(float* c, const uint32_t* a, const uint32_t* b) {
    asm volatile("mma.sync.aligned.m16n8k8.row.col.f32.tf32.tf32.f32 "
        "{%0,%1,%2,%3}, {%4,%5,%6,%7}, {%8,%9}, {%0,%1,%2,%3};"
        : "+f"(c[0]), "+f"(c[1]), "+f"(c[2]), "+f"(c[3])
        : "r"(a[0]), "r"(a[1]), "r"(a[2]), "r"(a[3]), "r"(b[0]), "r"(b[1]));
}
__device__ __forceinline__ void mma_bf16(float* c, const uint32_t* a, const uint32_t* b) {
    asm volatile("mma.sync.aligned.m16n8k16.row.col.f32.bf16.bf16.f32 "
        "{%0,%1,%2,%3}, {%4,%5,%6,%7}, {%8,%9}, {%0,%1,%2,%3};"
        : "+f"(c[0]), "+f"(c[1]), "+f"(c[2]), "+f"(c[3])
        : "r"(a[0]), "r"(a[1]), "r"(a[2]), "r"(a[3]), "r"(b[0]), "r"(b[1]));
}
__device__ __forceinline__ void cp16(void* sdst, const void* gsrc, bool pred) {
    uint32_t sa = (uint32_t)__cvta_generic_to_shared(sdst);
    int sz = pred ? 16 : 0;
    asm volatile("cp.async.cg.shared.global [%0], [%1], 16, %2;"
                 :: "r"(sa), "l"(gsrc), "r"(sz));
}
#define CP_COMMIT() asm volatile("cp.async.commit_group;")
#define CP_WAIT(n)  asm volatile("cp.async.wait_group %0;" :: "n"(n))

// ---------------- edge-index dtype detection --------------------------------
__global__ void detect_k(const int* __restrict__ ei32) {
    __shared__ int any;
    if (threadIdx.x == 0) any = 0;
    __syncthreads();
    int v = 0;
    for (int i = threadIdx.x; i < 1024; i += blockDim.x)
        v |= ei32[2 * i + 1];
    if (v) atomicOr(&any, 1);
    __syncthreads();
    if (threadIdx.x == 0) g_is64 = (any == 0) ? 1 : 0;
}
__device__ __forceinline__ int edge_at(const void* ei, long long pos) {
    return g_is64 ? (int)((const long long*)ei)[pos] : ((const int*)ei)[pos];
}

// ---------------- zero / round / pack helpers --------------------------------
__global__ void zero_scratch_k() {
    int stride = gridDim.x * blockDim.x;
    int i0 = blockIdx.x * blockDim.x + threadIdx.x;
    for (int i = i0; i < NN; i += stride) g_degi[i] = 0;
    for (int i = i0; i < KK * DD; i += stride) { g_xe[i] = 0.f; g_u2[i] = 0.f; }
    for (int i = i0; i < 6 * DD; i += stride) g_stats[i] = 0.f;
    for (int i = i0; i < KK; i += stride) g_esum[i] = 0.f;
}
__global__ void tobf_k(const float* __restrict__ in, __nv_bfloat16* __restrict__ o, long long n) {
    long long i = (long long)blockIdx.x * blockDim.x + threadIdx.x;
    long long stride = (long long)gridDim.x * blockDim.x;
    for (; i < n / 4; i += stride) {
        float4 v = reinterpret_cast<const float4*>(in)[i];
        uint2 p = make_uint2(packbf(v.x, v.y), packbf(v.z, v.w));
        reinterpret_cast<uint2*>(o)[i] = p;
    }
}
__global__ void packpairs_k(const float* __restrict__ W, uint32_t* __restrict__ Wp,
                            int Ncols, int total) {
    int idx = blockIdx.x * blockDim.x + threadIdx.x;
    if (idx >= total) return;
    int kp = idx / Ncols, n = idx - kp * Ncols;
    Wp[idx] = packbf(W[(size_t)(2 * kp) * Ncols + n], W[(size_t)(2 * kp + 1) * Ncols + n]);
}
// fused evc prep: evct (tf32), evcb (bf16), colsum — one read of evc
__global__ void prep_evc_k(const float* __restrict__ evc) {
    int c = threadIdx.x;                     // 128
    int r0 = blockIdx.x * 250;
    int r1 = min(r0 + 250, NN);
    float s = 0.f;
    for (int r = r0; r < r1; r++) {
        float v = evc[(size_t)r * KK + c];
        s += v;
        g_evct[(size_t)r * KK + c] = tf32r(v);
        g_evcb[(size_t)r * KK + c] = __float2bfloat16_rn(v);
    }
    atomicAdd(&g_esum[c], s);
}

// ---------------- bf16 tensor-core GEMM (k64 tiles, 3-stage pipeline) --------
template <bool BIAS, bool RELU, bool RND, bool OUTBF, bool ADDST>
__global__ void __launch_bounds__(256, 2) bfgemm_k(
    const __nv_bfloat16* __restrict__ A, int lda,
    const uint32_t* __restrict__ Bp, int ldb, long long bTs,
    void* __restrict__ Cv, int ldc, long long cTs,
    const float* __restrict__ bias,
    int M, int Kd,
    const float* __restrict__ Xadd, int bn)
{
    extern __shared__ uint32_t dynb[];
    uint32_t (*AsB)[128][36] = reinterpret_cast<uint32_t(*)[128][36]>(dynb);
    uint32_t (*BsB)[32][136] = reinterpret_cast<uint32_t(*)[32][136]>(dynb + 3 * 128 * 36);

    Bp += (long long)blockIdx.z * bTs;

    const int m0 = blockIdx.y * 128;
    const int n0 = blockIdx.x * 128;
    const int tid = threadIdx.x;
    const int lane = tid & 31;
    const int wid = tid >> 5;
    const int g = lane >> 2, t = lane & 3;
    const int wm0 = (wid & 1) * 64;
    const int wn0 = (wid >> 1) * 32;

    float acc[4][4][4] = {};
    const int T = Kd >> 6;

    auto load_tiles = [&](int it, int s) {
        int k0 = it * 64;
        #pragma unroll
        for (int l = 0; l < 4; l++) {
            int idx = tid + l * 256;
            int r = idx >> 3, ch = idx & 7;
            bool p = (m0 + r < M);
            int row = p ? (m0 + r) : 0;
            cp16(&AsB[s][r][ch * 4], &A[(size_t)row * lda + k0 + ch * 8], p);
        }
        #pragma unroll
        for (int l = 0; l < 4; l++) {
            int idx = tid + l * 256;
            int r = idx >> 5, c = (idx & 31) * 4;
            cp16(&BsB[s][r][c], &Bp[(size_t)(k0 / 2 + r) * ldb + n0 + c], true);
        }
    };

    load_tiles(0, 0);
    CP_COMMIT();
    if (T > 1) { load_tiles(1, 1); CP_COMMIT(); }

    for (int i = 0; i < T; i++) {
        int cur = i % 3;
        if (i + 1 < T) { CP_WAIT(1); } else { CP_WAIT(0); }
        __syncthreads();
        #pragma unroll
        for (int kk = 0; kk < 4; kk++) {
            uint32_t af[4][4], bf[4][2];
            #pragma unroll
            for (int mf = 0; mf < 4; mf++) {
                int mr = wm0 + mf * 16;
                af[mf][0] = AsB[cur][mr + g    ][kk * 8 + t];
                af[mf][1] = AsB[cur][mr + g + 8][kk * 8 + t];
                af[mf][2] = AsB[cur][mr + g    ][kk * 8 + t + 4];
                af[mf][3] = AsB[cur][mr + g + 8][kk * 8 + t + 4];
            }
            #pragma unroll
            for (int nf = 0; nf < 4; nf++) {
                bf[nf][0] = BsB[cur][kk * 8 + t    ][wn0 + nf * 8 + g];
                bf[nf][1] = BsB[cur][kk * 8 + t + 4][wn0 + nf * 8 + g];
            }
            #pragma unroll
            for (int mf = 0; mf < 4; mf++)
                #pragma unroll
                for (int nf = 0; nf < 4; nf++)
                    mma_bf16(acc[mf][nf], af[mf], bf[nf]);
        }
        if (i + 2 < T) { load_tiles(i + 2, (i + 2) % 3); CP_COMMIT(); }
    }

    float* C = (float*)Cv + (long long)blockIdx.z * cTs;
    __nv_bfloat16* Cb = (__nv_bfloat16*)Cv + (long long)blockIdx.z * cTs;
    float cs[4][2] = {}, cq[4][2] = {};

    #pragma unroll
    for (int mf = 0; mf < 4; mf++) {
        int row0 = m0 + wm0 + mf * 16 + g;
        int row1 = row0 + 8;
        #pragma unroll
        for (int nf = 0; nf < 4; nf++) {
            int n = n0 + wn0 + nf * 8 + 2 * t;
            float b0 = 0.f, b1 = 0.f;
            if (BIAS) { b0 = bias[n]; b1 = bias[n + 1]; }
            float2 v0 = make_float2(acc[mf][nf][0] + b0, acc[mf][nf][1] + b1);
            float2 v1 = make_float2(acc[mf][nf][2] + b0, acc[mf][nf][3] + b1);
            if (RELU) {
                v0.x = fmaxf(v0.x, 0.f); v0.y = fmaxf(v0.y, 0.f);
                v1.x = fmaxf(v1.x, 0.f); v1.y = fmaxf(v1.y, 0.f);
            }
            if (RND) {
                v0.x = tf32r(v0.x); v0.y = tf32r(v0.y);
                v1.x = tf32r(v1.x); v1.y = tf32r(v1.y);
            }
            if (row0 < M) {
                if (ADDST) {
                    v0.x += Xadd[(size_t)row0 * ldc + n];
                    v0.y += Xadd[(size_t)row0 * ldc + n + 1];
                    cs[nf][0] += v0.x; cq[nf][0] += v0.x * v0.x;
                    cs[nf][1] += v0.y; cq[nf][1] += v0.y * v0.y;
                }
                if (OUTBF) *reinterpret_cast<uint32_t*>(&Cb[(size_t)row0 * ldc + n]) = packbf(v0.x, v0.y);
                else       *reinterpret_cast<float2*>(&C[(size_t)row0 * ldc + n]) = v0;
            }
            if (row1 < M) {
                if (ADDST) {
                    v1.x += Xadd[(size_t)row1 * ldc + n];
                    v1.y += Xadd[(size_t)row1 * ldc + n + 1];
                    cs[nf][0] += v1.x; cq[nf][0] += v1.x * v1.x;
                    cs[nf][1] += v1.y; cq[nf][1] += v1.y * v1.y;
                }
                if (OUTBF) *reinterpret_cast<uint32_t*>(&Cb[(size_t)row1 * ldc + n]) = packbf(v1.x, v1.y);
                else       *reinterpret_cast<float2*>(&C[(size_t)row1 * ldc + n]) = v1;
            }
        }
    }

    if (ADDST) {
        #pragma unroll
        for (int nf = 0; nf < 4; nf++)
            #pragma unroll
            for (int c2 = 0; c2 < 2; c2++) {
                float s = cs[nf][c2], q = cq[nf][c2];
                #pragma unroll
                for (int off = 4; off < 32; off <<= 1) {
                    s += __shfl_xor_sync(0xffffffffu, s, off);
                    q += __shfl_xor_sync(0xffffffffu, q, off);
                }
                if (g == 0) {
                    int n = n0 + wn0 + nf * 8 + 2 * t + c2;
                    atomicAdd(&g_stats[(bn * 2 + 0) * DD + n], s);
                    atomicAdd(&g_stats[(bn * 2 + 1) * DD + n], q);
                }
            }
    }
}

// ---------------- tf32 GEMM (tiny 128-row GEMMs) -----------------------------
template <bool CVTA>
__global__ void __launch_bounds__(256, 2) tcgemm_k(
    const float* __restrict__ A, int lda,
    const float* __restrict__ B, int ldb,
    float* __restrict__ C, int ldc,
    int M, int Kd)
{
    extern __shared__ uint32_t dyn[];
    uint32_t (*As)[128][36]  = reinterpret_cast<uint32_t(*)[128][36]>(dyn);
    uint32_t (*Bs)[32][136]  = reinterpret_cast<uint32_t(*)[32][136]>(dyn + 2 * 128 * 36);

    const int m0 = blockIdx.y * 128;
    const int n0 = blockIdx.x * 128;
    const int tid = threadIdx.x;
    const int lane = tid & 31;
    const int wid = tid >> 5;
    const int g = lane >> 2, t = lane & 3;
    const int wm0 = (wid & 1) * 64;
    const int wn0 = (wid >> 1) * 32;

    float acc[4][4][4] = {};
    const int T = Kd >> 5;

    auto load_tiles = [&](int it, int s) {
        int k0 = it * 32;
        #pragma unroll
        for (int l = 0; l < 4; l++) {
            int idx = tid + l * 256;
            int r = idx >> 3, c = (idx & 7) * 4;
            bool p = (m0 + r < M);
            int row = p ? (m0 + r) : 0;
            cp16(&As[s][r][c], &A[(size_t)row * lda + k0 + c], p);
        }
        #pragma unroll
        for (int l = 0; l < 4; l++) {
            int idx = tid + l * 256;
            int r = idx >> 5, c = (idx & 31) * 4;
            cp16(&Bs[s][r][c], &B[(size_t)(k0 + r) * ldb + n0 + c], true);
        }
    };

    load_tiles(0, 0);
    CP_COMMIT();

    for (int i = 0; i < T; i++) {
        int cur = i & 1;
        if (i + 1 < T) { load_tiles(i + 1, cur ^ 1); CP_COMMIT(); CP_WAIT(1); }
        else          { CP_WAIT(0); }
        __syncthreads();
        #pragma unroll
        for (int kk = 0; kk < 4; kk++) {
            uint32_t af[4][4], bf[4][2];
            #pragma unroll
            for (int mf = 0; mf < 4; mf++) {
                int mr = wm0 + mf * 16;
                uint32_t a0 = As[cur][mr + g    ][kk * 8 + t];
                uint32_t a1 = As[cur][mr + g + 8][kk * 8 + t];
                uint32_t a2 = As[cur][mr + g    ][kk * 8 + t + 4];
                uint32_t a3 = As[cur][mr + g + 8][kk * 8 + t + 4];
                if (CVTA) { a0 = cvt_rna(a0); a1 = cvt_rna(a1); a2 = cvt_rna(a2); a3 = cvt_rna(a3); }
                af[mf][0] = a0; af[mf][1] = a1; af[mf][2] = a2; af[mf][3] = a3;
            }
            #pragma unroll
            for (int nf = 0; nf < 4; nf++) {
                bf[nf][0] = Bs[cur][kk * 8 + t    ][wn0 + nf * 8 + g];
                bf[nf][1] = Bs[cur][kk * 8 + t + 4][wn0 + nf * 8 + g];
            }
            #pragma unroll
            for (int mf = 0; mf < 4; mf++)
                #pragma unroll
                for (int nf = 0; nf < 4; nf++)
                    mma_tf32(acc[mf][nf], af[mf], bf[nf]);
        }
        __syncthreads();
    }

    #pragma unroll
    for (int mf = 0; mf < 4; mf++) {
        int row0 = m0 + wm0 + mf * 16 + g;
        int row1 = row0 + 8;
        #pragma unroll
        for (int nf = 0; nf < 4; nf++) {
            int n = n0 + wn0 + nf * 8 + 2 * t;
            float2 v0 = make_float2(acc[mf][nf][0], acc[mf][nf][1]);
            float2 v1 = make_float2(acc[mf][nf][2], acc[mf][nf][3]);
            if (row0 < M) *reinterpret_cast<float2*>(&C[(size_t)row0 * ldc + n]) = v0;
            if (row1 < M) *reinterpret_cast<float2*>(&C[(size_t)row1 * ldc + n]) = v1;
        }
    }
}

// ------- tf32 tall reduction: C[128, cols] += evc^T[128,N]*B[N,cols] --------
#define ATB_BLKS 64
template <bool CVTB>
__global__ void __launch_bounds__(256, 2) atb_k(
    const float* __restrict__ evc,
    const float* __restrict__ B, int ldb,
    float* __restrict__ C, int ldc)
{
    extern __shared__ uint32_t dyn[];
    uint32_t (*Es)[32][136] = reinterpret_cast<uint32_t(*)[32][136]>(dyn);
    uint32_t (*Hs)[32][136] = reinterpret_cast<uint32_t(*)[32][136]>(dyn + 2 * 32 * 136);

    const int noff = blockIdx.y * 128;

    const int chunk = (NN + ATB_BLKS - 1) / ATB_BLKS;
    const int nStart = blockIdx.x * chunk;
    const int nEnd = min(nStart + chunk, NN);
    const int iters = (chunk + 31) / 32;
    const int tid = threadIdx.x;
    const int lane = tid & 31;
    const int wid = tid >> 5;
    const int g = lane >> 2, t = lane & 3;
    const int wm0 = (wid & 1) * 64;
    const int wn0 = (wid >> 1) * 32;

    float acc[4][4][4] = {};

    auto load_tiles = [&](int it, int s) {
        int n0 = nStart + it * 32;
        #pragma unroll
        for (int l = 0; l < 4; l++) {
            int idx = tid + l * 256;
            int r = idx >> 5, c = (idx & 31) * 4;
            bool p = (n0 + r < nEnd);
            int row = p ? (n0 + r) : 0;
            cp16(&Es[s][r][c], &evc[(size_t)row * KK + c], p);
            cp16(&Hs[s][r][c], &B[(size_t)row * ldb + noff + c], p);
        }
    };

    load_tiles(0, 0);
    CP_COMMIT();

    for (int i = 0; i < iters; i++) {
        int cur = i & 1;
        if (i + 1 < iters) { load_tiles(i + 1, cur ^ 1); CP_COMMIT(); CP_WAIT(1); }
        else              { CP_WAIT(0); }
        __syncthreads();
        #pragma unroll
        for (int kk = 0; kk < 4; kk++) {
            uint32_t af[4][4], bf[4][2];
            #pragma unroll
            for (int mf = 0; mf < 4; mf++) {
                int mc = wm0 + mf * 16;
                af[mf][0] = Es[cur][kk * 8 + t    ][mc + g];
                af[mf][1] = Es[cur][kk * 8 + t    ][mc + g + 8];
                af[mf][2] = Es[cur][kk * 8 + t + 4][mc + g];
                af[mf][3] = Es[cur][kk * 8 + t + 4][mc + g + 8];
            }
            #pragma unroll
            for (int nf = 0; nf < 4; nf++) {
                uint32_t b0 = Hs[cur][kk * 8 + t    ][wn0 + nf * 8 + g];
                uint32_t b1 = Hs[cur][kk * 8 + t + 4][wn0 + nf * 8 + g];
                if (CVTB) { b0 = cvt_rna(b0); b1 = cvt_rna(b1); }
                bf[nf][0] = b0; bf[nf][1] = b1;
            }
            #pragma unroll
            for (int mf = 0; mf < 4; mf++)
                #pragma unroll
                for (int nf = 0; nf < 4; nf++)
                    mma_tf32(acc[mf][nf], af[mf], bf[nf]);
        }
        __syncthreads();
    }

    #pragma unroll
    for (int mf = 0; mf < 4; mf++) {
        int row0 = wm0 + mf * 16 + g;
        #pragma unroll
        for (int nf = 0; nf < 4; nf++) {
            int n = noff + wn0 + nf * 8 + 2 * t;
            float* p0 = &C[(size_t)row0 * ldc + n];
            float* p1 = &C[(size_t)(row0 + 8) * ldc + n];
            asm volatile("red.global.add.v2.f32 [%0], {%1,%2};"
                         :: "l"(p0), "f"(acc[mf][nf][0]), "f"(acc[mf][nf][1]) : "memory");
            asm volatile("red.global.add.v2.f32 [%0], {%1,%2};"
                         :: "l"(p1), "f"(acc[mf][nf][2]), "f"(acc[mf][nf][3]) : "memory");
        }
    }
}

// ---------------- graph: CSR build + gather ----------------------------------
__global__ void degi_k(const void* __restrict__ ei) {
    int e = blockIdx.x * blockDim.x + threadIdx.x;
    if (e < EE) atomicAdd(&g_degi[edge_at(ei, (long long)EE + e)], 1);
}
__global__ void dinv_k() {
    int n = blockIdx.x * blockDim.x + threadIdx.x;
    if (n < NN) g_deg[n] = rsqrtf((float)g_degi[n] + 1.0f);
}
__global__ void scan_k() {
    __shared__ int s[1024];
    int tid = threadIdx.x;
    const int per = (NN + 1023) / 1024;
    int start = tid * per, end = min(start + per, NN);
    int sum = 0;
    for (int i = start; i < end; i++) sum += g_degi[i];
    s[tid] = sum;
    __syncthreads();
    for (int off = 1; off < 1024; off <<= 1) {
        int v = 0;
        if (tid >= off) v = s[tid - off];
        __syncthreads();
        if (tid >= off) s[tid] += v;
        __syncthreads();
    }
    int base = s[tid] - sum;
    for (int i = start; i < end; i++) {
        g_off[i] = base; g_cur[i] = base;
        base += g_degi[i];
    }
    if (tid == 1023) g_off[NN] = base;
}
__global__ void fill_k(const void* __restrict__ ei) {
    int e = blockIdx.x * blockDim.x + threadIdx.x;
    if (e >= EE) return;
    int src = edge_at(ei, e);
    int dst = edge_at(ei, (long long)EE + e);
    int pos = atomicAdd(&g_cur[dst], 1);
    g_csrc[pos] = src;
}
__global__ void __launch_bounds__(128) gather_k(const float* __restrict__ x,
                                                const float* __restrict__ gcn_b) {
    const int n = blockIdx.x;
    const int c = threadIdx.x * 4;
    const int s0 = g_off[n], s1 = g_off[n + 1];
    const float dv = g_deg[n];
    float4 acc = make_float4(0.f, 0.f, 0.f, 0.f);
    int e = s0;
    #pragma unroll 1
    for (; e + 2 <= s1; e += 2) {
        int srcA = g_csrc[e], srcB = g_csrc[e + 1];
        float nA = dv * g_deg[srcA], nB = dv * g_deg[srcB];
        float4 vA = *reinterpret_cast<const float4*>(&g_xw[(size_t)srcA * DD + c]);
        float4 vB = *reinterpret_cast<const float4*>(&g_xw[(size_t)srcB * DD + c]);
        acc.x += nA * vA.x + nB * vB.x;
        acc.y += nA * vA.y + nB * vB.y;
        acc.z += nA * vA.z + nB * vB.z;
        acc.w += nA * vA.w + nB * vB.w;
    }
    if (e < s1) {
        int src = g_csrc[e];
        float nrm = dv * g_deg[src];
        float4 v = *reinterpret_cast<const float4*>(&g_xw[(size_t)src * DD + c]);
        acc.x += nrm * v.x; acc.y += nrm * v.y; acc.z += nrm * v.z; acc.w += nrm * v.w;
    }
    float4 xw = *reinterpret_cast<const float4*>(&g_xw[(size_t)n * DD + c]);
    float4 xr = *reinterpret_cast<const float4*>(&x[(size_t)n * DD + c]);
    float4 bb = *reinterpret_cast<const float4*>(&gcn_b[c]);
    float d2 = dv * dv;
    float4 o;
    o.x = xr.x + acc.x + d2 * xw.x + bb.x;
    o.y = xr.y + acc.y + d2 * xw.y + bb.y;
    o.z = xr.z + acc.z + d2 * xw.z + bb.z;
    o.w = xr.w + acc.w + d2 * xw.w + bb.w;
    *reinterpret_cast<float4*>(&g_bufL[(size_t)n * DD + c]) = o;
}
__global__ void stats0_k() {
    const int c = threadIdx.x;
    const int r0 = blockIdx.x * 128;
    const int rEnd = min(r0 + 128, NN);
    float s = 0.f, s2 = 0.f;
    for (int r = r0; r < rEnd; r++) {
        float v = g_bufL[(size_t)r * DD + c];
        s += v; s2 += v * v;
    }
    atomicAdd(&g_stats[0 * DD + c], s);
    atomicAdd(&g_stats[1 * DD + c], s2);
}

__global__ void finalize_k(int bn, const float* __restrict__ gamma, const float* __restrict__ beta) {
    int c = threadIdx.x;
    float s  = g_stats[(bn * 2 + 0) * DD + c];
    float s2 = g_stats[(bn * 2 + 1) * DD + c];
    float m = s * (1.0f / NN);
    float var = s2 * (1.0f / NN) - m * m;
    float a = gamma[c] * rsqrtf(var + EPSC);
    g_coef[(bn * 2 + 0) * DD + c] = a;
    g_coef[(bn * 2 + 1) * DD + c] = beta[c] - m * a;
}

__global__ void apply_sum_k() {
    int i = blockIdx.x * blockDim.x + threadIdx.x;
    if (i >= NN * DD / 2) return;
    int base = i * 2;
    int c = base & (DD - 1);
    float v0 = g_bufL[base] * g_coef[c] + g_coef[DD + c]
             + g_bufA[base] * g_coef[2 * DD + c] + g_coef[3 * DD + c];
    float v1 = g_bufL[base + 1] * g_coef[c + 1] + g_coef[DD + c + 1]
             + g_bufA[base + 1] * g_coef[2 * DD + c + 1] + g_coef[3 * DD + c + 1];
    g_h[base] = v0; g_h[base + 1] = v1;
    *reinterpret_cast<uint32_t*>(&g_hb[base]) = packbf(v0, v1);
}
__global__ void bn2_apply_k(float* __restrict__ out) {
    int idx = blockIdx.x * blockDim.x + threadIdx.x;
    if (idx >= NN * DD) return;
    int c = idx & (DD - 1);
    out[idx] = g_ff[idx] * g_coef[4 * DD + c] + g_coef[5 * DD + c];
}

// ---------------- wave helpers ----------------------------------------------
__global__ void pack_w_k(const float* __restrict__ linW, const float* __restrict__ fW) {
    int idx = blockIdx.x * blockDim.x + threadIdx.x;
    if (idx >= DD * DD) return;
    int d = idx >> 9, j = idx & 511;
    int t = j >> 7, s = j & 127;
    g_linWp[idx] = tf32r(linW[t * (DD * SSc) + d * SSc + s]);
    g_fWt[idx]   = tf32r(fW[idx]);
}
__global__ void post_u_k(const float* __restrict__ fs, const float* __restrict__ linB) {
    int idx = blockIdx.x * blockDim.x + threadIdx.x;
    if (idx >= (KK / 2) * DD) return;
    int kp = idx >> 9, j = idx & 511;
    int t = j >> 7, s = j & 127;
    float bl = linB[t * SSc + s];
    int k0 = 2 * kp, k1 = 2 * kp + 1;
    float v0 = fs[k0 * TJc + t] * (g_uraw[k0 * DD + j] + g_esum[k0] * bl);
    float v1 = fs[k1 * TJc + t] * (g_uraw[k1 * DD + j] + g_esum[k1] * bl);
    g_ubp[idx] = packbf(v0, v1);
}
__global__ void scale_u2_k(const float* __restrict__ fs) {
    int idx = blockIdx.x * blockDim.x + threadIdx.x;
    if (idx >= KK * DD) return;
    int k = idx >> 9, t = (idx & 511) >> 7;
    g_u2[idx] = tf32r(g_u2[idx] * fs[k * TJc + t]);
}

// ---------------- streams/events ----------------------------------------------
static cudaStream_t s_gcn = nullptr, s_aux = nullptr;
static cudaEvent_t ev_fork = nullptr, ev_xw = nullptr, ev_join = nullptr, ev_aux = nullptr;
namespace { struct StreamInit {
    StreamInit() {
        cudaStreamCreateWithFlags(&s_gcn, cudaStreamNonBlocking);
        cudaStreamCreateWithFlags(&s_aux, cudaStreamNonBlocking);
        cudaEventCreateWithFlags(&ev_fork, cudaEventDisableTiming);
        cudaEventCreateWithFlags(&ev_xw,   cudaEventDisableTiming);
        cudaEventCreateWithFlags(&ev_join, cudaEventDisableTiming);
        cudaEventCreateWithFlags(&ev_aux,  cudaEventDisableTiming);
    }
} s_init; }

// ---------------- launch -----------------------------------------------------
#define GSYM(p, ty, s) do { void* _t; cudaGetSymbolAddress(&_t, s); (p) = (ty)_t; } while (0)

extern "C" void kernel_launch(void* const* d_in, const int* in_sizes, int n_in,
                              void* d_out, int out_size) {
    const float* x        = (const float*)d_in[0];
    const void*  ei       = d_in[1];
    const float* evc      = (const float*)d_in[2];
    const float* fs       = (const float*)d_in[3];
    const float* gcn_W    = (const float*)d_in[4];
    const float* gcn_b    = (const float*)d_in[5];
    const float* lin_W    = (const float*)d_in[6];
    const float* lin_b    = (const float*)d_in[7];
    const float* fusion_W = (const float*)d_in[8];
    const float* fusion_b = (const float*)d_in[9];
    const float* bn1l_g   = (const float*)d_in[10];
    const float* bn1l_b   = (const float*)d_in[11];
    const float* bn1a_g   = (const float*)d_in[12];
    const float* bn1a_b   = (const float*)d_in[13];
    const float* bn2_g    = (const float*)d_in[14];
    const float* bn2_b    = (const float*)d_in[15];
    const float* ff1_W    = (const float*)d_in[16];
    const float* ff1_b    = (const float*)d_in[17];
    const float* ff2_W    = (const float*)d_in[18];
    const float* ff2_b    = (const float*)d_in[19];
    float* out = (float*)d_out;

    float *p_xw, *p_bufL, *p_v, *p_bufA, *p_h, *p_ff, *p_evct;
    float *p_xe, *p_uraw, *p_u2, *p_W2, *p_linWp, *p_fWt;
    __nv_bfloat16 *p_xb, *p_evcb, *p_hb, *p_midb;
    uint32_t *p_gWbp, *p_f1Wbp, *p_f2Wbp, *p_W2bp, *p_ubp;
    GSYM(p_xw, float*, g_xw);     GSYM(p_bufL, float*, g_bufL); GSYM(p_v, float*, g_v);
    GSYM(p_bufA, float*, g_bufA); GSYM(p_h, float*, g_h);       GSYM(p_ff, float*, g_ff);
    GSYM(p_evct, float*, g_evct);
    GSYM(p_xe, float*, g_xe);     GSYM(p_uraw, float*, g_uraw);
    GSYM(p_u2, float*, g_u2);     GSYM(p_W2, float*, g_W2);
    GSYM(p_linWp, float*, g_linWp); GSYM(p_fWt, float*, g_fWt);
    GSYM(p_xb, __nv_bfloat16*, g_xb);   GSYM(p_evcb, __nv_bfloat16*, g_evcb);
    GSYM(p_hb, __nv_bfloat16*, g_hb);   GSYM(p_midb, __nv_bfloat16*, g_midb);
    GSYM(p_gWbp, uint32_t*, g_gWbp);    GSYM(p_f1Wbp, uint32_t*, g_f1Wbp);
    GSYM(p_f2Wbp, uint32_t*, g_f2Wbp);  GSYM(p_W2bp, uint32_t*, g_W2bp);
    GSYM(p_ubp, uint32_t*, g_ubp);

    const int GEMM_SMEM = (2 * 128 * 36 + 2 * 32 * 136) * 4;   // 71680
    const int BF3_SMEM  = (3 * 128 * 36 + 3 * 32 * 136) * 4;   // 107520
    const int ATB_SMEM  = (2 * 32 * 136 * 2) * 4;
    cudaFuncSetAttribute(tcgemm_k<false>, cudaFuncAttributeMaxDynamicSharedMemorySize, GEMM_SMEM);
    cudaFuncSetAttribute(tcgemm_k<true>,  cudaFuncAttributeMaxDynamicSharedMemorySize, GEMM_SMEM);
    cudaFuncSetAttribute(atb_k<false>, cudaFuncAttributeMaxDynamicSharedMemorySize, ATB_SMEM);
    cudaFuncSetAttribute(atb_k<true>,  cudaFuncAttributeMaxDynamicSharedMemorySize, ATB_SMEM);
    cudaFuncSetAttribute(bfgemm_k<false, false, false, false, false>, cudaFuncAttributeMaxDynamicSharedMemorySize, BF3_SMEM);
    cudaFuncSetAttribute(bfgemm_k<false, true,  true,  false, false>, cudaFuncAttributeMaxDynamicSharedMemorySize, BF3_SMEM);
    cudaFuncSetAttribute(bfgemm_k<true,  true,  false, false, true >, cudaFuncAttributeMaxDynamicSharedMemorySize, BF3_SMEM);
    cudaFuncSetAttribute(bfgemm_k<true,  true,  false, true,  false>, cudaFuncAttributeMaxDynamicSharedMemorySize, BF3_SMEM);
    cudaFuncSetAttribute(bfgemm_k<true,  false, false, false, true >, cudaFuncAttributeMaxDynamicSharedMemorySize, BF3_SMEM);

    const int MB = (NN + 127) / 128;
    dim3 gD(4, MB);
    dim3 gF(8, MB);
    dim3 gTiny(4, 1);
    dim3 gAtbX(ATB_BLKS, 4, 1);
    dim3 gAtbU(ATB_BLKS, 4, 1);

    detect_k<<<1, 256>>>((const int*)ei);
    zero_scratch_k<<<1024, 256>>>();

    // ---- fork ----
    cudaEventRecord(ev_fork, 0);
    cudaStreamWaitEvent(s_gcn, ev_fork, 0);
    cudaStreamWaitEvent(s_aux, ev_fork, 0);

    // s_gcn: CSR build
    degi_k<<<(EE + 255) / 256, 256, 0, s_gcn>>>(ei);
    dinv_k<<<(NN + 255) / 256, 256, 0, s_gcn>>>();
    scan_k<<<1, 1024, 0, s_gcn>>>();
    fill_k<<<(EE + 255) / 256, 256, 0, s_gcn>>>(ei);

    // s_aux: weight packs needed later
    pack_w_k<<<(DD * DD + 255) / 256, 256, 0, s_aux>>>(lin_W, fusion_W);
    packpairs_k<<<((DD / 2) * DD2 + 255) / 256, 256, 0, s_aux>>>(ff1_W, p_f1Wbp, DD2, (DD / 2) * DD2);
    packpairs_k<<<((DD2 / 2) * DD + 255) / 256, 256, 0, s_aux>>>(ff2_W, p_f2Wbp, DD, (DD2 / 2) * DD);
    cudaEventRecord(ev_aux, s_aux);

    // main: prep + xw GEMM
    packpairs_k<<<((DD / 2) * DD + 255) / 256, 256>>>(gcn_W, p_gWbp, DD, (DD / 2) * DD);
    prep_evc_k<<<(NN + 249) / 250, KK>>>(evc);
    tobf_k<<<1024, 256>>>(x, p_xb, (long long)NN * DD);
    bfgemm_k<false, false, false, false, false><<<gD, 256, BF3_SMEM>>>(
        p_xb, DD, p_gWbp, DD, 0, p_xw, DD, 0, nullptr, NN, DD, nullptr, 0);
    cudaEventRecord(ev_xw, 0);

    // s_gcn: gather + BN0 stats (needs xw)
    cudaStreamWaitEvent(s_gcn, ev_xw, 0);
    gather_k<<<NN, 128, 0, s_gcn>>>(x, gcn_b);
    stats0_k<<<MB, DD, 0, s_gcn>>>();
    cudaEventRecord(ev_join, s_gcn);

    // main: wave branch
    atb_k<true><<<gAtbX, 256, ATB_SMEM>>>(p_evct, x, DD, p_xe, DD);
    cudaStreamWaitEvent(0, ev_aux, 0);
    tcgemm_k<true><<<gTiny, 256, GEMM_SMEM>>>(p_xe, DD, p_linWp, DD, p_uraw, DD, KK, DD);
    post_u_k<<<((KK / 2) * DD + 255) / 256, 256>>>(fs, lin_b);
    bfgemm_k<false, true, true, false, false><<<gD, 256, BF3_SMEM>>>(
        p_evcb, KK, p_ubp, DD, 0, p_v, DD, 0, nullptr, NN, KK, nullptr, 0);
    atb_k<false><<<gAtbU, 256, ATB_SMEM>>>(p_evct, p_v, DD, p_u2, DD);
    scale_u2_k<<<(KK * DD + 255) / 256, 256>>>(fs);
    tcgemm_k<false><<<gTiny, 256, GEMM_SMEM>>>(p_u2, DD, p_fWt, DD, p_W2, DD, KK, DD);
    packpairs_k<<<((KK / 2) * DD + 255) / 256, 256>>>(p_W2, p_W2bp, DD, (KK / 2) * DD);
    bfgemm_k<true, true, false, false, true><<<gD, 256, BF3_SMEM>>>(
        p_evcb, KK, p_W2bp, DD, 0, p_bufA, DD, 0, fusion_b, NN, KK, x, 1);

    // ---- join + BN ----
    cudaStreamWaitEvent(0, ev_join, 0);
    finalize_k<<<1, DD>>>(0, bn1l_g, bn1l_b);
    finalize_k<<<1, DD>>>(1, bn1a_g, bn1a_b);
    apply_sum_k<<<(NN * DD / 2 + 255) / 256, 256>>>();

    // ---- feed-forward ----
    bfgemm_k<true, true, false, true, false><<<gF, 256, BF3_SMEM>>>(
        p_hb, DD, p_f1Wbp, DD2, 0, p_midb, DD2, 0, ff1_b, NN, DD, nullptr, 0);
    bfgemm_k<true, false, false, false, true><<<gD, 256, BF3_SMEM>>>(
        p_midb, DD2, p_f2Wbp, DD, 0, p_ff, DD, 0, ff2_b, NN, DD2, p_h, 2);
    finalize_k<<<1, DD>>>(2, bn2_g, bn2_b);
    bn2_apply_k<<<(NN * DD + 255) / 256, 256>>>(out);
}

// round 13
// speedup vs baseline: 1.0250x; 1.0250x over previous
#include <cuda_runtime.h>
#include <cuda_bf16.h>
#include <cstdint>

#define NN  50000
#define EE  800000
#define DD  512
#define KK  128
#define TJc 4
#define SSc 128
#define DD2 1024
#define EPSC 1e-5f

// ---------------- scratch (device globals) -----------------------------------
__device__ float g_xw  [(size_t)NN * DD];
__device__ float g_bufL[(size_t)NN * DD];
__device__ float g_v   [(size_t)NN * DD];
__device__ float g_bufA[(size_t)NN * DD];
__device__ float g_h   [(size_t)NN * DD];
__device__ float g_ff  [(size_t)NN * DD];
__device__ float g_evct[(size_t)NN * KK];
__device__ __nv_bfloat16 g_xb  [(size_t)NN * DD];
__device__ __nv_bfloat16 g_evcb[(size_t)NN * KK];
__device__ __nv_bfloat16 g_hb  [(size_t)NN * DD];
__device__ __nv_bfloat16 g_midb[(size_t)NN * DD2];
__device__ uint32_t g_gWbp [(DD / 2) * DD];
__device__ uint32_t g_f1Wbp[(DD / 2) * DD2];
__device__ uint32_t g_f2Wbp[(DD2 / 2) * DD];
__device__ uint32_t g_W2bp [(KK / 2) * DD];
__device__ uint32_t g_ubp  [(KK / 2) * DD];
__device__ float g_deg [NN];
__device__ int   g_degi[NN];
__device__ int   g_off [NN + 1];
__device__ int   g_cur [NN];
__device__ int   g_csrc[EE];
__device__ float g_esum[KK];
__device__ float g_xe  [KK * DD];
__device__ float g_uraw[KK * DD];
__device__ float g_u2  [KK * DD];
__device__ float g_W2  [KK * DD];
__device__ float g_stats[6 * DD];
__device__ float g_coef [6 * DD];
__device__ float g_linWp[DD * DD];
__device__ float g_fWt  [DD * DD];
__device__ int   g_is64;

// ---------------- helpers -----------------------------------------------------
__device__ __forceinline__ float tf32r(float f) {
    uint32_t u; asm("cvt.rna.tf32.f32 %0, %1;" : "=r"(u) : "f"(f));
    return __uint_as_float(u);
}
__device__ __forceinline__ uint32_t cvt_rna(uint32_t x) {
    uint32_t u; float f = __uint_as_float(x);
    asm("cvt.rna.tf32.f32 %0, %1;" : "=r"(u) : "f"(f)); return u;
}
__device__ __forceinline__ uint32_t packbf(float lo, float hi) {
    uint32_t r; asm("cvt.rn.bf16x2.f32 %0, %1, %2;" : "=r"(r) : "f"(hi), "f"(lo));
    return r;
}
__device__ __forceinline__ void mma_tf32(float* c, const uint32_t* a, const uint32_t* b) {
    asm volatile("mma.sync.aligned.m16n8k8.row.col.f32.tf32.tf32.f32 "
        "{%0,%1,%2,%3}, {%4,%5,%6,%7}, {%8,%9}, {%0,%1,%2,%3};"
        : "+f"(c[0]), "+f"(c[1]), "+f"(c[2]), "+f"(c[3])
        : "r"(a[0]), "r"(a[1]), "r"(a[2]), "r"(a[3]), "r"(b[0]), "r"(b[1]));
}
__device__ __forceinline__ void mma_bf16(float* c, const uint32_t* a, const uint32_t* b) {
    asm volatile("mma.sync.aligned.m16n8k16.row.col.f32.bf16.bf16.f32 "
        "{%0,%1,%2,%3}, {%4,%5,%6,%7}, {%8,%9}, {%0,%1,%2,%3};"
        : "+f"(c[0]), "+f"(c[1]), "+f"(c[2]), "+f"(c[3])
        : "r"(a[0]), "r"(a[1]), "r"(a[2]), "r"(a[3]), "r"(b[0]), "r"(b[1]));
}
__device__ __forceinline__ void cp16(void* sdst, const void* gsrc, bool pred) {
    uint32_t sa = (uint32_t)__cvta_generic_to_shared(sdst);
    int sz = pred ? 16 : 0;
    asm volatile("cp.async.cg.shared.global [%0], [%1], 16, %2;"
                 :: "r"(sa), "l"(gsrc), "r"(sz));
}
#define CP_COMMIT() asm volatile("cp.async.commit_group;")
#define CP_WAIT(n)  asm volatile("cp.async.wait_group %0;" :: "n"(n))

// ---------------- edge-index dtype detection --------------------------------
__global__ void detect_k(const int* __restrict__ ei32) {
    __shared__ int any;
    if (threadIdx.x == 0) any = 0;
    __syncthreads();
    int v = 0;
    for (int i = threadIdx.x; i < 1024; i += blockDim.x)
        v |= ei32[2 * i + 1];
    if (v) atomicOr(&any, 1);
    __syncthreads();
    if (threadIdx.x == 0) g_is64 = (any == 0) ? 1 : 0;
}
__device__ __forceinline__ int edge_at(const void* ei, long long pos) {
    return g_is64 ? (int)((const long long*)ei)[pos] : ((const int*)ei)[pos];
}

// ---------------- zero / round / pack helpers --------------------------------
__global__ void zero_scratch_k() {
    int stride = gridDim.x * blockDim.x;
    int i0 = blockIdx.x * blockDim.x + threadIdx.x;
    for (int i = i0; i < NN; i += stride) g_degi[i] = 0;
    for (int i = i0; i < KK * DD; i += stride) { g_xe[i] = 0.f; g_u2[i] = 0.f; }
    for (int i = i0; i < 6 * DD; i += stride) g_stats[i] = 0.f;
    for (int i = i0; i < KK; i += stride) g_esum[i] = 0.f;
}
__global__ void tobf_k(const float* __restrict__ in, __nv_bfloat16* __restrict__ o, long long n) {
    long long i = (long long)blockIdx.x * blockDim.x + threadIdx.x;
    long long stride = (long long)gridDim.x * blockDim.x;
    for (; i < n / 4; i += stride) {
        float4 v = reinterpret_cast<const float4*>(in)[i];
        uint2 p = make_uint2(packbf(v.x, v.y), packbf(v.z, v.w));
        reinterpret_cast<uint2*>(o)[i] = p;
    }
}
__global__ void packpairs_k(const float* __restrict__ W, uint32_t* __restrict__ Wp,
                            int Ncols, int total) {
    int idx = blockIdx.x * blockDim.x + threadIdx.x;
    if (idx >= total) return;
    int kp = idx / Ncols, n = idx - kp * Ncols;
    Wp[idx] = packbf(W[(size_t)(2 * kp) * Ncols + n], W[(size_t)(2 * kp + 1) * Ncols + n]);
}
// fused evc prep: evct (tf32), evcb (bf16), colsum — one read of evc
__global__ void prep_evc_k(const float* __restrict__ evc) {
    int c = threadIdx.x;                     // 128
    int r0 = blockIdx.x * 250;
    int r1 = min(r0 + 250, NN);
    float s = 0.f;
    for (int r = r0; r < r1; r++) {
        float v = evc[(size_t)r * KK + c];
        s += v;
        g_evct[(size_t)r * KK + c] = tf32r(v);
        g_evcb[(size_t)r * KK + c] = __float2bfloat16_rn(v);
    }
    atomicAdd(&g_esum[c], s);
}

// ---------------- bf16 tensor-core GEMM (k64 tiles, 2-stage) -----------------
template <bool BIAS, bool RELU, bool RND, bool OUTBF, bool ADDST>
__global__ void __launch_bounds__(256, 2) bfgemm_k(
    const __nv_bfloat16* __restrict__ A, int lda,
    const uint32_t* __restrict__ Bp, int ldb, long long bTs,
    void* __restrict__ Cv, int ldc, long long cTs,
    const float* __restrict__ bias,
    int M, int Kd,
    const float* __restrict__ Xadd, int bn)
{
    extern __shared__ uint32_t dynb[];
    uint32_t (*AsB)[128][36] = reinterpret_cast<uint32_t(*)[128][36]>(dynb);
    uint32_t (*BsB)[32][136] = reinterpret_cast<uint32_t(*)[32][136]>(dynb + 2 * 128 * 36);

    Bp += (long long)blockIdx.z * bTs;

    const int m0 = blockIdx.y * 128;
    const int n0 = blockIdx.x * 128;
    const int tid = threadIdx.x;
    const int lane = tid & 31;
    const int wid = tid >> 5;
    const int g = lane >> 2, t = lane & 3;
    const int wm0 = (wid & 1) * 64;
    const int wn0 = (wid >> 1) * 32;

    float acc[4][4][4] = {};
    const int T = Kd >> 6;

    auto load_tiles = [&](int it, int s) {
        int k0 = it * 64;
        #pragma unroll
        for (int l = 0; l < 4; l++) {               // A: 128 x 64 bf16
            int idx = tid + l * 256;
            int r = idx >> 3, ch = idx & 7;
            bool p = (m0 + r < M);
            int row = p ? (m0 + r) : 0;
            cp16(&AsB[s][r][ch * 4], &A[(size_t)row * lda + k0 + ch * 8], p);
        }
        #pragma unroll
        for (int l = 0; l < 4; l++) {               // B: 32 pair-rows x 128 u32
            int idx = tid + l * 256;
            int r = idx >> 5, c = (idx & 31) * 4;
            cp16(&BsB[s][r][c], &Bp[(size_t)(k0 / 2 + r) * ldb + n0 + c], true);
        }
    };

    load_tiles(0, 0);
    CP_COMMIT();

    for (int i = 0; i < T; i++) {
        int cur = i & 1;
        if (i + 1 < T) { load_tiles(i + 1, cur ^ 1); CP_COMMIT(); CP_WAIT(1); }
        else          { CP_WAIT(0); }
        __syncthreads();
        #pragma unroll
        for (int kk = 0; kk < 4; kk++) {            // 4 x k16 per k64 tile
            uint32_t af[4][4], bf[4][2];
            #pragma unroll
            for (int mf = 0; mf < 4; mf++) {
                int mr = wm0 + mf * 16;
                af[mf][0] = AsB[cur][mr + g    ][kk * 8 + t];
                af[mf][1] = AsB[cur][mr + g + 8][kk * 8 + t];
                af[mf][2] = AsB[cur][mr + g    ][kk * 8 + t + 4];
                af[mf][3] = AsB[cur][mr + g + 8][kk * 8 + t + 4];
            }
            #pragma unroll
            for (int nf = 0; nf < 4; nf++) {
                bf[nf][0] = BsB[cur][kk * 8 + t    ][wn0 + nf * 8 + g];
                bf[nf][1] = BsB[cur][kk * 8 + t + 4][wn0 + nf * 8 + g];
            }
            #pragma unroll
            for (int mf = 0; mf < 4; mf++)
                #pragma unroll
                for (int nf = 0; nf < 4; nf++)
                    mma_bf16(acc[mf][nf], af[mf], bf[nf]);
        }
        __syncthreads();
    }

    float* C = (float*)Cv + (long long)blockIdx.z * cTs;
    __nv_bfloat16* Cb = (__nv_bfloat16*)Cv + (long long)blockIdx.z * cTs;
    float cs[4][2] = {}, cq[4][2] = {};

    #pragma unroll
    for (int mf = 0; mf < 4; mf++) {
        int row0 = m0 + wm0 + mf * 16 + g;
        int row1 = row0 + 8;
        #pragma unroll
        for (int nf = 0; nf < 4; nf++) {
            int n = n0 + wn0 + nf * 8 + 2 * t;
            float b0 = 0.f, b1 = 0.f;
            if (BIAS) { b0 = bias[n]; b1 = bias[n + 1]; }
            float2 v0 = make_float2(acc[mf][nf][0] + b0, acc[mf][nf][1] + b1);
            float2 v1 = make_float2(acc[mf][nf][2] + b0, acc[mf][nf][3] + b1);
            if (RELU) {
                v0.x = fmaxf(v0.x, 0.f); v0.y = fmaxf(v0.y, 0.f);
                v1.x = fmaxf(v1.x, 0.f); v1.y = fmaxf(v1.y, 0.f);
            }
            if (RND) {
                v0.x = tf32r(v0.x); v0.y = tf32r(v0.y);
                v1.x = tf32r(v1.x); v1.y = tf32r(v1.y);
            }
            if (row0 < M) {
                if (ADDST) {
                    v0.x += Xadd[(size_t)row0 * ldc + n];
                    v0.y += Xadd[(size_t)row0 * ldc + n + 1];
                    cs[nf][0] += v0.x; cq[nf][0] += v0.x * v0.x;
                    cs[nf][1] += v0.y; cq[nf][1] += v0.y * v0.y;
                }
                if (OUTBF) *reinterpret_cast<uint32_t*>(&Cb[(size_t)row0 * ldc + n]) = packbf(v0.x, v0.y);
                else       *reinterpret_cast<float2*>(&C[(size_t)row0 * ldc + n]) = v0;
            }
            if (row1 < M) {
                if (ADDST) {
                    v1.x += Xadd[(size_t)row1 * ldc + n];
                    v1.y += Xadd[(size_t)row1 * ldc + n + 1];
                    cs[nf][0] += v1.x; cq[nf][0] += v1.x * v1.x;
                    cs[nf][1] += v1.y; cq[nf][1] += v1.y * v1.y;
                }
                if (OUTBF) *reinterpret_cast<uint32_t*>(&Cb[(size_t)row1 * ldc + n]) = packbf(v1.x, v1.y);
                else       *reinterpret_cast<float2*>(&C[(size_t)row1 * ldc + n]) = v1;
            }
        }
    }

    if (ADDST) {
        #pragma unroll
        for (int nf = 0; nf < 4; nf++)
            #pragma unroll
            for (int c2 = 0; c2 < 2; c2++) {
                float s = cs[nf][c2], q = cq[nf][c2];
                #pragma unroll
                for (int off = 4; off < 32; off <<= 1) {
                    s += __shfl_xor_sync(0xffffffffu, s, off);
                    q += __shfl_xor_sync(0xffffffffu, q, off);
                }
                if (g == 0) {
                    int n = n0 + wn0 + nf * 8 + 2 * t + c2;
                    atomicAdd(&g_stats[(bn * 2 + 0) * DD + n], s);
                    atomicAdd(&g_stats[(bn * 2 + 1) * DD + n], q);
                }
            }
    }
}

// ---------------- tf32 GEMM (tiny 128-row GEMMs) -----------------------------
template <bool CVTA>
__global__ void __launch_bounds__(256, 2) tcgemm_k(
    const float* __restrict__ A, int lda,
    const float* __restrict__ B, int ldb,
    float* __restrict__ C, int ldc,
    int M, int Kd)
{
    extern __shared__ uint32_t dyn[];
    uint32_t (*As)[128][36]  = reinterpret_cast<uint32_t(*)[128][36]>(dyn);
    uint32_t (*Bs)[32][136]  = reinterpret_cast<uint32_t(*)[32][136]>(dyn + 2 * 128 * 36);

    const int m0 = blockIdx.y * 128;
    const int n0 = blockIdx.x * 128;
    const int tid = threadIdx.x;
    const int lane = tid & 31;
    const int wid = tid >> 5;
    const int g = lane >> 2, t = lane & 3;
    const int wm0 = (wid & 1) * 64;
    const int wn0 = (wid >> 1) * 32;

    float acc[4][4][4] = {};
    const int T = Kd >> 5;

    auto load_tiles = [&](int it, int s) {
        int k0 = it * 32;
        #pragma unroll
        for (int l = 0; l < 4; l++) {
            int idx = tid + l * 256;
            int r = idx >> 3, c = (idx & 7) * 4;
            bool p = (m0 + r < M);
            int row = p ? (m0 + r) : 0;
            cp16(&As[s][r][c], &A[(size_t)row * lda + k0 + c], p);
        }
        #pragma unroll
        for (int l = 0; l < 4; l++) {
            int idx = tid + l * 256;
            int r = idx >> 5, c = (idx & 31) * 4;
            cp16(&Bs[s][r][c], &B[(size_t)(k0 + r) * ldb + n0 + c], true);
        }
    };

    load_tiles(0, 0);
    CP_COMMIT();

    for (int i = 0; i < T; i++) {
        int cur = i & 1;
        if (i + 1 < T) { load_tiles(i + 1, cur ^ 1); CP_COMMIT(); CP_WAIT(1); }
        else          { CP_WAIT(0); }
        __syncthreads();
        #pragma unroll
        for (int kk = 0; kk < 4; kk++) {
            uint32_t af[4][4], bf[4][2];
            #pragma unroll
            for (int mf = 0; mf < 4; mf++) {
                int mr = wm0 + mf * 16;
                uint32_t a0 = As[cur][mr + g    ][kk * 8 + t];
                uint32_t a1 = As[cur][mr + g + 8][kk * 8 + t];
                uint32_t a2 = As[cur][mr + g    ][kk * 8 + t + 4];
                uint32_t a3 = As[cur][mr + g + 8][kk * 8 + t + 4];
                if (CVTA) { a0 = cvt_rna(a0); a1 = cvt_rna(a1); a2 = cvt_rna(a2); a3 = cvt_rna(a3); }
                af[mf][0] = a0; af[mf][1] = a1; af[mf][2] = a2; af[mf][3] = a3;
            }
            #pragma unroll
            for (int nf = 0; nf < 4; nf++) {
                bf[nf][0] = Bs[cur][kk * 8 + t    ][wn0 + nf * 8 + g];
                bf[nf][1] = Bs[cur][kk * 8 + t + 4][wn0 + nf * 8 + g];
            }
            #pragma unroll
            for (int mf = 0; mf < 4; mf++)
                #pragma unroll
                for (int nf = 0; nf < 4; nf++)
                    mma_tf32(acc[mf][nf], af[mf], bf[nf]);
        }
        __syncthreads();
    }

    #pragma unroll
    for (int mf = 0; mf < 4; mf++) {
        int row0 = m0 + wm0 + mf * 16 + g;
        int row1 = row0 + 8;
        #pragma unroll
        for (int nf = 0; nf < 4; nf++) {
            int n = n0 + wn0 + nf * 8 + 2 * t;
            float2 v0 = make_float2(acc[mf][nf][0], acc[mf][nf][1]);
            float2 v1 = make_float2(acc[mf][nf][2], acc[mf][nf][3]);
            if (row0 < M) *reinterpret_cast<float2*>(&C[(size_t)row0 * ldc + n]) = v0;
            if (row1 < M) *reinterpret_cast<float2*>(&C[(size_t)row1 * ldc + n]) = v1;
        }
    }
}

// ------- tf32 tall reduction: C[128, cols] += evc^T[128,N]*B[N,cols] --------
#define ATB_BLKS 64
template <bool CVTB>
__global__ void __launch_bounds__(256, 2) atb_k(
    const float* __restrict__ evc,
    const float* __restrict__ B, int ldb,
    float* __restrict__ C, int ldc)
{
    extern __shared__ uint32_t dyn[];
    uint32_t (*Es)[32][136] = reinterpret_cast<uint32_t(*)[32][136]>(dyn);
    uint32_t (*Hs)[32][136] = reinterpret_cast<uint32_t(*)[32][136]>(dyn + 2 * 32 * 136);

    const int noff = blockIdx.y * 128;

    const int chunk = (NN + ATB_BLKS - 1) / ATB_BLKS;
    const int nStart = blockIdx.x * chunk;
    const int nEnd = min(nStart + chunk, NN);
    const int iters = (chunk + 31) / 32;
    const int tid = threadIdx.x;
    const int lane = tid & 31;
    const int wid = tid >> 5;
    const int g = lane >> 2, t = lane & 3;
    const int wm0 = (wid & 1) * 64;
    const int wn0 = (wid >> 1) * 32;

    float acc[4][4][4] = {};

    auto load_tiles = [&](int it, int s) {
        int n0 = nStart + it * 32;
        #pragma unroll
        for (int l = 0; l < 4; l++) {
            int idx = tid + l * 256;
            int r = idx >> 5, c = (idx & 31) * 4;
            bool p = (n0 + r < nEnd);
            int row = p ? (n0 + r) : 0;
            cp16(&Es[s][r][c], &evc[(size_t)row * KK + c], p);
            cp16(&Hs[s][r][c], &B[(size_t)row * ldb + noff + c], p);
        }
    };

    load_tiles(0, 0);
    CP_COMMIT();

    for (int i = 0; i < iters; i++) {
        int cur = i & 1;
        if (i + 1 < iters) { load_tiles(i + 1, cur ^ 1); CP_COMMIT(); CP_WAIT(1); }
        else              { CP_WAIT(0); }
        __syncthreads();
        #pragma unroll
        for (int kk = 0; kk < 4; kk++) {
            uint32_t af[4][4], bf[4][2];
            #pragma unroll
            for (int mf = 0; mf < 4; mf++) {
                int mc = wm0 + mf * 16;
                af[mf][0] = Es[cur][kk * 8 + t    ][mc + g];
                af[mf][1] = Es[cur][kk * 8 + t    ][mc + g + 8];
                af[mf][2] = Es[cur][kk * 8 + t + 4][mc + g];
                af[mf][3] = Es[cur][kk * 8 + t + 4][mc + g + 8];
            }
            #pragma unroll
            for (int nf = 0; nf < 4; nf++) {
                uint32_t b0 = Hs[cur][kk * 8 + t    ][wn0 + nf * 8 + g];
                uint32_t b1 = Hs[cur][kk * 8 + t + 4][wn0 + nf * 8 + g];
                if (CVTB) { b0 = cvt_rna(b0); b1 = cvt_rna(b1); }
                bf[nf][0] = b0; bf[nf][1] = b1;
            }
            #pragma unroll
            for (int mf = 0; mf < 4; mf++)
                #pragma unroll
                for (int nf = 0; nf < 4; nf++)
                    mma_tf32(acc[mf][nf], af[mf], bf[nf]);
        }
        __syncthreads();
    }

    #pragma unroll
    for (int mf = 0; mf < 4; mf++) {
        int row0 = wm0 + mf * 16 + g;
        #pragma unroll
        for (int nf = 0; nf < 4; nf++) {
            int n = noff + wn0 + nf * 8 + 2 * t;
            float* p0 = &C[(size_t)row0 * ldc + n];
            float* p1 = &C[(size_t)(row0 + 8) * ldc + n];
            asm volatile("red.global.add.v2.f32 [%0], {%1,%2};"
                         :: "l"(p0), "f"(acc[mf][nf][0]), "f"(acc[mf][nf][1]) : "memory");
            asm volatile("red.global.add.v2.f32 [%0], {%1,%2};"
                         :: "l"(p1), "f"(acc[mf][nf][2]), "f"(acc[mf][nf][3]) : "memory");
        }
    }
}

// ---------------- graph: CSR build + gather ----------------------------------
__global__ void degi_k(const void* __restrict__ ei) {
    int e = blockIdx.x * blockDim.x + threadIdx.x;
    if (e < EE) atomicAdd(&g_degi[edge_at(ei, (long long)EE + e)], 1);
}
__global__ void dinv_k() {
    int n = blockIdx.x * blockDim.x + threadIdx.x;
    if (n < NN) g_deg[n] = rsqrtf((float)g_degi[n] + 1.0f);
}
__global__ void scan_k() {
    __shared__ int s[1024];
    int tid = threadIdx.x;
    const int per = (NN + 1023) / 1024;
    int start = tid * per, end = min(start + per, NN);
    int sum = 0;
    for (int i = start; i < end; i++) sum += g_degi[i];
    s[tid] = sum;
    __syncthreads();
    for (int off = 1; off < 1024; off <<= 1) {
        int v = 0;
        if (tid >= off) v = s[tid - off];
        __syncthreads();
        if (tid >= off) s[tid] += v;
        __syncthreads();
    }
    int base = s[tid] - sum;
    for (int i = start; i < end; i++) {
        g_off[i] = base; g_cur[i] = base;
        base += g_degi[i];
    }
    if (tid == 1023) g_off[NN] = base;
}
__global__ void fill_k(const void* __restrict__ ei) {
    int e = blockIdx.x * blockDim.x + threadIdx.x;
    if (e >= EE) return;
    int src = edge_at(ei, e);
    int dst = edge_at(ei, (long long)EE + e);
    int pos = atomicAdd(&g_cur[dst], 1);
    g_csrc[pos] = src;
}
__global__ void __launch_bounds__(128) gather_k(const float* __restrict__ x,
                                                const float* __restrict__ gcn_b) {
    const int n = blockIdx.x;
    const int c = threadIdx.x * 4;
    const int s0 = g_off[n], s1 = g_off[n + 1];
    const float dv = g_deg[n];
    float4 acc = make_float4(0.f, 0.f, 0.f, 0.f);
    int e = s0;
    #pragma unroll 1
    for (; e + 2 <= s1; e += 2) {
        int srcA = g_csrc[e], srcB = g_csrc[e + 1];
        float nA = dv * g_deg[srcA], nB = dv * g_deg[srcB];
        float4 vA = *reinterpret_cast<const float4*>(&g_xw[(size_t)srcA * DD + c]);
        float4 vB = *reinterpret_cast<const float4*>(&g_xw[(size_t)srcB * DD + c]);
        acc.x += nA * vA.x + nB * vB.x;
        acc.y += nA * vA.y + nB * vB.y;
        acc.z += nA * vA.z + nB * vB.z;
        acc.w += nA * vA.w + nB * vB.w;
    }
    if (e < s1) {
        int src = g_csrc[e];
        float nrm = dv * g_deg[src];
        float4 v = *reinterpret_cast<const float4*>(&g_xw[(size_t)src * DD + c]);
        acc.x += nrm * v.x; acc.y += nrm * v.y; acc.z += nrm * v.z; acc.w += nrm * v.w;
    }
    float4 xw = *reinterpret_cast<const float4*>(&g_xw[(size_t)n * DD + c]);
    float4 xr = *reinterpret_cast<const float4*>(&x[(size_t)n * DD + c]);
    float4 bb = *reinterpret_cast<const float4*>(&gcn_b[c]);
    float d2 = dv * dv;
    float4 o;
    o.x = xr.x + acc.x + d2 * xw.x + bb.x;
    o.y = xr.y + acc.y + d2 * xw.y + bb.y;
    o.z = xr.z + acc.z + d2 * xw.z + bb.z;
    o.w = xr.w + acc.w + d2 * xw.w + bb.w;
    *reinterpret_cast<float4*>(&g_bufL[(size_t)n * DD + c]) = o;
}
__global__ void stats0_k() {
    const int c = threadIdx.x;
    const int r0 = blockIdx.x * 128;
    const int rEnd = min(r0 + 128, NN);
    float s = 0.f, s2 = 0.f;
    for (int r = r0; r < rEnd; r++) {
        float v = g_bufL[(size_t)r * DD + c];
        s += v; s2 += v * v;
    }
    atomicAdd(&g_stats[0 * DD + c], s);
    atomicAdd(&g_stats[1 * DD + c], s2);
}

__global__ void finalize_k(int bn, const float* __restrict__ gamma, const float* __restrict__ beta) {
    int c = threadIdx.x;
    float s  = g_stats[(bn * 2 + 0) * DD + c];
    float s2 = g_stats[(bn * 2 + 1) * DD + c];
    float m = s * (1.0f / NN);
    float var = s2 * (1.0f / NN) - m * m;
    float a = gamma[c] * rsqrtf(var + EPSC);
    g_coef[(bn * 2 + 0) * DD + c] = a;
    g_coef[(bn * 2 + 1) * DD + c] = beta[c] - m * a;
}

__global__ void apply_sum_k() {          // float4: h fp32 + hb bf16x2 pair
    int i = blockIdx.x * blockDim.x + threadIdx.x;
    if (i >= NN * DD / 4) return;
    int base = i * 4;
    int c = base & (DD - 1);
    float4 bl = *reinterpret_cast<const float4*>(&g_bufL[base]);
    float4 ba = *reinterpret_cast<const float4*>(&g_bufA[base]);
    float4 a0 = *reinterpret_cast<const float4*>(&g_coef[c]);
    float4 b0 = *reinterpret_cast<const float4*>(&g_coef[DD + c]);
    float4 a1 = *reinterpret_cast<const float4*>(&g_coef[2 * DD + c]);
    float4 b1 = *reinterpret_cast<const float4*>(&g_coef[3 * DD + c]);
    float4 v;
    v.x = bl.x * a0.x + b0.x + ba.x * a1.x + b1.x;
    v.y = bl.y * a0.y + b0.y + ba.y * a1.y + b1.y;
    v.z = bl.z * a0.z + b0.z + ba.z * a1.z + b1.z;
    v.w = bl.w * a0.w + b0.w + ba.w * a1.w + b1.w;
    *reinterpret_cast<float4*>(&g_h[base]) = v;
    uint2 p = make_uint2(packbf(v.x, v.y), packbf(v.z, v.w));
    *reinterpret_cast<uint2*>(&g_hb[base]) = p;
}
__global__ void bn2_apply_k(float* __restrict__ out) {   // float4
    int i = blockIdx.x * blockDim.x + threadIdx.x;
    if (i >= NN * DD / 4) return;
    int base = i * 4;
    int c = base & (DD - 1);
    float4 f = *reinterpret_cast<const float4*>(&g_ff[base]);
    float4 a = *reinterpret_cast<const float4*>(&g_coef[4 * DD + c]);
    float4 b = *reinterpret_cast<const float4*>(&g_coef[5 * DD + c]);
    float4 v;
    v.x = f.x * a.x + b.x;
    v.y = f.y * a.y + b.y;
    v.z = f.z * a.z + b.z;
    v.w = f.w * a.w + b.w;
    *reinterpret_cast<float4*>(&out[base]) = v;
}

// ---------------- wave helpers ----------------------------------------------
__global__ void pack_w_k(const float* __restrict__ linW, const float* __restrict__ fW) {
    int idx = blockIdx.x * blockDim.x + threadIdx.x;
    if (idx >= DD * DD) return;
    int d = idx >> 9, j = idx & 511;
    int t = j >> 7, s = j & 127;
    g_linWp[idx] = tf32r(linW[t * (DD * SSc) + d * SSc + s]);
    g_fWt[idx]   = tf32r(fW[idx]);
}
__global__ void post_u_k(const float* __restrict__ fs, const float* __restrict__ linB) {
    int idx = blockIdx.x * blockDim.x + threadIdx.x;
    if (idx >= (KK / 2) * DD) return;
    int kp = idx >> 9, j = idx & 511;
    int t = j >> 7, s = j & 127;
    float bl = linB[t * SSc + s];
    int k0 = 2 * kp, k1 = 2 * kp + 1;
    float v0 = fs[k0 * TJc + t] * (g_uraw[k0 * DD + j] + g_esum[k0] * bl);
    float v1 = fs[k1 * TJc + t] * (g_uraw[k1 * DD + j] + g_esum[k1] * bl);
    g_ubp[idx] = packbf(v0, v1);
}
__global__ void scale_u2_k(const float* __restrict__ fs) {
    int idx = blockIdx.x * blockDim.x + threadIdx.x;
    if (idx >= KK * DD) return;
    int k = idx >> 9, t = (idx & 511) >> 7;
    g_u2[idx] = tf32r(g_u2[idx] * fs[k * TJc + t]);
}

// ---------------- streams/events ----------------------------------------------
static cudaStream_t s_gcn = nullptr, s_aux = nullptr;
static cudaEvent_t ev_fork = nullptr, ev_xw = nullptr, ev_join = nullptr, ev_aux = nullptr;
namespace { struct StreamInit {
    StreamInit() {
        cudaStreamCreateWithFlags(&s_gcn, cudaStreamNonBlocking);
        cudaStreamCreateWithFlags(&s_aux, cudaStreamNonBlocking);
        cudaEventCreateWithFlags(&ev_fork, cudaEventDisableTiming);
        cudaEventCreateWithFlags(&ev_xw,   cudaEventDisableTiming);
        cudaEventCreateWithFlags(&ev_join, cudaEventDisableTiming);
        cudaEventCreateWithFlags(&ev_aux,  cudaEventDisableTiming);
    }
} s_init; }

// ---------------- launch -----------------------------------------------------
#define GSYM(p, ty, s) do { void* _t; cudaGetSymbolAddress(&_t, s); (p) = (ty)_t; } while (0)

extern "C" void kernel_launch(void* const* d_in, const int* in_sizes, int n_in,
                              void* d_out, int out_size) {
    const float* x        = (const float*)d_in[0];
    const void*  ei       = d_in[1];
    const float* evc      = (const float*)d_in[2];
    const float* fs       = (const float*)d_in[3];
    const float* gcn_W    = (const float*)d_in[4];
    const float* gcn_b    = (const float*)d_in[5];
    const float* lin_W    = (const float*)d_in[6];
    const float* lin_b    = (const float*)d_in[7];
    const float* fusion_W = (const float*)d_in[8];
    const float* fusion_b = (const float*)d_in[9];
    const float* bn1l_g   = (const float*)d_in[10];
    const float* bn1l_b   = (const float*)d_in[11];
    const float* bn1a_g   = (const float*)d_in[12];
    const float* bn1a_b   = (const float*)d_in[13];
    const float* bn2_g    = (const float*)d_in[14];
    const float* bn2_b    = (const float*)d_in[15];
    const float* ff1_W    = (const float*)d_in[16];
    const float* ff1_b    = (const float*)d_in[17];
    const float* ff2_W    = (const float*)d_in[18];
    const float* ff2_b    = (const float*)d_in[19];
    float* out = (float*)d_out;

    float *p_xw, *p_bufL, *p_v, *p_bufA, *p_h, *p_ff, *p_evct;
    float *p_xe, *p_uraw, *p_u2, *p_W2, *p_linWp, *p_fWt;
    __nv_bfloat16 *p_xb, *p_evcb, *p_hb, *p_midb;
    uint32_t *p_gWbp, *p_f1Wbp, *p_f2Wbp, *p_W2bp, *p_ubp;
    GSYM(p_xw, float*, g_xw);     GSYM(p_bufL, float*, g_bufL); GSYM(p_v, float*, g_v);
    GSYM(p_bufA, float*, g_bufA); GSYM(p_h, float*, g_h);       GSYM(p_ff, float*, g_ff);
    GSYM(p_evct, float*, g_evct);
    GSYM(p_xe, float*, g_xe);     GSYM(p_uraw, float*, g_uraw);
    GSYM(p_u2, float*, g_u2);     GSYM(p_W2, float*, g_W2);
    GSYM(p_linWp, float*, g_linWp); GSYM(p_fWt, float*, g_fWt);
    GSYM(p_xb, __nv_bfloat16*, g_xb);   GSYM(p_evcb, __nv_bfloat16*, g_evcb);
    GSYM(p_hb, __nv_bfloat16*, g_hb);   GSYM(p_midb, __nv_bfloat16*, g_midb);
    GSYM(p_gWbp, uint32_t*, g_gWbp);    GSYM(p_f1Wbp, uint32_t*, g_f1Wbp);
    GSYM(p_f2Wbp, uint32_t*, g_f2Wbp);  GSYM(p_W2bp, uint32_t*, g_W2bp);
    GSYM(p_ubp, uint32_t*, g_ubp);

    const int GEMM_SMEM = (2 * 128 * 36 + 2 * 32 * 136) * 4;   // 71680
    const int BF_SMEM   = GEMM_SMEM;
    const int ATB_SMEM  = (2 * 32 * 136 * 2) * 4;
    cudaFuncSetAttribute(tcgemm_k<false>, cudaFuncAttributeMaxDynamicSharedMemorySize, GEMM_SMEM);
    cudaFuncSetAttribute(tcgemm_k<true>,  cudaFuncAttributeMaxDynamicSharedMemorySize, GEMM_SMEM);
    cudaFuncSetAttribute(atb_k<false>, cudaFuncAttributeMaxDynamicSharedMemorySize, ATB_SMEM);
    cudaFuncSetAttribute(atb_k<true>,  cudaFuncAttributeMaxDynamicSharedMemorySize, ATB_SMEM);
    cudaFuncSetAttribute(bfgemm_k<false, false, false, false, false>, cudaFuncAttributeMaxDynamicSharedMemorySize, BF_SMEM);
    cudaFuncSetAttribute(bfgemm_k<false, true,  true,  false, false>, cudaFuncAttributeMaxDynamicSharedMemorySize, BF_SMEM);
    cudaFuncSetAttribute(bfgemm_k<true,  true,  false, false, true >, cudaFuncAttributeMaxDynamicSharedMemorySize, BF_SMEM);
    cudaFuncSetAttribute(bfgemm_k<true,  true,  false, true,  false>, cudaFuncAttributeMaxDynamicSharedMemorySize, BF_SMEM);
    cudaFuncSetAttribute(bfgemm_k<true,  false, false, false, true >, cudaFuncAttributeMaxDynamicSharedMemorySize, BF_SMEM);

    const int MB = (NN + 127) / 128;
    dim3 gD(4, MB);
    dim3 gF(8, MB);
    dim3 gTiny(4, 1);
    dim3 gAtbX(ATB_BLKS, 4, 1);
    dim3 gAtbU(ATB_BLKS, 4, 1);

    detect_k<<<1, 256>>>((const int*)ei);
    zero_scratch_k<<<1024, 256>>>();

    // ---- fork ----
    cudaEventRecord(ev_fork, 0);
    cudaStreamWaitEvent(s_gcn, ev_fork, 0);
    cudaStreamWaitEvent(s_aux, ev_fork, 0);

    // s_gcn: CSR build
    degi_k<<<(EE + 255) / 256, 256, 0, s_gcn>>>(ei);
    dinv_k<<<(NN + 255) / 256, 256, 0, s_gcn>>>();
    scan_k<<<1, 1024, 0, s_gcn>>>();
    fill_k<<<(EE + 255) / 256, 256, 0, s_gcn>>>(ei);

    // s_aux: weight packs needed later
    pack_w_k<<<(DD * DD + 255) / 256, 256, 0, s_aux>>>(lin_W, fusion_W);
    packpairs_k<<<((DD / 2) * DD2 + 255) / 256, 256, 0, s_aux>>>(ff1_W, p_f1Wbp, DD2, (DD / 2) * DD2);
    packpairs_k<<<((DD2 / 2) * DD + 255) / 256, 256, 0, s_aux>>>(ff2_W, p_f2Wbp, DD, (DD2 / 2) * DD);
    cudaEventRecord(ev_aux, s_aux);

    // main: prep + xw GEMM
    packpairs_k<<<((DD / 2) * DD + 255) / 256, 256>>>(gcn_W, p_gWbp, DD, (DD / 2) * DD);
    prep_evc_k<<<(NN + 249) / 250, KK>>>(evc);
    tobf_k<<<1024, 256>>>(x, p_xb, (long long)NN * DD);
    bfgemm_k<false, false, false, false, false><<<gD, 256, BF_SMEM>>>(
        p_xb, DD, p_gWbp, DD, 0, p_xw, DD, 0, nullptr, NN, DD, nullptr, 0);
    cudaEventRecord(ev_xw, 0);

    // s_gcn: gather + BN0 stats (needs xw)
    cudaStreamWaitEvent(s_gcn, ev_xw, 0);
    gather_k<<<NN, 128, 0, s_gcn>>>(x, gcn_b);
    stats0_k<<<MB, DD, 0, s_gcn>>>();
    cudaEventRecord(ev_join, s_gcn);

    // main: wave branch
    atb_k<true><<<gAtbX, 256, ATB_SMEM>>>(p_evct, x, DD, p_xe, DD);
    cudaStreamWaitEvent(0, ev_aux, 0);
    tcgemm_k<true><<<gTiny, 256, GEMM_SMEM>>>(p_xe, DD, p_linWp, DD, p_uraw, DD, KK, DD);
    post_u_k<<<((KK / 2) * DD + 255) / 256, 256>>>(fs, lin_b);
    bfgemm_k<false, true, true, false, false><<<gD, 256, BF_SMEM>>>(
        p_evcb, KK, p_ubp, DD, 0, p_v, DD, 0, nullptr, NN, KK, nullptr, 0);
    atb_k<false><<<gAtbU, 256, ATB_SMEM>>>(p_evct, p_v, DD, p_u2, DD);
    scale_u2_k<<<(KK * DD + 255) / 256, 256>>>(fs);
    tcgemm_k<false><<<gTiny, 256, GEMM_SMEM>>>(p_u2, DD, p_fWt, DD, p_W2, DD, KK, DD);
    packpairs_k<<<((KK / 2) * DD + 255) / 256, 256>>>(p_W2, p_W2bp, DD, (KK / 2) * DD);
    bfgemm_k<true, true, false, false, true><<<gD, 256, BF_SMEM>>>(
        p_evcb, KK, p_W2bp, DD, 0, p_bufA, DD, 0, fusion_b, NN, KK, x, 1);

    // ---- join + BN ----
    cudaStreamWaitEvent(0, ev_join, 0);
    finalize_k<<<1, DD>>>(0, bn1l_g, bn1l_b);
    finalize_k<<<1, DD>>>(1, bn1a_g, bn1a_b);
    apply_sum_k<<<(NN * DD / 4 + 255) / 256, 256>>>();

    // ---- feed-forward ----
    bfgemm_k<true, true, false, true, false><<<gF, 256, BF_SMEM>>>(
        p_hb, DD, p_f1Wbp, DD2, 0, p_midb, DD2, 0, ff1_b, NN, DD, nullptr, 0);
    bfgemm_k<true, false, false, false, true><<<gD, 256, BF_SMEM>>>(
        p_midb, DD2, p_f2Wbp, DD, 0, p_ff, DD, 0, ff2_b, NN, DD2, p_h, 2);
    finalize_k<<<1, DD>>>(2, bn2_g, bn2_b);
    bn2_apply_k<<<(NN * DD / 4 + 255) / 256, 256>>>(out);
}

// round 14
// speedup vs baseline: 1.0324x; 1.0072x over previous
#include <cuda_runtime.h>
#include <cuda_bf16.h>
#include <cstdint>

#define NN  50000
#define EE  800000
#define DD  512
#define KK  128
#define TJc 4
#define SSc 128
#define DD2 1024
#define EPSC 1e-5f

// ---------------- scratch (device globals) -----------------------------------
__device__ float g_xw  [(size_t)NN * DD];
__device__ float g_bufL[(size_t)NN * DD];
__device__ float g_v   [(size_t)NN * DD];
__device__ float g_bufA[(size_t)NN * DD];
__device__ float g_h   [(size_t)NN * DD];
__device__ float g_ff  [(size_t)NN * DD];
__device__ float g_evct[(size_t)NN * KK];
__device__ __nv_bfloat16 g_xb  [(size_t)NN * DD];
__device__ __nv_bfloat16 g_evcb[(size_t)NN * KK];
__device__ __nv_bfloat16 g_hb  [(size_t)NN * DD];
__device__ __nv_bfloat16 g_midb[(size_t)NN * DD2];
__device__ uint32_t g_gWbp [(DD / 2) * DD];
__device__ uint32_t g_f1Wbp[(DD / 2) * DD2];
__device__ uint32_t g_f2Wbp[(DD2 / 2) * DD];
__device__ uint32_t g_W2bp [(KK / 2) * DD];
__device__ uint32_t g_ubp  [(KK / 2) * DD];
__device__ float g_deg [NN];
__device__ int   g_degi[NN];
__device__ int   g_off [NN + 1];
__device__ int   g_cur [NN];
__device__ int   g_csrc[EE];
__device__ float g_esum[KK];
__device__ float g_xe  [KK * DD];
__device__ float g_uraw[KK * DD];
__device__ float g_u2  [KK * DD];
__device__ float g_W2  [KK * DD];
__device__ float g_stats[6 * DD];
__device__ float g_coef [6 * DD];
__device__ float g_linWp[DD * DD];
__device__ float g_fWt  [DD * DD];
__device__ int   g_is64;

// ---------------- helpers -----------------------------------------------------
__device__ __forceinline__ float tf32r(float f) {
    uint32_t u; asm("cvt.rna.tf32.f32 %0, %1;" : "=r"(u) : "f"(f));
    return __uint_as_float(u);
}
__device__ __forceinline__ uint32_t cvt_rna(uint32_t x) {
    uint32_t u; float f = __uint_as_float(x);
    asm("cvt.rna.tf32.f32 %0, %1;" : "=r"(u) : "f"(f)); return u;
}
__device__ __forceinline__ uint32_t packbf(float lo, float hi) {
    uint32_t r; asm("cvt.rn.bf16x2.f32 %0, %1, %2;" : "=r"(r) : "f"(hi), "f"(lo));
    return r;
}
__device__ __forceinline__ void mma_tf32(float* c, const uint32_t* a, const uint32_t* b) {
    asm volatile("mma.sync.aligned.m16n8k8.row.col.f32.tf32.tf32.f32 "
        "{%0,%1,%2,%3}, {%4,%5,%6,%7}, {%8,%9}, {%0,%1,%2,%3};"
        : "+f"(c[0]), "+f"(c[1]), "+f"(c[2]), "+f"(c[3])
        : "r"(a[0]), "r"(a[1]), "r"(a[2]), "r"(a[3]), "r"(b[0]), "r"(b[1]));
}
__device__ __forceinline__ void mma_bf16(float* c, const uint32_t* a, const uint32_t* b) {
    asm volatile("mma.sync.aligned.m16n8k16.row.col.f32.bf16.bf16.f32 "
        "{%0,%1,%2,%3}, {%4,%5,%6,%7}, {%8,%9}, {%0,%1,%2,%3};"
        : "+f"(c[0]), "+f"(c[1]), "+f"(c[2]), "+f"(c[3])
        : "r"(a[0]), "r"(a[1]), "r"(a[2]), "r"(a[3]), "r"(b[0]), "r"(b[1]));
}
__device__ __forceinline__ void ldmat_x4(uint32_t* r, uint32_t saddr) {
    asm volatile("ldmatrix.sync.aligned.m8n8.x4.shared.b16 {%0,%1,%2,%3}, [%4];"
        : "=r"(r[0]), "=r"(r[1]), "=r"(r[2]), "=r"(r[3]) : "r"(saddr));
}
__device__ __forceinline__ void cp16(void* sdst, const void* gsrc, bool pred) {
    uint32_t sa = (uint32_t)__cvta_generic_to_shared(sdst);
    int sz = pred ? 16 : 0;
    asm volatile("cp.async.cg.shared.global [%0], [%1], 16, %2;"
                 :: "r"(sa), "l"(gsrc), "r"(sz));
}
#define CP_COMMIT() asm volatile("cp.async.commit_group;")
#define CP_WAIT(n)  asm volatile("cp.async.wait_group %0;" :: "n"(n))

// ---------------- edge-index dtype detection --------------------------------
__global__ void detect_k(const int* __restrict__ ei32) {
    __shared__ int any;
    if (threadIdx.x == 0) any = 0;
    __syncthreads();
    int v = 0;
    for (int i = threadIdx.x; i < 1024; i += blockDim.x)
        v |= ei32[2 * i + 1];
    if (v) atomicOr(&any, 1);
    __syncthreads();
    if (threadIdx.x == 0) g_is64 = (any == 0) ? 1 : 0;
}
__device__ __forceinline__ int edge_at(const void* ei, long long pos) {
    return g_is64 ? (int)((const long long*)ei)[pos] : ((const int*)ei)[pos];
}

// ---------------- zero / round / pack helpers --------------------------------
__global__ void zero_scratch_k() {
    int stride = gridDim.x * blockDim.x;
    int i0 = blockIdx.x * blockDim.x + threadIdx.x;
    for (int i = i0; i < NN; i += stride) g_degi[i] = 0;
    for (int i = i0; i < KK * DD; i += stride) { g_xe[i] = 0.f; g_u2[i] = 0.f; }
    for (int i = i0; i < 6 * DD; i += stride) g_stats[i] = 0.f;
    for (int i = i0; i < KK; i += stride) g_esum[i] = 0.f;
}
__global__ void tobf_k(const float* __restrict__ in, __nv_bfloat16* __restrict__ o, long long n) {
    long long i = (long long)blockIdx.x * blockDim.x + threadIdx.x;
    long long stride = (long long)gridDim.x * blockDim.x;
    for (; i < n / 4; i += stride) {
        float4 v = reinterpret_cast<const float4*>(in)[i];
        uint2 p = make_uint2(packbf(v.x, v.y), packbf(v.z, v.w));
        reinterpret_cast<uint2*>(o)[i] = p;
    }
}
__global__ void packpairs_k(const float* __restrict__ W, uint32_t* __restrict__ Wp,
                            int Ncols, int total) {
    int idx = blockIdx.x * blockDim.x + threadIdx.x;
    if (idx >= total) return;
    int kp = idx / Ncols, n = idx - kp * Ncols;
    Wp[idx] = packbf(W[(size_t)(2 * kp) * Ncols + n], W[(size_t)(2 * kp + 1) * Ncols + n]);
}
__global__ void prep_evc_k(const float* __restrict__ evc) {
    int c = threadIdx.x;
    int r0 = blockIdx.x * 250;
    int r1 = min(r0 + 250, NN);
    float s = 0.f;
    for (int r = r0; r < r1; r++) {
        float v = evc[(size_t)r * KK + c];
        s += v;
        g_evct[(size_t)r * KK + c] = tf32r(v);
        g_evcb[(size_t)r * KK + c] = __float2bfloat16_rn(v);
    }
    atomicAdd(&g_esum[c], s);
}

// ---------------- bf16 tensor-core GEMM (k64, 2-stage, ldmatrix A) -----------
template <bool BIAS, bool RELU, bool RND, bool OUTBF, bool ADDST>
__global__ void __launch_bounds__(256, 2) bfgemm_k(
    const __nv_bfloat16* __restrict__ A, int lda,
    const uint32_t* __restrict__ Bp, int ldb, long long bTs,
    void* __restrict__ Cv, int ldc, long long cTs,
    const float* __restrict__ bias,
    int M, int Kd,
    const float* __restrict__ Xadd, int bn)
{
    extern __shared__ uint32_t dynb[];
    uint32_t (*AsB)[128][36] = reinterpret_cast<uint32_t(*)[128][36]>(dynb);
    uint32_t (*BsB)[32][136] = reinterpret_cast<uint32_t(*)[32][136]>(dynb + 2 * 128 * 36);

    Bp += (long long)blockIdx.z * bTs;

    const int m0 = blockIdx.y * 128;
    const int n0 = blockIdx.x * 128;
    const int tid = threadIdx.x;
    const int lane = tid & 31;
    const int wid = tid >> 5;
    const int g = lane >> 2, t = lane & 3;
    const int wm0 = (wid & 1) * 64;
    const int wn0 = (wid >> 1) * 32;

    // ldmatrix per-lane geometry: rows mr+lrow, k-pair offset kk*8+lpo
    const uint32_t as_base = (uint32_t)__cvta_generic_to_shared(&AsB[0][0][0]);
    const uint32_t lrow = ((lane >> 3) & 1) * 8 + (lane & 7);
    const uint32_t lpo  = (lane >> 4) * 4;

    float acc[4][4][4] = {};
    const int T = Kd >> 6;

    auto load_tiles = [&](int it, int s) {
        int k0 = it * 64;
        #pragma unroll
        for (int l = 0; l < 4; l++) {
            int idx = tid + l * 256;
            int r = idx >> 3, ch = idx & 7;
            bool p = (m0 + r < M);
            int row = p ? (m0 + r) : 0;
            cp16(&AsB[s][r][ch * 4], &A[(size_t)row * lda + k0 + ch * 8], p);
        }
        #pragma unroll
        for (int l = 0; l < 4; l++) {
            int idx = tid + l * 256;
            int r = idx >> 5, c = (idx & 31) * 4;
            cp16(&BsB[s][r][c], &Bp[(size_t)(k0 / 2 + r) * ldb + n0 + c], true);
        }
    };

    load_tiles(0, 0);
    CP_COMMIT();

    for (int i = 0; i < T; i++) {
        int cur = i & 1;
        if (i + 1 < T) { load_tiles(i + 1, cur ^ 1); CP_COMMIT(); CP_WAIT(1); }
        else          { CP_WAIT(0); }
        __syncthreads();
        uint32_t abase = as_base + (uint32_t)cur * (128 * 36 * 4);
        #pragma unroll
        for (int kk = 0; kk < 4; kk++) {
            uint32_t af[4][4], bf[4][2];
            #pragma unroll
            for (int mf = 0; mf < 4; mf++) {
                uint32_t addr = abase
                    + (uint32_t)(wm0 + mf * 16 + lrow) * (36 * 4)
                    + (uint32_t)(kk * 8 + lpo) * 4;
                ldmat_x4(af[mf], addr);
            }
            #pragma unroll
            for (int nf = 0; nf < 4; nf++) {
                bf[nf][0] = BsB[cur][kk * 8 + t    ][wn0 + nf * 8 + g];
                bf[nf][1] = BsB[cur][kk * 8 + t + 4][wn0 + nf * 8 + g];
            }
            #pragma unroll
            for (int mf = 0; mf < 4; mf++)
                #pragma unroll
                for (int nf = 0; nf < 4; nf++)
                    mma_bf16(acc[mf][nf], af[mf], bf[nf]);
        }
        __syncthreads();
    }

    float* C = (float*)Cv + (long long)blockIdx.z * cTs;
    __nv_bfloat16* Cb = (__nv_bfloat16*)Cv + (long long)blockIdx.z * cTs;
    float cs[4][2] = {}, cq[4][2] = {};

    #pragma unroll
    for (int mf = 0; mf < 4; mf++) {
        int row0 = m0 + wm0 + mf * 16 + g;
        int row1 = row0 + 8;
        #pragma unroll
        for (int nf = 0; nf < 4; nf++) {
            int n = n0 + wn0 + nf * 8 + 2 * t;
            float b0 = 0.f, b1 = 0.f;
            if (BIAS) { b0 = bias[n]; b1 = bias[n + 1]; }
            float2 v0 = make_float2(acc[mf][nf][0] + b0, acc[mf][nf][1] + b1);
            float2 v1 = make_float2(acc[mf][nf][2] + b0, acc[mf][nf][3] + b1);
            if (RELU) {
                v0.x = fmaxf(v0.x, 0.f); v0.y = fmaxf(v0.y, 0.f);
                v1.x = fmaxf(v1.x, 0.f); v1.y = fmaxf(v1.y, 0.f);
            }
            if (RND) {
                v0.x = tf32r(v0.x); v0.y = tf32r(v0.y);
                v1.x = tf32r(v1.x); v1.y = tf32r(v1.y);
            }
            if (row0 < M) {
                if (ADDST) {
                    v0.x += Xadd[(size_t)row0 * ldc + n];
                    v0.y += Xadd[(size_t)row0 * ldc + n + 1];
                    cs[nf][0] += v0.x; cq[nf][0] += v0.x * v0.x;
                    cs[nf][1] += v0.y; cq[nf][1] += v0.y * v0.y;
                }
                if (OUTBF) *reinterpret_cast<uint32_t*>(&Cb[(size_t)row0 * ldc + n]) = packbf(v0.x, v0.y);
                else       *reinterpret_cast<float2*>(&C[(size_t)row0 * ldc + n]) = v0;
            }
            if (row1 < M) {
                if (ADDST) {
                    v1.x += Xadd[(size_t)row1 * ldc + n];
                    v1.y += Xadd[(size_t)row1 * ldc + n + 1];
                    cs[nf][0] += v1.x; cq[nf][0] += v1.x * v1.x;
                    cs[nf][1] += v1.y; cq[nf][1] += v1.y * v1.y;
                }
                if (OUTBF) *reinterpret_cast<uint32_t*>(&Cb[(size_t)row1 * ldc + n]) = packbf(v1.x, v1.y);
                else       *reinterpret_cast<float2*>(&C[(size_t)row1 * ldc + n]) = v1;
            }
        }
    }

    if (ADDST) {
        #pragma unroll
        for (int nf = 0; nf < 4; nf++)
            #pragma unroll
            for (int c2 = 0; c2 < 2; c2++) {
                float s = cs[nf][c2], q = cq[nf][c2];
                #pragma unroll
                for (int off = 4; off < 32; off <<= 1) {
                    s += __shfl_xor_sync(0xffffffffu, s, off);
                    q += __shfl_xor_sync(0xffffffffu, q, off);
                }
                if (g == 0) {
                    int n = n0 + wn0 + nf * 8 + 2 * t + c2;
                    atomicAdd(&g_stats[(bn * 2 + 0) * DD + n], s);
                    atomicAdd(&g_stats[(bn * 2 + 1) * DD + n], q);
                }
            }
    }
}

// ---------------- tf32 GEMM (tiny 128-row GEMMs) -----------------------------
template <bool CVTA>
__global__ void __launch_bounds__(256, 2) tcgemm_k(
    const float* __restrict__ A, int lda,
    const float* __restrict__ B, int ldb,
    float* __restrict__ C, int ldc,
    int M, int Kd)
{
    extern __shared__ uint32_t dyn[];
    uint32_t (*As)[128][36]  = reinterpret_cast<uint32_t(*)[128][36]>(dyn);
    uint32_t (*Bs)[32][136]  = reinterpret_cast<uint32_t(*)[32][136]>(dyn + 2 * 128 * 36);

    const int m0 = blockIdx.y * 128;
    const int n0 = blockIdx.x * 128;
    const int tid = threadIdx.x;
    const int lane = tid & 31;
    const int wid = tid >> 5;
    const int g = lane >> 2, t = lane & 3;
    const int wm0 = (wid & 1) * 64;
    const int wn0 = (wid >> 1) * 32;

    float acc[4][4][4] = {};
    const int T = Kd >> 5;

    auto load_tiles = [&](int it, int s) {
        int k0 = it * 32;
        #pragma unroll
        for (int l = 0; l < 4; l++) {
            int idx = tid + l * 256;
            int r = idx >> 3, c = (idx & 7) * 4;
            bool p = (m0 + r < M);
            int row = p ? (m0 + r) : 0;
            cp16(&As[s][r][c], &A[(size_t)row * lda + k0 + c], p);
        }
        #pragma unroll
        for (int l = 0; l < 4; l++) {
            int idx = tid + l * 256;
            int r = idx >> 5, c = (idx & 31) * 4;
            cp16(&Bs[s][r][c], &B[(size_t)(k0 + r) * ldb + n0 + c], true);
        }
    };

    load_tiles(0, 0);
    CP_COMMIT();

    for (int i = 0; i < T; i++) {
        int cur = i & 1;
        if (i + 1 < T) { load_tiles(i + 1, cur ^ 1); CP_COMMIT(); CP_WAIT(1); }
        else          { CP_WAIT(0); }
        __syncthreads();
        #pragma unroll
        for (int kk = 0; kk < 4; kk++) {
            uint32_t af[4][4], bf[4][2];
            #pragma unroll
            for (int mf = 0; mf < 4; mf++) {
                int mr = wm0 + mf * 16;
                uint32_t a0 = As[cur][mr + g    ][kk * 8 + t];
                uint32_t a1 = As[cur][mr + g + 8][kk * 8 + t];
                uint32_t a2 = As[cur][mr + g    ][kk * 8 + t + 4];
                uint32_t a3 = As[cur][mr + g + 8][kk * 8 + t + 4];
                if (CVTA) { a0 = cvt_rna(a0); a1 = cvt_rna(a1); a2 = cvt_rna(a2); a3 = cvt_rna(a3); }
                af[mf][0] = a0; af[mf][1] = a1; af[mf][2] = a2; af[mf][3] = a3;
            }
            #pragma unroll
            for (int nf = 0; nf < 4; nf++) {
                bf[nf][0] = Bs[cur][kk * 8 + t    ][wn0 + nf * 8 + g];
                bf[nf][1] = Bs[cur][kk * 8 + t + 4][wn0 + nf * 8 + g];
            }
            #pragma unroll
            for (int mf = 0; mf < 4; mf++)
                #pragma unroll
                for (int nf = 0; nf < 4; nf++)
                    mma_tf32(acc[mf][nf], af[mf], bf[nf]);
        }
        __syncthreads();
    }

    #pragma unroll
    for (int mf = 0; mf < 4; mf++) {
        int row0 = m0 + wm0 + mf * 16 + g;
        int row1 = row0 + 8;
        #pragma unroll
        for (int nf = 0; nf < 4; nf++) {
            int n = n0 + wn0 + nf * 8 + 2 * t;
            float2 v0 = make_float2(acc[mf][nf][0], acc[mf][nf][1]);
            float2 v1 = make_float2(acc[mf][nf][2], acc[mf][nf][3]);
            if (row0 < M) *reinterpret_cast<float2*>(&C[(size_t)row0 * ldc + n]) = v0;
            if (row1 < M) *reinterpret_cast<float2*>(&C[(size_t)row1 * ldc + n]) = v1;
        }
    }
}

// ------- tf32 tall reduction: C[128, cols] += evc^T[128,N]*B[N,cols] --------
#define ATB_BLKS 64
template <bool CVTB>
__global__ void __launch_bounds__(256, 2) atb_k(
    const float* __restrict__ evc,
    const float* __restrict__ B, int ldb,
    float* __restrict__ C, int ldc)
{
    extern __shared__ uint32_t dyn[];
    uint32_t (*Es)[32][136] = reinterpret_cast<uint32_t(*)[32][136]>(dyn);
    uint32_t (*Hs)[32][136] = reinterpret_cast<uint32_t(*)[32][136]>(dyn + 2 * 32 * 136);

    const int noff = blockIdx.y * 128;

    const int chunk = (NN + ATB_BLKS - 1) / ATB_BLKS;
    const int nStart = blockIdx.x * chunk;
    const int nEnd = min(nStart + chunk, NN);
    const int iters = (chunk + 31) / 32;
    const int tid = threadIdx.x;
    const int lane = tid & 31;
    const int wid = tid >> 5;
    const int g = lane >> 2, t = lane & 3;
    const int wm0 = (wid & 1) * 64;
    const int wn0 = (wid >> 1) * 32;

    float acc[4][4][4] = {};

    auto load_tiles = [&](int it, int s) {
        int n0 = nStart + it * 32;
        #pragma unroll
        for (int l = 0; l < 4; l++) {
            int idx = tid + l * 256;
            int r = idx >> 5, c = (idx & 31) * 4;
            bool p = (n0 + r < nEnd);
            int row = p ? (n0 + r) : 0;
            cp16(&Es[s][r][c], &evc[(size_t)row * KK + c], p);
            cp16(&Hs[s][r][c], &B[(size_t)row * ldb + noff + c], p);
        }
    };

    load_tiles(0, 0);
    CP_COMMIT();

    for (int i = 0; i < iters; i++) {
        int cur = i & 1;
        if (i + 1 < iters) { load_tiles(i + 1, cur ^ 1); CP_COMMIT(); CP_WAIT(1); }
        else              { CP_WAIT(0); }
        __syncthreads();
        #pragma unroll
        for (int kk = 0; kk < 4; kk++) {
            uint32_t af[4][4], bf[4][2];
            #pragma unroll
            for (int mf = 0; mf < 4; mf++) {
                int mc = wm0 + mf * 16;
                af[mf][0] = Es[cur][kk * 8 + t    ][mc + g];
                af[mf][1] = Es[cur][kk * 8 + t    ][mc + g + 8];
                af[mf][2] = Es[cur][kk * 8 + t + 4][mc + g];
                af[mf][3] = Es[cur][kk * 8 + t + 4][mc + g + 8];
            }
            #pragma unroll
            for (int nf = 0; nf < 4; nf++) {
                uint32_t b0 = Hs[cur][kk * 8 + t    ][wn0 + nf * 8 + g];
                uint32_t b1 = Hs[cur][kk * 8 + t + 4][wn0 + nf * 8 + g];
                if (CVTB) { b0 = cvt_rna(b0); b1 = cvt_rna(b1); }
                bf[nf][0] = b0; bf[nf][1] = b1;
            }
            #pragma unroll
            for (int mf = 0; mf < 4; mf++)
                #pragma unroll
                for (int nf = 0; nf < 4; nf++)
                    mma_tf32(acc[mf][nf], af[mf], bf[nf]);
        }
        __syncthreads();
    }

    #pragma unroll
    for (int mf = 0; mf < 4; mf++) {
        int row0 = wm0 + mf * 16 + g;
        #pragma unroll
        for (int nf = 0; nf < 4; nf++) {
            int n = noff + wn0 + nf * 8 + 2 * t;
            float* p0 = &C[(size_t)row0 * ldc + n];
            float* p1 = &C[(size_t)(row0 + 8) * ldc + n];
            asm volatile("red.global.add.v2.f32 [%0], {%1,%2};"
                         :: "l"(p0), "f"(acc[mf][nf][0]), "f"(acc[mf][nf][1]) : "memory");
            asm volatile("red.global.add.v2.f32 [%0], {%1,%2};"
                         :: "l"(p1), "f"(acc[mf][nf][2]), "f"(acc[mf][nf][3]) : "memory");
        }
    }
}

// ---------------- graph: CSR build + gather ----------------------------------
__global__ void degi_k(const void* __restrict__ ei) {
    int e = blockIdx.x * blockDim.x + threadIdx.x;
    if (e < EE) atomicAdd(&g_degi[edge_at(ei, (long long)EE + e)], 1);
}
__global__ void dinv_k() {
    int n = blockIdx.x * blockDim.x + threadIdx.x;
    if (n < NN) g_deg[n] = rsqrtf((float)g_degi[n] + 1.0f);
}
__global__ void scan_k() {
    __shared__ int s[1024];
    int tid = threadIdx.x;
    const int per = (NN + 1023) / 1024;
    int start = tid * per, end = min(start + per, NN);
    int sum = 0;
    for (int i = start; i < end; i++) sum += g_degi[i];
    s[tid] = sum;
    __syncthreads();
    for (int off = 1; off < 1024; off <<= 1) {
        int v = 0;
        if (tid >= off) v = s[tid - off];
        __syncthreads();
        if (tid >= off) s[tid] += v;
        __syncthreads();
    }
    int base = s[tid] - sum;
    for (int i = start; i < end; i++) {
        g_off[i] = base; g_cur[i] = base;
        base += g_degi[i];
    }
    if (tid == 1023) g_off[NN] = base;
}
__global__ void fill_k(const void* __restrict__ ei) {
    int e = blockIdx.x * blockDim.x + threadIdx.x;
    if (e >= EE) return;
    int src = edge_at(ei, e);
    int dst = edge_at(ei, (long long)EE + e);
    int pos = atomicAdd(&g_cur[dst], 1);
    g_csrc[pos] = src;
}
__global__ void __launch_bounds__(128) gather_k(const float* __restrict__ x,
                                                const float* __restrict__ gcn_b) {
    const int n = blockIdx.x;
    const int c = threadIdx.x * 4;
    const int s0 = g_off[n], s1 = g_off[n + 1];
    const float dv = g_deg[n];
    float4 acc = make_float4(0.f, 0.f, 0.f, 0.f);
    int e = s0;
    #pragma unroll 1
    for (; e + 2 <= s1; e += 2) {
        int srcA = g_csrc[e], srcB = g_csrc[e + 1];
        float nA = dv * g_deg[srcA], nB = dv * g_deg[srcB];
        float4 vA = *reinterpret_cast<const float4*>(&g_xw[(size_t)srcA * DD + c]);
        float4 vB = *reinterpret_cast<const float4*>(&g_xw[(size_t)srcB * DD + c]);
        acc.x += nA * vA.x + nB * vB.x;
        acc.y += nA * vA.y + nB * vB.y;
        acc.z += nA * vA.z + nB * vB.z;
        acc.w += nA * vA.w + nB * vB.w;
    }
    if (e < s1) {
        int src = g_csrc[e];
        float nrm = dv * g_deg[src];
        float4 v = *reinterpret_cast<const float4*>(&g_xw[(size_t)src * DD + c]);
        acc.x += nrm * v.x; acc.y += nrm * v.y; acc.z += nrm * v.z; acc.w += nrm * v.w;
    }
    float4 xw = *reinterpret_cast<const float4*>(&g_xw[(size_t)n * DD + c]);
    float4 xr = *reinterpret_cast<const float4*>(&x[(size_t)n * DD + c]);
    float4 bb = *reinterpret_cast<const float4*>(&gcn_b[c]);
    float d2 = dv * dv;
    float4 o;
    o.x = xr.x + acc.x + d2 * xw.x + bb.x;
    o.y = xr.y + acc.y + d2 * xw.y + bb.y;
    o.z = xr.z + acc.z + d2 * xw.z + bb.z;
    o.w = xr.w + acc.w + d2 * xw.w + bb.w;
    *reinterpret_cast<float4*>(&g_bufL[(size_t)n * DD + c]) = o;
}
__global__ void stats0_k() {
    const int c = threadIdx.x;
    const int r0 = blockIdx.x * 128;
    const int rEnd = min(r0 + 128, NN);
    float s = 0.f, s2 = 0.f;
    for (int r = r0; r < rEnd; r++) {
        float v = g_bufL[(size_t)r * DD + c];
        s += v; s2 += v * v;
    }
    atomicAdd(&g_stats[0 * DD + c], s);
    atomicAdd(&g_stats[1 * DD + c], s2);
}

__global__ void finalize_k(int bn, const float* __restrict__ gamma, const float* __restrict__ beta) {
    int c = threadIdx.x;
    float s  = g_stats[(bn * 2 + 0) * DD + c];
    float s2 = g_stats[(bn * 2 + 1) * DD + c];
    float m = s * (1.0f / NN);
    float var = s2 * (1.0f / NN) - m * m;
    float a = gamma[c] * rsqrtf(var + EPSC);
    g_coef[(bn * 2 + 0) * DD + c] = a;
    g_coef[(bn * 2 + 1) * DD + c] = beta[c] - m * a;
}

__global__ void apply_sum_k() {
    int i = blockIdx.x * blockDim.x + threadIdx.x;
    if (i >= NN * DD / 4) return;
    int base = i * 4;
    int c = base & (DD - 1);
    float4 bl = *reinterpret_cast<const float4*>(&g_bufL[base]);
    float4 ba = *reinterpret_cast<const float4*>(&g_bufA[base]);
    float4 a0 = *reinterpret_cast<const float4*>(&g_coef[c]);
    float4 b0 = *reinterpret_cast<const float4*>(&g_coef[DD + c]);
    float4 a1 = *reinterpret_cast<const float4*>(&g_coef[2 * DD + c]);
    float4 b1 = *reinterpret_cast<const float4*>(&g_coef[3 * DD + c]);
    float4 v;
    v.x = bl.x * a0.x + b0.x + ba.x * a1.x + b1.x;
    v.y = bl.y * a0.y + b0.y + ba.y * a1.y + b1.y;
    v.z = bl.z * a0.z + b0.z + ba.z * a1.z + b1.z;
    v.w = bl.w * a0.w + b0.w + ba.w * a1.w + b1.w;
    *reinterpret_cast<float4*>(&g_h[base]) = v;
    uint2 p = make_uint2(packbf(v.x, v.y), packbf(v.z, v.w));
    *reinterpret_cast<uint2*>(&g_hb[base]) = p;
}
__global__ void bn2_apply_k(float* __restrict__ out) {
    int i = blockIdx.x * blockDim.x + threadIdx.x;
    if (i >= NN * DD / 4) return;
    int base = i * 4;
    int c = base & (DD - 1);
    float4 f = *reinterpret_cast<const float4*>(&g_ff[base]);
    float4 a = *reinterpret_cast<const float4*>(&g_coef[4 * DD + c]);
    float4 b = *reinterpret_cast<const float4*>(&g_coef[5 * DD + c]);
    float4 v;
    v.x = f.x * a.x + b.x;
    v.y = f.y * a.y + b.y;
    v.z = f.z * a.z + b.z;
    v.w = f.w * a.w + b.w;
    *reinterpret_cast<float4*>(&out[base]) = v;
}

// ---------------- wave helpers ----------------------------------------------
__global__ void pack_w_k(const float* __restrict__ linW, const float* __restrict__ fW) {
    int idx = blockIdx.x * blockDim.x + threadIdx.x;
    if (idx >= DD * DD) return;
    int d = idx >> 9, j = idx & 511;
    int t = j >> 7, s = j & 127;
    g_linWp[idx] = tf32r(linW[t * (DD * SSc) + d * SSc + s]);
    g_fWt[idx]   = tf32r(fW[idx]);
}
__global__ void post_u_k(const float* __restrict__ fs, const float* __restrict__ linB) {
    int idx = blockIdx.x * blockDim.x + threadIdx.x;
    if (idx >= (KK / 2) * DD) return;
    int kp = idx >> 9, j = idx & 511;
    int t = j >> 7, s = j & 127;
    float bl = linB[t * SSc + s];
    int k0 = 2 * kp, k1 = 2 * kp + 1;
    float v0 = fs[k0 * TJc + t] * (g_uraw[k0 * DD + j] + g_esum[k0] * bl);
    float v1 = fs[k1 * TJc + t] * (g_uraw[k1 * DD + j] + g_esum[k1] * bl);
    g_ubp[idx] = packbf(v0, v1);
}
__global__ void scale_u2_k(const float* __restrict__ fs) {
    int idx = blockIdx.x * blockDim.x + threadIdx.x;
    if (idx >= KK * DD) return;
    int k = idx >> 9, t = (idx & 511) >> 7;
    g_u2[idx] = tf32r(g_u2[idx] * fs[k * TJc + t]);
}

// ---------------- streams/events ----------------------------------------------
static cudaStream_t s_gcn = nullptr, s_aux = nullptr;
static cudaEvent_t ev_fork = nullptr, ev_xw = nullptr, ev_join = nullptr, ev_aux = nullptr;
namespace { struct StreamInit {
    StreamInit() {
        cudaStreamCreateWithFlags(&s_gcn, cudaStreamNonBlocking);
        cudaStreamCreateWithFlags(&s_aux, cudaStreamNonBlocking);
        cudaEventCreateWithFlags(&ev_fork, cudaEventDisableTiming);
        cudaEventCreateWithFlags(&ev_xw,   cudaEventDisableTiming);
        cudaEventCreateWithFlags(&ev_join, cudaEventDisableTiming);
        cudaEventCreateWithFlags(&ev_aux,  cudaEventDisableTiming);
    }
} s_init; }

// ---------------- launch -----------------------------------------------------
#define GSYM(p, ty, s) do { void* _t; cudaGetSymbolAddress(&_t, s); (p) = (ty)_t; } while (0)

extern "C" void kernel_launch(void* const* d_in, const int* in_sizes, int n_in,
                              void* d_out, int out_size) {
    const float* x        = (const float*)d_in[0];
    const void*  ei       = d_in[1];
    const float* evc      = (const float*)d_in[2];
    const float* fs       = (const float*)d_in[3];
    const float* gcn_W    = (const float*)d_in[4];
    const float* gcn_b    = (const float*)d_in[5];
    const float* lin_W    = (const float*)d_in[6];
    const float* lin_b    = (const float*)d_in[7];
    const float* fusion_W = (const float*)d_in[8];
    const float* fusion_b = (const float*)d_in[9];
    const float* bn1l_g   = (const float*)d_in[10];
    const float* bn1l_b   = (const float*)d_in[11];
    const float* bn1a_g   = (const float*)d_in[12];
    const float* bn1a_b   = (const float*)d_in[13];
    const float* bn2_g    = (const float*)d_in[14];
    const float* bn2_b    = (const float*)d_in[15];
    const float* ff1_W    = (const float*)d_in[16];
    const float* ff1_b    = (const float*)d_in[17];
    const float* ff2_W    = (const float*)d_in[18];
    const float* ff2_b    = (const float*)d_in[19];
    float* out = (float*)d_out;

    float *p_xw, *p_bufL, *p_v, *p_bufA, *p_h, *p_ff, *p_evct;
    float *p_xe, *p_uraw, *p_u2, *p_W2, *p_linWp, *p_fWt;
    __nv_bfloat16 *p_xb, *p_evcb, *p_hb, *p_midb;
    uint32_t *p_gWbp, *p_f1Wbp, *p_f2Wbp, *p_W2bp, *p_ubp;
    GSYM(p_xw, float*, g_xw);     GSYM(p_bufL, float*, g_bufL); GSYM(p_v, float*, g_v);
    GSYM(p_bufA, float*, g_bufA); GSYM(p_h, float*, g_h);       GSYM(p_ff, float*, g_ff);
    GSYM(p_evct, float*, g_evct);
    GSYM(p_xe, float*, g_xe);     GSYM(p_uraw, float*, g_uraw);
    GSYM(p_u2, float*, g_u2);     GSYM(p_W2, float*, g_W2);
    GSYM(p_linWp, float*, g_linWp); GSYM(p_fWt, float*, g_fWt);
    GSYM(p_xb, __nv_bfloat16*, g_xb);   GSYM(p_evcb, __nv_bfloat16*, g_evcb);
    GSYM(p_hb, __nv_bfloat16*, g_hb);   GSYM(p_midb, __nv_bfloat16*, g_midb);
    GSYM(p_gWbp, uint32_t*, g_gWbp);    GSYM(p_f1Wbp, uint32_t*, g_f1Wbp);
    GSYM(p_f2Wbp, uint32_t*, g_f2Wbp);  GSYM(p_W2bp, uint32_t*, g_W2bp);
    GSYM(p_ubp, uint32_t*, g_ubp);

    const int GEMM_SMEM = (2 * 128 * 36 + 2 * 32 * 136) * 4;   // 71680
    const int BF_SMEM   = GEMM_SMEM;
    const int ATB_SMEM  = (2 * 32 * 136 * 2) * 4;
    cudaFuncSetAttribute(tcgemm_k<false>, cudaFuncAttributeMaxDynamicSharedMemorySize, GEMM_SMEM);
    cudaFuncSetAttribute(tcgemm_k<true>,  cudaFuncAttributeMaxDynamicSharedMemorySize, GEMM_SMEM);
    cudaFuncSetAttribute(atb_k<false>, cudaFuncAttributeMaxDynamicSharedMemorySize, ATB_SMEM);
    cudaFuncSetAttribute(atb_k<true>,  cudaFuncAttributeMaxDynamicSharedMemorySize, ATB_SMEM);
    cudaFuncSetAttribute(bfgemm_k<false, false, false, false, false>, cudaFuncAttributeMaxDynamicSharedMemorySize, BF_SMEM);
    cudaFuncSetAttribute(bfgemm_k<false, true,  true,  false, false>, cudaFuncAttributeMaxDynamicSharedMemorySize, BF_SMEM);
    cudaFuncSetAttribute(bfgemm_k<true,  true,  false, false, true >, cudaFuncAttributeMaxDynamicSharedMemorySize, BF_SMEM);
    cudaFuncSetAttribute(bfgemm_k<true,  true,  false, true,  false>, cudaFuncAttributeMaxDynamicSharedMemorySize, BF_SMEM);
    cudaFuncSetAttribute(bfgemm_k<true,  false, false, false, true >, cudaFuncAttributeMaxDynamicSharedMemorySize, BF_SMEM);

    const int MB = (NN + 127) / 128;
    dim3 gD(4, MB);
    dim3 gF(8, MB);
    dim3 gTiny(4, 1);
    dim3 gAtbX(ATB_BLKS, 4, 1);
    dim3 gAtbU(ATB_BLKS, 4, 1);

    detect_k<<<1, 256>>>((const int*)ei);
    zero_scratch_k<<<1024, 256>>>();

    // ---- fork ----
    cudaEventRecord(ev_fork, 0);
    cudaStreamWaitEvent(s_gcn, ev_fork, 0);
    cudaStreamWaitEvent(s_aux, ev_fork, 0);

    // s_gcn: CSR build
    degi_k<<<(EE + 255) / 256, 256, 0, s_gcn>>>(ei);
    dinv_k<<<(NN + 255) / 256, 256, 0, s_gcn>>>();
    scan_k<<<1, 1024, 0, s_gcn>>>();
    fill_k<<<(EE + 255) / 256, 256, 0, s_gcn>>>(ei);

    // s_aux: weight packs needed later
    pack_w_k<<<(DD * DD + 255) / 256, 256, 0, s_aux>>>(lin_W, fusion_W);
    packpairs_k<<<((DD / 2) * DD2 + 255) / 256, 256, 0, s_aux>>>(ff1_W, p_f1Wbp, DD2, (DD / 2) * DD2);
    packpairs_k<<<((DD2 / 2) * DD + 255) / 256, 256, 0, s_aux>>>(ff2_W, p_f2Wbp, DD, (DD2 / 2) * DD);
    cudaEventRecord(ev_aux, s_aux);

    // main: prep + xw GEMM
    packpairs_k<<<((DD / 2) * DD + 255) / 256, 256>>>(gcn_W, p_gWbp, DD, (DD / 2) * DD);
    prep_evc_k<<<(NN + 249) / 250, KK>>>(evc);
    tobf_k<<<1024, 256>>>(x, p_xb, (long long)NN * DD);
    bfgemm_k<false, false, false, false, false><<<gD, 256, BF_SMEM>>>(
        p_xb, DD, p_gWbp, DD, 0, p_xw, DD, 0, nullptr, NN, DD, nullptr, 0);
    cudaEventRecord(ev_xw, 0);

    // s_gcn: gather + BN0 stats (needs xw)
    cudaStreamWaitEvent(s_gcn, ev_xw, 0);
    gather_k<<<NN, 128, 0, s_gcn>>>(x, gcn_b);
    stats0_k<<<MB, DD, 0, s_gcn>>>();
    cudaEventRecord(ev_join, s_gcn);

    // main: wave branch
    atb_k<true><<<gAtbX, 256, ATB_SMEM>>>(p_evct, x, DD, p_xe, DD);
    cudaStreamWaitEvent(0, ev_aux, 0);
    tcgemm_k<true><<<gTiny, 256, GEMM_SMEM>>>(p_xe, DD, p_linWp, DD, p_uraw, DD, KK, DD);
    post_u_k<<<((KK / 2) * DD + 255) / 256, 256>>>(fs, lin_b);
    bfgemm_k<false, true, true, false, false><<<gD, 256, BF_SMEM>>>(
        p_evcb, KK, p_ubp, DD, 0, p_v, DD, 0, nullptr, NN, KK, nullptr, 0);
    atb_k<false><<<gAtbU, 256, ATB_SMEM>>>(p_evct, p_v, DD, p_u2, DD);
    scale_u2_k<<<(KK * DD + 255) / 256, 256>>>(fs);
    tcgemm_k<false><<<gTiny, 256, GEMM_SMEM>>>(p_u2, DD, p_fWt, DD, p_W2, DD, KK, DD);
    packpairs_k<<<((KK / 2) * DD + 255) / 256, 256>>>(p_W2, p_W2bp, DD, (KK / 2) * DD);
    bfgemm_k<true, true, false, false, true><<<gD, 256, BF_SMEM>>>(
        p_evcb, KK, p_W2bp, DD, 0, p_bufA, DD, 0, fusion_b, NN, KK, x, 1);

    // ---- join + BN ----
    cudaStreamWaitEvent(0, ev_join, 0);
    finalize_k<<<1, DD>>>(0, bn1l_g, bn1l_b);
    finalize_k<<<1, DD>>>(1, bn1a_g, bn1a_b);
    apply_sum_k<<<(NN * DD / 4 + 255) / 256, 256>>>();

    // ---- feed-forward ----
    bfgemm_k<true, true, false, true, false><<<gF, 256, BF_SMEM>>>(
        p_hb, DD, p_f1Wbp, DD2, 0, p_midb, DD2, 0, ff1_b, NN, DD, nullptr, 0);
    bfgemm_k<true, false, false, false, true><<<gD, 256, BF_SMEM>>>(
        p_midb, DD2, p_f2Wbp, DD, 0, p_ff, DD, 0, ff2_b, NN, DD2, p_h, 2);
    finalize_k<<<1, DD>>>(2, bn2_g, bn2_b);
    bn2_apply_k<<<(NN * DD / 4 + 255) / 256, 256>>>(out);
}

// round 15
// speedup vs baseline: 1.0608x; 1.0275x over previous
#include <cuda_runtime.h>
#include <cuda_bf16.h>
#include <cstdint>

#define NN  50000
#define EE  800000
#define DD  512
#define KK  128
#define TJc 4
#define SSc 128
#define DD2 1024
#define EPSC 1e-5f

// ---------------- scratch (device globals) -----------------------------------
__device__ float g_xw  [(size_t)NN * DD];
__device__ float g_bufL[(size_t)NN * DD];
__device__ __nv_bfloat16 g_vb[(size_t)NN * DD];   // v bf16 [N,512]
__device__ float g_bufA[(size_t)NN * DD];
__device__ float g_h   [(size_t)NN * DD];
__device__ float g_ff  [(size_t)NN * DD];
__device__ float g_evct[(size_t)NN * KK];
__device__ __nv_bfloat16 g_xb  [(size_t)NN * DD];
__device__ __nv_bfloat16 g_evcb[(size_t)NN * KK];
__device__ __nv_bfloat16 g_hb  [(size_t)NN * DD];
__device__ __nv_bfloat16 g_midb[(size_t)NN * DD2];
__device__ uint32_t g_gWbp [(DD / 2) * DD];
__device__ uint32_t g_f1Wbp[(DD / 2) * DD2];
__device__ uint32_t g_f2Wbp[(DD2 / 2) * DD];
__device__ uint32_t g_W2bp [(KK / 2) * DD];
__device__ uint32_t g_ubp  [(KK / 2) * DD];
__device__ float g_deg [NN];
__device__ int   g_degi[NN];
__device__ int   g_off [NN + 1];
__device__ int   g_cur [NN];
__device__ int   g_csrc[EE];
__device__ float g_esum[KK];
__device__ float g_xe  [KK * DD];
__device__ float g_uraw[KK * DD];
__device__ float g_u2  [KK * DD];
__device__ float g_W2  [KK * DD];
__device__ float g_stats[6 * DD];
__device__ float g_coef [6 * DD];
__device__ float g_linWp[DD * DD];
__device__ float g_fWt  [DD * DD];
__device__ int   g_is64;

// ---------------- helpers -----------------------------------------------------
__device__ __forceinline__ float tf32r(float f) {
    uint32_t u; asm("cvt.rna.tf32.f32 %0, %1;" : "=r"(u) : "f"(f));
    return __uint_as_float(u);
}
__device__ __forceinline__ uint32_t cvt_rna(uint32_t x) {
    uint32_t u; float f = __uint_as_float(x);
    asm("cvt.rna.tf32.f32 %0, %1;" : "=r"(u) : "f"(f)); return u;
}
__device__ __forceinline__ uint32_t packbf(float lo, float hi) {
    uint32_t r; asm("cvt.rn.bf16x2.f32 %0, %1, %2;" : "=r"(r) : "f"(hi), "f"(lo));
    return r;
}
__device__ __forceinline__ void mma_tf32(float* c, const uint32_t* a, const uint32_t* b) {
    asm volatile("mma.sync.aligned.m16n8k8.row.col.f32.tf32.tf32.f32 "
        "{%0,%1,%2,%3}, {%4,%5,%6,%7}, {%8,%9}, {%0,%1,%2,%3};"
        : "+f"(c[0]), "+f"(c[1]), "+f"(c[2]), "+f"(c[3])
        : "r"(a[0]), "r"(a[1]), "r"(a[2]), "r"(a[3]), "r"(b[0]), "r"(b[1]));
}
__device__ __forceinline__ void mma_bf16(float* c, const uint32_t* a, const uint32_t* b) {
    asm volatile("mma.sync.aligned.m16n8k16.row.col.f32.bf16.bf16.f32 "
        "{%0,%1,%2,%3}, {%4,%5,%6,%7}, {%8,%9}, {%0,%1,%2,%3};"
        : "+f"(c[0]), "+f"(c[1]), "+f"(c[2]), "+f"(c[3])
        : "r"(a[0]), "r"(a[1]), "r"(a[2]), "r"(a[3]), "r"(b[0]), "r"(b[1]));
}
__device__ __forceinline__ void ldmat_x4(uint32_t* r, uint32_t saddr) {
    asm volatile("ldmatrix.sync.aligned.m8n8.x4.shared.b16 {%0,%1,%2,%3}, [%4];"
        : "=r"(r[0]), "=r"(r[1]), "=r"(r[2]), "=r"(r[3]) : "r"(saddr));
}
__device__ __forceinline__ void ldmat_x4t(uint32_t* r, uint32_t saddr) {
    asm volatile("ldmatrix.sync.aligned.m8n8.x4.trans.shared.b16 {%0,%1,%2,%3}, [%4];"
        : "=r"(r[0]), "=r"(r[1]), "=r"(r[2]), "=r"(r[3]) : "r"(saddr));
}
__device__ __forceinline__ void cp16(void* sdst, const void* gsrc, bool pred) {
    uint32_t sa = (uint32_t)__cvta_generic_to_shared(sdst);
    int sz = pred ? 16 : 0;
    asm volatile("cp.async.cg.shared.global [%0], [%1], 16, %2;"
                 :: "r"(sa), "l"(gsrc), "r"(sz));
}
#define CP_COMMIT() asm volatile("cp.async.commit_group;")
#define CP_WAIT(n)  asm volatile("cp.async.wait_group %0;" :: "n"(n))

// ---------------- edge-index dtype detection --------------------------------
__global__ void detect_k(const int* __restrict__ ei32) {
    __shared__ int any;
    if (threadIdx.x == 0) any = 0;
    __syncthreads();
    int v = 0;
    for (int i = threadIdx.x; i < 1024; i += blockDim.x)
        v |= ei32[2 * i + 1];
    if (v) atomicOr(&any, 1);
    __syncthreads();
    if (threadIdx.x == 0) g_is64 = (any == 0) ? 1 : 0;
}
__device__ __forceinline__ int edge_at(const void* ei, long long pos) {
    return g_is64 ? (int)((const long long*)ei)[pos] : ((const int*)ei)[pos];
}

// ---------------- zero / round / pack helpers --------------------------------
__global__ void zero_scratch_k() {
    int stride = gridDim.x * blockDim.x;
    int i0 = blockIdx.x * blockDim.x + threadIdx.x;
    for (int i = i0; i < NN; i += stride) g_degi[i] = 0;
    for (int i = i0; i < KK * DD; i += stride) { g_xe[i] = 0.f; g_u2[i] = 0.f; }
    for (int i = i0; i < 6 * DD; i += stride) g_stats[i] = 0.f;
    for (int i = i0; i < KK; i += stride) g_esum[i] = 0.f;
}
__global__ void tobf_k(const float* __restrict__ in, __nv_bfloat16* __restrict__ o, long long n) {
    long long i = (long long)blockIdx.x * blockDim.x + threadIdx.x;
    long long stride = (long long)gridDim.x * blockDim.x;
    for (; i < n / 4; i += stride) {
        float4 v = reinterpret_cast<const float4*>(in)[i];
        uint2 p = make_uint2(packbf(v.x, v.y), packbf(v.z, v.w));
        reinterpret_cast<uint2*>(o)[i] = p;
    }
}
__global__ void packpairs_k(const float* __restrict__ W, uint32_t* __restrict__ Wp,
                            int Ncols, int total) {
    int idx = blockIdx.x * blockDim.x + threadIdx.x;
    if (idx >= total) return;
    int kp = idx / Ncols, n = idx - kp * Ncols;
    Wp[idx] = packbf(W[(size_t)(2 * kp) * Ncols + n], W[(size_t)(2 * kp + 1) * Ncols + n]);
}
__global__ void prep_evc_k(const float* __restrict__ evc) {
    int c = threadIdx.x;
    int r0 = blockIdx.x * 250;
    int r1 = min(r0 + 250, NN);
    float s = 0.f;
    for (int r = r0; r < r1; r++) {
        float v = evc[(size_t)r * KK + c];
        s += v;
        g_evct[(size_t)r * KK + c] = tf32r(v);
        g_evcb[(size_t)r * KK + c] = __float2bfloat16_rn(v);
    }
    atomicAdd(&g_esum[c], s);
}

// ---------------- bf16 tensor-core GEMM (k64, 2-stage, ldmatrix A) -----------
template <bool BIAS, bool RELU, bool RND, bool OUTBF, bool ADDST>
__global__ void __launch_bounds__(256, 2) bfgemm_k(
    const __nv_bfloat16* __restrict__ A, int lda,
    const uint32_t* __restrict__ Bp, int ldb, long long bTs,
    void* __restrict__ Cv, int ldc, long long cTs,
    const float* __restrict__ bias,
    int M, int Kd,
    const float* __restrict__ Xadd, int bn)
{
    extern __shared__ uint32_t dynb[];
    uint32_t (*AsB)[128][36] = reinterpret_cast<uint32_t(*)[128][36]>(dynb);
    uint32_t (*BsB)[32][136] = reinterpret_cast<uint32_t(*)[32][136]>(dynb + 2 * 128 * 36);

    Bp += (long long)blockIdx.z * bTs;

    const int m0 = blockIdx.y * 128;
    const int n0 = blockIdx.x * 128;
    const int tid = threadIdx.x;
    const int lane = tid & 31;
    const int wid = tid >> 5;
    const int g = lane >> 2, t = lane & 3;
    const int wm0 = (wid & 1) * 64;
    const int wn0 = (wid >> 1) * 32;

    const uint32_t as_base = (uint32_t)__cvta_generic_to_shared(&AsB[0][0][0]);
    const uint32_t lrow = ((lane >> 3) & 1) * 8 + (lane & 7);
    const uint32_t lpo  = (lane >> 4) * 4;

    float acc[4][4][4] = {};
    const int T = Kd >> 6;

    auto load_tiles = [&](int it, int s) {
        int k0 = it * 64;
        #pragma unroll
        for (int l = 0; l < 4; l++) {
            int idx = tid + l * 256;
            int r = idx >> 3, ch = idx & 7;
            bool p = (m0 + r < M);
            int row = p ? (m0 + r) : 0;
            cp16(&AsB[s][r][ch * 4], &A[(size_t)row * lda + k0 + ch * 8], p);
        }
        #pragma unroll
        for (int l = 0; l < 4; l++) {
            int idx = tid + l * 256;
            int r = idx >> 5, c = (idx & 31) * 4;
            cp16(&BsB[s][r][c], &Bp[(size_t)(k0 / 2 + r) * ldb + n0 + c], true);
        }
    };

    load_tiles(0, 0);
    CP_COMMIT();

    for (int i = 0; i < T; i++) {
        int cur = i & 1;
        if (i + 1 < T) { load_tiles(i + 1, cur ^ 1); CP_COMMIT(); CP_WAIT(1); }
        else          { CP_WAIT(0); }
        __syncthreads();
        uint32_t abase = as_base + (uint32_t)cur * (128 * 36 * 4);
        #pragma unroll
        for (int kk = 0; kk < 4; kk++) {
            uint32_t af[4][4], bf[4][2];
            #pragma unroll
            for (int mf = 0; mf < 4; mf++) {
                uint32_t addr = abase
                    + (uint32_t)(wm0 + mf * 16 + lrow) * (36 * 4)
                    + (uint32_t)(kk * 8 + lpo) * 4;
                ldmat_x4(af[mf], addr);
            }
            #pragma unroll
            for (int nf = 0; nf < 4; nf++) {
                bf[nf][0] = BsB[cur][kk * 8 + t    ][wn0 + nf * 8 + g];
                bf[nf][1] = BsB[cur][kk * 8 + t + 4][wn0 + nf * 8 + g];
            }
            #pragma unroll
            for (int mf = 0; mf < 4; mf++)
                #pragma unroll
                for (int nf = 0; nf < 4; nf++)
                    mma_bf16(acc[mf][nf], af[mf], bf[nf]);
        }
        __syncthreads();
    }

    float* C = (float*)Cv + (long long)blockIdx.z * cTs;
    __nv_bfloat16* Cb = (__nv_bfloat16*)Cv + (long long)blockIdx.z * cTs;
    float cs[4][2] = {}, cq[4][2] = {};

    #pragma unroll
    for (int mf = 0; mf < 4; mf++) {
        int row0 = m0 + wm0 + mf * 16 + g;
        int row1 = row0 + 8;
        #pragma unroll
        for (int nf = 0; nf < 4; nf++) {
            int n = n0 + wn0 + nf * 8 + 2 * t;
            float b0 = 0.f, b1 = 0.f;
            if (BIAS) { b0 = bias[n]; b1 = bias[n + 1]; }
            float2 v0 = make_float2(acc[mf][nf][0] + b0, acc[mf][nf][1] + b1);
            float2 v1 = make_float2(acc[mf][nf][2] + b0, acc[mf][nf][3] + b1);
            if (RELU) {
                v0.x = fmaxf(v0.x, 0.f); v0.y = fmaxf(v0.y, 0.f);
                v1.x = fmaxf(v1.x, 0.f); v1.y = fmaxf(v1.y, 0.f);
            }
            if (RND) {
                v0.x = tf32r(v0.x); v0.y = tf32r(v0.y);
                v1.x = tf32r(v1.x); v1.y = tf32r(v1.y);
            }
            if (row0 < M) {
                if (ADDST) {
                    v0.x += Xadd[(size_t)row0 * ldc + n];
                    v0.y += Xadd[(size_t)row0 * ldc + n + 1];
                    cs[nf][0] += v0.x; cq[nf][0] += v0.x * v0.x;
                    cs[nf][1] += v0.y; cq[nf][1] += v0.y * v0.y;
                }
                if (OUTBF) *reinterpret_cast<uint32_t*>(&Cb[(size_t)row0 * ldc + n]) = packbf(v0.x, v0.y);
                else       *reinterpret_cast<float2*>(&C[(size_t)row0 * ldc + n]) = v0;
            }
            if (row1 < M) {
                if (ADDST) {
                    v1.x += Xadd[(size_t)row1 * ldc + n];
                    v1.y += Xadd[(size_t)row1 * ldc + n + 1];
                    cs[nf][0] += v1.x; cq[nf][0] += v1.x * v1.x;
                    cs[nf][1] += v1.y; cq[nf][1] += v1.y * v1.y;
                }
                if (OUTBF) *reinterpret_cast<uint32_t*>(&Cb[(size_t)row1 * ldc + n]) = packbf(v1.x, v1.y);
                else       *reinterpret_cast<float2*>(&C[(size_t)row1 * ldc + n]) = v1;
            }
        }
    }

    if (ADDST) {
        #pragma unroll
        for (int nf = 0; nf < 4; nf++)
            #pragma unroll
            for (int c2 = 0; c2 < 2; c2++) {
                float s = cs[nf][c2], q = cq[nf][c2];
                #pragma unroll
                for (int off = 4; off < 32; off <<= 1) {
                    s += __shfl_xor_sync(0xffffffffu, s, off);
                    q += __shfl_xor_sync(0xffffffffu, q, off);
                }
                if (g == 0) {
                    int n = n0 + wn0 + nf * 8 + 2 * t + c2;
                    atomicAdd(&g_stats[(bn * 2 + 0) * DD + n], s);
                    atomicAdd(&g_stats[(bn * 2 + 1) * DD + n], q);
                }
            }
    }
}

// ---------------- tf32 GEMM (tiny 128-row GEMMs) -----------------------------
template <bool CVTA>
__global__ void __launch_bounds__(256, 2) tcgemm_k(
    const float* __restrict__ A, int lda,
    const float* __restrict__ B, int ldb,
    float* __restrict__ C, int ldc,
    int M, int Kd)
{
    extern __shared__ uint32_t dyn[];
    uint32_t (*As)[128][36]  = reinterpret_cast<uint32_t(*)[128][36]>(dyn);
    uint32_t (*Bs)[32][136]  = reinterpret_cast<uint32_t(*)[32][136]>(dyn + 2 * 128 * 36);

    const int m0 = blockIdx.y * 128;
    const int n0 = blockIdx.x * 128;
    const int tid = threadIdx.x;
    const int lane = tid & 31;
    const int wid = tid >> 5;
    const int g = lane >> 2, t = lane & 3;
    const int wm0 = (wid & 1) * 64;
    const int wn0 = (wid >> 1) * 32;

    float acc[4][4][4] = {};
    const int T = Kd >> 5;

    auto load_tiles = [&](int it, int s) {
        int k0 = it * 32;
        #pragma unroll
        for (int l = 0; l < 4; l++) {
            int idx = tid + l * 256;
            int r = idx >> 3, c = (idx & 7) * 4;
            bool p = (m0 + r < M);
            int row = p ? (m0 + r) : 0;
            cp16(&As[s][r][c], &A[(size_t)row * lda + k0 + c], p);
        }
        #pragma unroll
        for (int l = 0; l < 4; l++) {
            int idx = tid + l * 256;
            int r = idx >> 5, c = (idx & 31) * 4;
            cp16(&Bs[s][r][c], &B[(size_t)(k0 + r) * ldb + n0 + c], true);
        }
    };

    load_tiles(0, 0);
    CP_COMMIT();

    for (int i = 0; i < T; i++) {
        int cur = i & 1;
        if (i + 1 < T) { load_tiles(i + 1, cur ^ 1); CP_COMMIT(); CP_WAIT(1); }
        else          { CP_WAIT(0); }
        __syncthreads();
        #pragma unroll
        for (int kk = 0; kk < 4; kk++) {
            uint32_t af[4][4], bf[4][2];
            #pragma unroll
            for (int mf = 0; mf < 4; mf++) {
                int mr = wm0 + mf * 16;
                uint32_t a0 = As[cur][mr + g    ][kk * 8 + t];
                uint32_t a1 = As[cur][mr + g + 8][kk * 8 + t];
                uint32_t a2 = As[cur][mr + g    ][kk * 8 + t + 4];
                uint32_t a3 = As[cur][mr + g + 8][kk * 8 + t + 4];
                if (CVTA) { a0 = cvt_rna(a0); a1 = cvt_rna(a1); a2 = cvt_rna(a2); a3 = cvt_rna(a3); }
                af[mf][0] = a0; af[mf][1] = a1; af[mf][2] = a2; af[mf][3] = a3;
            }
            #pragma unroll
            for (int nf = 0; nf < 4; nf++) {
                bf[nf][0] = Bs[cur][kk * 8 + t    ][wn0 + nf * 8 + g];
                bf[nf][1] = Bs[cur][kk * 8 + t + 4][wn0 + nf * 8 + g];
            }
            #pragma unroll
            for (int mf = 0; mf < 4; mf++)
                #pragma unroll
                for (int nf = 0; nf < 4; nf++)
                    mma_tf32(acc[mf][nf], af[mf], bf[nf]);
        }
        __syncthreads();
    }

    #pragma unroll
    for (int mf = 0; mf < 4; mf++) {
        int row0 = m0 + wm0 + mf * 16 + g;
        int row1 = row0 + 8;
        #pragma unroll
        for (int nf = 0; nf < 4; nf++) {
            int n = n0 + wn0 + nf * 8 + 2 * t;
            float2 v0 = make_float2(acc[mf][nf][0], acc[mf][nf][1]);
            float2 v1 = make_float2(acc[mf][nf][2], acc[mf][nf][3]);
            if (row0 < M) *reinterpret_cast<float2*>(&C[(size_t)row0 * ldc + n]) = v0;
            if (row1 < M) *reinterpret_cast<float2*>(&C[(size_t)row1 * ldc + n]) = v1;
        }
    }
}

// ------- tf32 tall reduction (x path): C[128,cols] += evc^T * B -------------
#define ATB_BLKS 64
template <bool CVTB>
__global__ void __launch_bounds__(256, 2) atb_k(
    const float* __restrict__ evc,
    const float* __restrict__ B, int ldb,
    float* __restrict__ C, int ldc)
{
    extern __shared__ uint32_t dyn[];
    uint32_t (*Es)[32][136] = reinterpret_cast<uint32_t(*)[32][136]>(dyn);
    uint32_t (*Hs)[32][136] = reinterpret_cast<uint32_t(*)[32][136]>(dyn + 2 * 32 * 136);

    const int noff = blockIdx.y * 128;

    const int chunk = (NN + ATB_BLKS - 1) / ATB_BLKS;
    const int nStart = blockIdx.x * chunk;
    const int nEnd = min(nStart + chunk, NN);
    const int iters = (chunk + 31) / 32;
    const int tid = threadIdx.x;
    const int lane = tid & 31;
    const int wid = tid >> 5;
    const int g = lane >> 2, t = lane & 3;
    const int wm0 = (wid & 1) * 64;
    const int wn0 = (wid >> 1) * 32;

    float acc[4][4][4] = {};

    auto load_tiles = [&](int it, int s) {
        int n0 = nStart + it * 32;
        #pragma unroll
        for (int l = 0; l < 4; l++) {
            int idx = tid + l * 256;
            int r = idx >> 5, c = (idx & 31) * 4;
            bool p = (n0 + r < nEnd);
            int row = p ? (n0 + r) : 0;
            cp16(&Es[s][r][c], &evc[(size_t)row * KK + c], p);
            cp16(&Hs[s][r][c], &B[(size_t)row * ldb + noff + c], p);
        }
    };

    load_tiles(0, 0);
    CP_COMMIT();

    for (int i = 0; i < iters; i++) {
        int cur = i & 1;
        if (i + 1 < iters) { load_tiles(i + 1, cur ^ 1); CP_COMMIT(); CP_WAIT(1); }
        else              { CP_WAIT(0); }
        __syncthreads();
        #pragma unroll
        for (int kk = 0; kk < 4; kk++) {
            uint32_t af[4][4], bf[4][2];
            #pragma unroll
            for (int mf = 0; mf < 4; mf++) {
                int mc = wm0 + mf * 16;
                af[mf][0] = Es[cur][kk * 8 + t    ][mc + g];
                af[mf][1] = Es[cur][kk * 8 + t    ][mc + g + 8];
                af[mf][2] = Es[cur][kk * 8 + t + 4][mc + g];
                af[mf][3] = Es[cur][kk * 8 + t + 4][mc + g + 8];
            }
            #pragma unroll
            for (int nf = 0; nf < 4; nf++) {
                uint32_t b0 = Hs[cur][kk * 8 + t    ][wn0 + nf * 8 + g];
                uint32_t b1 = Hs[cur][kk * 8 + t + 4][wn0 + nf * 8 + g];
                if (CVTB) { b0 = cvt_rna(b0); b1 = cvt_rna(b1); }
                bf[nf][0] = b0; bf[nf][1] = b1;
            }
            #pragma unroll
            for (int mf = 0; mf < 4; mf++)
                #pragma unroll
                for (int nf = 0; nf < 4; nf++)
                    mma_tf32(acc[mf][nf], af[mf], bf[nf]);
        }
        __syncthreads();
    }

    #pragma unroll
    for (int mf = 0; mf < 4; mf++) {
        int row0 = wm0 + mf * 16 + g;
        #pragma unroll
        for (int nf = 0; nf < 4; nf++) {
            int n = noff + wn0 + nf * 8 + 2 * t;
            float* p0 = &C[(size_t)row0 * ldc + n];
            float* p1 = &C[(size_t)(row0 + 8) * ldc + n];
            asm volatile("red.global.add.v2.f32 [%0], {%1,%2};"
                         :: "l"(p0), "f"(acc[mf][nf][0]), "f"(acc[mf][nf][1]) : "memory");
            asm volatile("red.global.add.v2.f32 [%0], {%1,%2};"
                         :: "l"(p1), "f"(acc[mf][nf][2]), "f"(acc[mf][nf][3]) : "memory");
        }
    }
}

// ------- bf16 tall reduction (u2): u2[128,128-tile] += evc^T[.,N] @ v -------
// evcb [N,128] bf16, vb [N,512] bf16. Fragments via ldmatrix.x4.trans.
__global__ void __launch_bounds__(256, 2) atbb_k(
    const __nv_bfloat16* __restrict__ evcb,
    const __nv_bfloat16* __restrict__ vb,
    float* __restrict__ C)           // u2 [128 x 512]
{
    __shared__ __align__(16) __nv_bfloat16 Eb[2][32][136];
    __shared__ __align__(16) __nv_bfloat16 Vb[2][32][136];

    const int noff = blockIdx.y * 128;
    const int chunk = (NN + ATB_BLKS - 1) / ATB_BLKS;
    const int nStart = blockIdx.x * chunk;
    const int nEnd = min(nStart + chunk, NN);
    const int iters = (chunk + 31) / 32;
    const int tid = threadIdx.x;
    const int lane = tid & 31;
    const int wid = tid >> 5;
    const int g = lane >> 2, t = lane & 3;
    const int wm0 = (wid & 1) * 64;
    const int wn0 = (wid >> 1) * 32;

    const uint32_t eb_base = (uint32_t)__cvta_generic_to_shared(&Eb[0][0][0]);
    const uint32_t vb_base = (uint32_t)__cvta_generic_to_shared(&Vb[0][0][0]);
    const int I = lane >> 3, r = lane & 7;
    const uint32_t TILE = 32 * 136 * 2;   // bytes per buffer
    const uint32_t RS = 136 * 2;          // row stride bytes

    float acc[4][4][4] = {};

    auto load_tiles = [&](int it, int s) {
        int n0 = nStart + it * 32;
        #pragma unroll
        for (int l = 0; l < 2; l++) {
            int idx = tid + l * 256;
            int rr = idx >> 4, ch = idx & 15;
            bool p = (n0 + rr < nEnd);
            int row = p ? (n0 + rr) : 0;
            cp16(&Eb[s][rr][ch * 8], &evcb[(size_t)row * KK + ch * 8], p);
            cp16(&Vb[s][rr][ch * 8], &vb[(size_t)row * DD + noff + ch * 8], p);
        }
    };

    load_tiles(0, 0);
    CP_COMMIT();

    for (int i = 0; i < iters; i++) {
        int cur = i & 1;
        if (i + 1 < iters) { load_tiles(i + 1, cur ^ 1); CP_COMMIT(); CP_WAIT(1); }
        else              { CP_WAIT(0); }
        __syncthreads();
        uint32_t ebase = eb_base + (uint32_t)cur * TILE;
        uint32_t vbase = vb_base + (uint32_t)cur * TILE;
        #pragma unroll
        for (int kk = 0; kk < 2; kk++) {          // 2 x k16 (n-dim) per 32-row tile
            uint32_t af[4][4], bf[4][2];
            // A = evc^T: matrixI: rows n = kk*16 + (I>>1)*8 + r, cols k = wm0+mf*16 + (I&1)*8
            #pragma unroll
            for (int mf = 0; mf < 4; mf++) {
                uint32_t addr = ebase
                    + (uint32_t)(kk * 16 + (I >> 1) * 8 + r) * RS
                    + (uint32_t)(wm0 + mf * 16 + (I & 1) * 8) * 2;
                ldmat_x4t(af[mf], addr);
            }
            // B = v: x4 covers two j8 blocks: matrixI rows n = kk*16 + (I&1)*8 + r,
            // cols j = wn0 + nf2*16 + (I>>1)*8
            #pragma unroll
            for (int nf2 = 0; nf2 < 2; nf2++) {
                uint32_t tmp[4];
                uint32_t addr = vbase
                    + (uint32_t)(kk * 16 + (I & 1) * 8 + r) * RS
                    + (uint32_t)(wn0 + nf2 * 16 + (I >> 1) * 8) * 2;
                ldmat_x4t(tmp, addr);
                bf[nf2 * 2    ][0] = tmp[0]; bf[nf2 * 2    ][1] = tmp[1];
                bf[nf2 * 2 + 1][0] = tmp[2]; bf[nf2 * 2 + 1][1] = tmp[3];
            }
            #pragma unroll
            for (int mf = 0; mf < 4; mf++)
                #pragma unroll
                for (int nf = 0; nf < 4; nf++)
                    mma_bf16(acc[mf][nf], af[mf], bf[nf]);
        }
        __syncthreads();
    }

    #pragma unroll
    for (int mf = 0; mf < 4; mf++) {
        int row0 = wm0 + mf * 16 + g;
        #pragma unroll
        for (int nf = 0; nf < 4; nf++) {
            int n = noff + wn0 + nf * 8 + 2 * t;
            float* p0 = &C[(size_t)row0 * DD + n];
            float* p1 = &C[(size_t)(row0 + 8) * DD + n];
            asm volatile("red.global.add.v2.f32 [%0], {%1,%2};"
                         :: "l"(p0), "f"(acc[mf][nf][0]), "f"(acc[mf][nf][1]) : "memory");
            asm volatile("red.global.add.v2.f32 [%0], {%1,%2};"
                         :: "l"(p1), "f"(acc[mf][nf][2]), "f"(acc[mf][nf][3]) : "memory");
        }
    }
}

// ---------------- graph: CSR build + gather ----------------------------------
__global__ void degi_k(const void* __restrict__ ei) {
    int e = blockIdx.x * blockDim.x + threadIdx.x;
    if (e < EE) atomicAdd(&g_degi[edge_at(ei, (long long)EE + e)], 1);
}
__global__ void dinv_k() {
    int n = blockIdx.x * blockDim.x + threadIdx.x;
    if (n < NN) g_deg[n] = rsqrtf((float)g_degi[n] + 1.0f);
}
__global__ void scan_k() {
    __shared__ int s[1024];
    int tid = threadIdx.x;
    const int per = (NN + 1023) / 1024;
    int start = tid * per, end = min(start + per, NN);
    int sum = 0;
    for (int i = start; i < end; i++) sum += g_degi[i];
    s[tid] = sum;
    __syncthreads();
    for (int off = 1; off < 1024; off <<= 1) {
        int v = 0;
        if (tid >= off) v = s[tid - off];
        __syncthreads();
        if (tid >= off) s[tid] += v;
        __syncthreads();
    }
    int base = s[tid] - sum;
    for (int i = start; i < end; i++) {
        g_off[i] = base; g_cur[i] = base;
        base += g_degi[i];
    }
    if (tid == 1023) g_off[NN] = base;
}
__global__ void fill_k(const void* __restrict__ ei) {
    int e = blockIdx.x * blockDim.x + threadIdx.x;
    if (e >= EE) return;
    int src = edge_at(ei, e);
    int dst = edge_at(ei, (long long)EE + e);
    int pos = atomicAdd(&g_cur[dst], 1);
    g_csrc[pos] = src;
}
__global__ void __launch_bounds__(128) gather_k(const float* __restrict__ x,
                                                const float* __restrict__ gcn_b) {
    const int n = blockIdx.x;
    const int c = threadIdx.x * 4;
    const int s0 = g_off[n], s1 = g_off[n + 1];
    const float dv = g_deg[n];
    float4 acc = make_float4(0.f, 0.f, 0.f, 0.f);
    int e = s0;
    #pragma unroll 1
    for (; e + 2 <= s1; e += 2) {
        int srcA = g_csrc[e], srcB = g_csrc[e + 1];
        float nA = dv * g_deg[srcA], nB = dv * g_deg[srcB];
        float4 vA = *reinterpret_cast<const float4*>(&g_xw[(size_t)srcA * DD + c]);
        float4 vB = *reinterpret_cast<const float4*>(&g_xw[(size_t)srcB * DD + c]);
        acc.x += nA * vA.x + nB * vB.x;
        acc.y += nA * vA.y + nB * vB.y;
        acc.z += nA * vA.z + nB * vB.z;
        acc.w += nA * vA.w + nB * vB.w;
    }
    if (e < s1) {
        int src = g_csrc[e];
        float nrm = dv * g_deg[src];
        float4 v = *reinterpret_cast<const float4*>(&g_xw[(size_t)src * DD + c]);
        acc.x += nrm * v.x; acc.y += nrm * v.y; acc.z += nrm * v.z; acc.w += nrm * v.w;
    }
    float4 xw = *reinterpret_cast<const float4*>(&g_xw[(size_t)n * DD + c]);
    float4 xr = *reinterpret_cast<const float4*>(&x[(size_t)n * DD + c]);
    float4 bb = *reinterpret_cast<const float4*>(&gcn_b[c]);
    float d2 = dv * dv;
    float4 o;
    o.x = xr.x + acc.x + d2 * xw.x + bb.x;
    o.y = xr.y + acc.y + d2 * xw.y + bb.y;
    o.z = xr.z + acc.z + d2 * xw.z + bb.z;
    o.w = xr.w + acc.w + d2 * xw.w + bb.w;
    *reinterpret_cast<float4*>(&g_bufL[(size_t)n * DD + c]) = o;
}
__global__ void stats0_k() {
    const int c = threadIdx.x;
    const int r0 = blockIdx.x * 128;
    const int rEnd = min(r0 + 128, NN);
    float s = 0.f, s2 = 0.f;
    for (int r = r0; r < rEnd; r++) {
        float v = g_bufL[(size_t)r * DD + c];
        s += v; s2 += v * v;
    }
    atomicAdd(&g_stats[0 * DD + c], s);
    atomicAdd(&g_stats[1 * DD + c], s2);
}

// merged finalize for bn 0 and 1 (blockIdx.x selects)
__global__ void finalize01_k(const float* __restrict__ g0, const float* __restrict__ b0,
                             const float* __restrict__ g1, const float* __restrict__ b1) {
    int bn = blockIdx.x;
    const float* gamma = bn ? g1 : g0;
    const float* beta  = bn ? b1 : b0;
    int c = threadIdx.x;
    float s  = g_stats[(bn * 2 + 0) * DD + c];
    float s2 = g_stats[(bn * 2 + 1) * DD + c];
    float m = s * (1.0f / NN);
    float var = s2 * (1.0f / NN) - m * m;
    float a = gamma[c] * rsqrtf(var + EPSC);
    g_coef[(bn * 2 + 0) * DD + c] = a;
    g_coef[(bn * 2 + 1) * DD + c] = beta[c] - m * a;
}
__global__ void finalize_k(int bn, const float* __restrict__ gamma, const float* __restrict__ beta) {
    int c = threadIdx.x;
    float s  = g_stats[(bn * 2 + 0) * DD + c];
    float s2 = g_stats[(bn * 2 + 1) * DD + c];
    float m = s * (1.0f / NN);
    float var = s2 * (1.0f / NN) - m * m;
    float a = gamma[c] * rsqrtf(var + EPSC);
    g_coef[(bn * 2 + 0) * DD + c] = a;
    g_coef[(bn * 2 + 1) * DD + c] = beta[c] - m * a;
}

__global__ void apply_sum_k() {
    int i = blockIdx.x * blockDim.x + threadIdx.x;
    if (i >= NN * DD / 4) return;
    int base = i * 4;
    int c = base & (DD - 1);
    float4 bl = *reinterpret_cast<const float4*>(&g_bufL[base]);
    float4 ba = *reinterpret_cast<const float4*>(&g_bufA[base]);
    float4 a0 = *reinterpret_cast<const float4*>(&g_coef[c]);
    float4 b0 = *reinterpret_cast<const float4*>(&g_coef[DD + c]);
    float4 a1 = *reinterpret_cast<const float4*>(&g_coef[2 * DD + c]);
    float4 b1 = *reinterpret_cast<const float4*>(&g_coef[3 * DD + c]);
    float4 v;
    v.x = bl.x * a0.x + b0.x + ba.x * a1.x + b1.x;
    v.y = bl.y * a0.y + b0.y + ba.y * a1.y + b1.y;
    v.z = bl.z * a0.z + b0.z + ba.z * a1.z + b1.z;
    v.w = bl.w * a0.w + b0.w + ba.w * a1.w + b1.w;
    *reinterpret_cast<float4*>(&g_h[base]) = v;
    uint2 p = make_uint2(packbf(v.x, v.y), packbf(v.z, v.w));
    *reinterpret_cast<uint2*>(&g_hb[base]) = p;
}
__global__ void bn2_apply_k(float* __restrict__ out) {
    int i = blockIdx.x * blockDim.x + threadIdx.x;
    if (i >= NN * DD / 4) return;
    int base = i * 4;
    int c = base & (DD - 1);
    float4 f = *reinterpret_cast<const float4*>(&g_ff[base]);
    float4 a = *reinterpret_cast<const float4*>(&g_coef[4 * DD + c]);
    float4 b = *reinterpret_cast<const float4*>(&g_coef[5 * DD + c]);
    float4 v;
    v.x = f.x * a.x + b.x;
    v.y = f.y * a.y + b.y;
    v.z = f.z * a.z + b.z;
    v.w = f.w * a.w + b.w;
    *reinterpret_cast<float4*>(&out[base]) = v;
}

// ---------------- wave helpers ----------------------------------------------
__global__ void pack_w_k(const float* __restrict__ linW, const float* __restrict__ fW) {
    int idx = blockIdx.x * blockDim.x + threadIdx.x;
    if (idx >= DD * DD) return;
    int d = idx >> 9, j = idx & 511;
    int t = j >> 7, s = j & 127;
    g_linWp[idx] = tf32r(linW[t * (DD * SSc) + d * SSc + s]);
    g_fWt[idx]   = tf32r(fW[idx]);
}
__global__ void post_u_k(const float* __restrict__ fs, const float* __restrict__ linB) {
    int idx = blockIdx.x * blockDim.x + threadIdx.x;
    if (idx >= (KK / 2) * DD) return;
    int kp = idx >> 9, j = idx & 511;
    int t = j >> 7, s = j & 127;
    float bl = linB[t * SSc + s];
    int k0 = 2 * kp, k1 = 2 * kp + 1;
    float v0 = fs[k0 * TJc + t] * (g_uraw[k0 * DD + j] + g_esum[k0] * bl);
    float v1 = fs[k1 * TJc + t] * (g_uraw[k1 * DD + j] + g_esum[k1] * bl);
    g_ubp[idx] = packbf(v0, v1);
}
__global__ void scale_u2_k(const float* __restrict__ fs) {
    int idx = blockIdx.x * blockDim.x + threadIdx.x;
    if (idx >= KK * DD) return;
    int k = idx >> 9, t = (idx & 511) >> 7;
    g_u2[idx] = tf32r(g_u2[idx] * fs[k * TJc + t]);
}

// ---------------- streams/events ----------------------------------------------
static cudaStream_t s_gcn = nullptr, s_aux = nullptr;
static cudaEvent_t ev_fork = nullptr, ev_xw = nullptr, ev_join = nullptr, ev_aux = nullptr;
namespace { struct StreamInit {
    StreamInit() {
        cudaStreamCreateWithFlags(&s_gcn, cudaStreamNonBlocking);
        cudaStreamCreateWithFlags(&s_aux, cudaStreamNonBlocking);
        cudaEventCreateWithFlags(&ev_fork, cudaEventDisableTiming);
        cudaEventCreateWithFlags(&ev_xw,   cudaEventDisableTiming);
        cudaEventCreateWithFlags(&ev_join, cudaEventDisableTiming);
        cudaEventCreateWithFlags(&ev_aux,  cudaEventDisableTiming);
    }
} s_init; }

// ---------------- launch -----------------------------------------------------
#define GSYM(p, ty, s) do { void* _t; cudaGetSymbolAddress(&_t, s); (p) = (ty)_t; } while (0)

extern "C" void kernel_launch(void* const* d_in, const int* in_sizes, int n_in,
                              void* d_out, int out_size) {
    const float* x        = (const float*)d_in[0];
    const void*  ei       = d_in[1];
    const float* evc      = (const float*)d_in[2];
    const float* fs       = (const float*)d_in[3];
    const float* gcn_W    = (const float*)d_in[4];
    const float* gcn_b    = (const float*)d_in[5];
    const float* lin_W    = (const float*)d_in[6];
    const float* lin_b    = (const float*)d_in[7];
    const float* fusion_W = (const float*)d_in[8];
    const float* fusion_b = (const float*)d_in[9];
    const float* bn1l_g   = (const float*)d_in[10];
    const float* bn1l_b   = (const float*)d_in[11];
    const float* bn1a_g   = (const float*)d_in[12];
    const float* bn1a_b   = (const float*)d_in[13];
    const float* bn2_g    = (const float*)d_in[14];
    const float* bn2_b    = (const float*)d_in[15];
    const float* ff1_W    = (const float*)d_in[16];
    const float* ff1_b    = (const float*)d_in[17];
    const float* ff2_W    = (const float*)d_in[18];
    const float* ff2_b    = (const float*)d_in[19];
    float* out = (float*)d_out;

    float *p_xw, *p_bufL, *p_bufA, *p_h, *p_ff, *p_evct;
    float *p_xe, *p_uraw, *p_u2, *p_W2, *p_linWp, *p_fWt;
    __nv_bfloat16 *p_xb, *p_evcb, *p_hb, *p_midb, *p_vb;
    uint32_t *p_gWbp, *p_f1Wbp, *p_f2Wbp, *p_W2bp, *p_ubp;
    GSYM(p_xw, float*, g_xw);     GSYM(p_bufL, float*, g_bufL);
    GSYM(p_bufA, float*, g_bufA); GSYM(p_h, float*, g_h);       GSYM(p_ff, float*, g_ff);
    GSYM(p_evct, float*, g_evct);
    GSYM(p_xe, float*, g_xe);     GSYM(p_uraw, float*, g_uraw);
    GSYM(p_u2, float*, g_u2);     GSYM(p_W2, float*, g_W2);
    GSYM(p_linWp, float*, g_linWp); GSYM(p_fWt, float*, g_fWt);
    GSYM(p_xb, __nv_bfloat16*, g_xb);   GSYM(p_evcb, __nv_bfloat16*, g_evcb);
    GSYM(p_hb, __nv_bfloat16*, g_hb);   GSYM(p_midb, __nv_bfloat16*, g_midb);
    GSYM(p_vb, __nv_bfloat16*, g_vb);
    GSYM(p_gWbp, uint32_t*, g_gWbp);    GSYM(p_f1Wbp, uint32_t*, g_f1Wbp);
    GSYM(p_f2Wbp, uint32_t*, g_f2Wbp);  GSYM(p_W2bp, uint32_t*, g_W2bp);
    GSYM(p_ubp, uint32_t*, g_ubp);

    const int GEMM_SMEM = (2 * 128 * 36 + 2 * 32 * 136) * 4;   // 71680
    const int BF_SMEM   = GEMM_SMEM;
    const int ATB_SMEM  = (2 * 32 * 136 * 2) * 4;
    cudaFuncSetAttribute(tcgemm_k<false>, cudaFuncAttributeMaxDynamicSharedMemorySize, GEMM_SMEM);
    cudaFuncSetAttribute(tcgemm_k<true>,  cudaFuncAttributeMaxDynamicSharedMemorySize, GEMM_SMEM);
    cudaFuncSetAttribute(atb_k<true>,  cudaFuncAttributeMaxDynamicSharedMemorySize, ATB_SMEM);
    cudaFuncSetAttribute(bfgemm_k<false, false, false, false, false>, cudaFuncAttributeMaxDynamicSharedMemorySize, BF_SMEM);
    cudaFuncSetAttribute(bfgemm_k<false, true,  false, true,  false>, cudaFuncAttributeMaxDynamicSharedMemorySize, BF_SMEM);
    cudaFuncSetAttribute(bfgemm_k<true,  true,  false, false, true >, cudaFuncAttributeMaxDynamicSharedMemorySize, BF_SMEM);
    cudaFuncSetAttribute(bfgemm_k<true,  true,  false, true,  false>, cudaFuncAttributeMaxDynamicSharedMemorySize, BF_SMEM);
    cudaFuncSetAttribute(bfgemm_k<true,  false, false, false, true >, cudaFuncAttributeMaxDynamicSharedMemorySize, BF_SMEM);

    const int MB = (NN + 127) / 128;
    dim3 gD(4, MB);
    dim3 gF(8, MB);
    dim3 gTiny(4, 1);
    dim3 gAtbX(ATB_BLKS, 4, 1);
    dim3 gAtbU(ATB_BLKS, 4, 1);

    detect_k<<<1, 256>>>((const int*)ei);
    zero_scratch_k<<<1024, 256>>>();

    // ---- fork ----
    cudaEventRecord(ev_fork, 0);
    cudaStreamWaitEvent(s_gcn, ev_fork, 0);
    cudaStreamWaitEvent(s_aux, ev_fork, 0);

    // s_gcn: CSR build
    degi_k<<<(EE + 255) / 256, 256, 0, s_gcn>>>(ei);
    dinv_k<<<(NN + 255) / 256, 256, 0, s_gcn>>>();
    scan_k<<<1, 1024, 0, s_gcn>>>();
    fill_k<<<(EE + 255) / 256, 256, 0, s_gcn>>>(ei);

    // s_aux: weight packs
    pack_w_k<<<(DD * DD + 255) / 256, 256, 0, s_aux>>>(lin_W, fusion_W);
    packpairs_k<<<((DD / 2) * DD2 + 255) / 256, 256, 0, s_aux>>>(ff1_W, p_f1Wbp, DD2, (DD / 2) * DD2);
    packpairs_k<<<((DD2 / 2) * DD + 255) / 256, 256, 0, s_aux>>>(ff2_W, p_f2Wbp, DD, (DD2 / 2) * DD);
    cudaEventRecord(ev_aux, s_aux);

    // main: prep + xw GEMM
    packpairs_k<<<((DD / 2) * DD + 255) / 256, 256>>>(gcn_W, p_gWbp, DD, (DD / 2) * DD);
    prep_evc_k<<<(NN + 249) / 250, KK>>>(evc);
    tobf_k<<<1024, 256>>>(x, p_xb, (long long)NN * DD);
    bfgemm_k<false, false, false, false, false><<<gD, 256, BF_SMEM>>>(
        p_xb, DD, p_gWbp, DD, 0, p_xw, DD, 0, nullptr, NN, DD, nullptr, 0);
    cudaEventRecord(ev_xw, 0);

    // s_gcn: gather + BN0 stats
    cudaStreamWaitEvent(s_gcn, ev_xw, 0);
    gather_k<<<NN, 128, 0, s_gcn>>>(x, gcn_b);
    stats0_k<<<MB, DD, 0, s_gcn>>>();
    cudaEventRecord(ev_join, s_gcn);

    // main: wave branch
    atb_k<true><<<gAtbX, 256, ATB_SMEM>>>(p_evct, x, DD, p_xe, DD);
    cudaStreamWaitEvent(0, ev_aux, 0);
    tcgemm_k<true><<<gTiny, 256, GEMM_SMEM>>>(p_xe, DD, p_linWp, DD, p_uraw, DD, KK, DD);
    post_u_k<<<((KK / 2) * DD + 255) / 256, 256>>>(fs, lin_b);
    // v (bf16) = relu(evc @ u)
    bfgemm_k<false, true, false, true, false><<<gD, 256, BF_SMEM>>>(
        p_evcb, KK, p_ubp, DD, 0, p_vb, DD, 0, nullptr, NN, KK, nullptr, 0);
    atbb_k<<<gAtbU, 256>>>(p_evcb, p_vb, p_u2);
    scale_u2_k<<<(KK * DD + 255) / 256, 256>>>(fs);
    tcgemm_k<false><<<gTiny, 256, GEMM_SMEM>>>(p_u2, DD, p_fWt, DD, p_W2, DD, KK, DD);
    packpairs_k<<<((KK / 2) * DD + 255) / 256, 256>>>(p_W2, p_W2bp, DD, (KK / 2) * DD);
    bfgemm_k<true, true, false, false, true><<<gD, 256, BF_SMEM>>>(
        p_evcb, KK, p_W2bp, DD, 0, p_bufA, DD, 0, fusion_b, NN, KK, x, 1);

    // ---- join + BN ----
    cudaStreamWaitEvent(0, ev_join, 0);
    finalize01_k<<<2, DD>>>(bn1l_g, bn1l_b, bn1a_g, bn1a_b);
    apply_sum_k<<<(NN * DD / 4 + 255) / 256, 256>>>();

    // ---- feed-forward ----
    bfgemm_k<true, true, false, true, false><<<gF, 256, BF_SMEM>>>(
        p_hb, DD, p_f1Wbp, DD2, 0, p_midb, DD2, 0, ff1_b, NN, DD, nullptr, 0);
    bfgemm_k<true, false, false, false, true><<<gD, 256, BF_SMEM>>>(
        p_midb, DD2, p_f2Wbp, DD, 0, p_ff, DD, 0, ff2_b, NN, DD2, p_h, 2);
    finalize_k<<<1, DD>>>(2, bn2_g, bn2_b);
    bn2_apply_k<<<(NN * DD / 4 + 255) / 256, 256>>>(out);
}

// round 16
// speedup vs baseline: 1.0695x; 1.0082x over previous
#include <cuda_runtime.h>
#include <cuda_bf16.h>
#include <cstdint>

#define NN  50000
#define EE  800000
#define DD  512
#define KK  128
#define TJc 4
#define SSc 128
#define DD2 1024
#define EPSC 1e-5f

// ---------------- scratch (device globals) -----------------------------------
__device__ float g_xw  [(size_t)NN * DD];
__device__ float g_bufL[(size_t)NN * DD];
__device__ float g_bufA[(size_t)NN * DD];
__device__ float g_h   [(size_t)NN * DD];
__device__ float g_ff  [(size_t)NN * DD];
__device__ float g_evct[(size_t)NN * KK];
__device__ __nv_bfloat16 g_xb  [(size_t)NN * DD];
__device__ __nv_bfloat16 g_evcb[(size_t)NN * KK];
__device__ __nv_bfloat16 g_hb  [(size_t)NN * DD];
__device__ __nv_bfloat16 g_midb[(size_t)NN * DD2];
__device__ uint32_t g_gWbp [(DD / 2) * DD];
__device__ uint32_t g_f1Wbp[(DD / 2) * DD2];
__device__ uint32_t g_f2Wbp[(DD2 / 2) * DD];
__device__ uint32_t g_W2bp [(KK / 2) * DD];
__device__ uint32_t g_ubp  [(KK / 2) * DD];
__device__ float g_deg [NN];
__device__ int   g_degi[NN];
__device__ int   g_off [NN + 1];
__device__ int   g_cur [NN];
__device__ int   g_csrc[EE];
__device__ float g_esum[KK];
__device__ float g_xe  [KK * DD];
__device__ float g_uraw[KK * DD];
__device__ float g_u2  [KK * DD];
__device__ float g_W2  [KK * DD];
__device__ float g_stats[6 * DD];
__device__ float g_coef [6 * DD];
__device__ float g_linWp[DD * DD];
__device__ float g_fWt  [DD * DD];
__device__ int   g_is64;

// ---------------- helpers -----------------------------------------------------
__device__ __forceinline__ float tf32r(float f) {
    uint32_t u; asm("cvt.rna.tf32.f32 %0, %1;" : "=r"(u) : "f"(f));
    return __uint_as_float(u);
}
__device__ __forceinline__ uint32_t cvt_rna(uint32_t x) {
    uint32_t u; float f = __uint_as_float(x);
    asm("cvt.rna.tf32.f32 %0, %1;" : "=r"(u) : "f"(f)); return u;
}
__device__ __forceinline__ uint32_t packbf(float lo, float hi) {
    uint32_t r; asm("cvt.rn.bf16x2.f32 %0, %1, %2;" : "=r"(r) : "f"(hi), "f"(lo));
    return r;
}
__device__ __forceinline__ void mma_tf32(float* c, const uint32_t* a, const uint32_t* b) {
    asm volatile("mma.sync.aligned.m16n8k8.row.col.f32.tf32.tf32.f32 "
        "{%0,%1,%2,%3}, {%4,%5,%6,%7}, {%8,%9}, {%0,%1,%2,%3};"
        : "+f"(c[0]), "+f"(c[1]), "+f"(c[2]), "+f"(c[3])
        : "r"(a[0]), "r"(a[1]), "r"(a[2]), "r"(a[3]), "r"(b[0]), "r"(b[1]));
}
__device__ __forceinline__ void mma_bf16(float* c, const uint32_t* a, const uint32_t* b) {
    asm volatile("mma.sync.aligned.m16n8k16.row.col.f32.bf16.bf16.f32 "
        "{%0,%1,%2,%3}, {%4,%5,%6,%7}, {%8,%9}, {%0,%1,%2,%3};"
        : "+f"(c[0]), "+f"(c[1]), "+f"(c[2]), "+f"(c[3])
        : "r"(a[0]), "r"(a[1]), "r"(a[2]), "r"(a[3]), "r"(b[0]), "r"(b[1]));
}
__device__ __forceinline__ void ldmat_x4(uint32_t* r, uint32_t saddr) {
    asm volatile("ldmatrix.sync.aligned.m8n8.x4.shared.b16 {%0,%1,%2,%3}, [%4];"
        : "=r"(r[0]), "=r"(r[1]), "=r"(r[2]), "=r"(r[3]) : "r"(saddr));
}
__device__ __forceinline__ void ldmat_x4t(uint32_t* r, uint32_t saddr) {
    asm volatile("ldmatrix.sync.aligned.m8n8.x4.trans.shared.b16 {%0,%1,%2,%3}, [%4];"
        : "=r"(r[0]), "=r"(r[1]), "=r"(r[2]), "=r"(r[3]) : "r"(saddr));
}
__device__ __forceinline__ void cp16(void* sdst, const void* gsrc, bool pred) {
    uint32_t sa = (uint32_t)__cvta_generic_to_shared(sdst);
    int sz = pred ? 16 : 0;
    asm volatile("cp.async.cg.shared.global [%0], [%1], 16, %2;"
                 :: "r"(sa), "l"(gsrc), "r"(sz));
}
#define CP_COMMIT() asm volatile("cp.async.commit_group;")
#define CP_WAIT(n)  asm volatile("cp.async.wait_group %0;" :: "n"(n))

// ---------------- edge-index dtype detection --------------------------------
__global__ void detect_k(const int* __restrict__ ei32) {
    __shared__ int any;
    if (threadIdx.x == 0) any = 0;
    __syncthreads();
    int v = 0;
    for (int i = threadIdx.x; i < 1024; i += blockDim.x)
        v |= ei32[2 * i + 1];
    if (v) atomicOr(&any, 1);
    __syncthreads();
    if (threadIdx.x == 0) g_is64 = (any == 0) ? 1 : 0;
}
__device__ __forceinline__ int edge_at(const void* ei, long long pos) {
    return g_is64 ? (int)((const long long*)ei)[pos] : ((const int*)ei)[pos];
}

// ---------------- zero / round / pack helpers --------------------------------
__global__ void zero_scratch_k() {
    int stride = gridDim.x * blockDim.x;
    int i0 = blockIdx.x * blockDim.x + threadIdx.x;
    for (int i = i0; i < NN; i += stride) g_degi[i] = 0;
    for (int i = i0; i < KK * DD; i += stride) { g_xe[i] = 0.f; g_u2[i] = 0.f; }
    for (int i = i0; i < 6 * DD; i += stride) g_stats[i] = 0.f;
    for (int i = i0; i < KK; i += stride) g_esum[i] = 0.f;
}
__global__ void tobf_k(const float* __restrict__ in, __nv_bfloat16* __restrict__ o, long long n) {
    long long i = (long long)blockIdx.x * blockDim.x + threadIdx.x;
    long long stride = (long long)gridDim.x * blockDim.x;
    for (; i < n / 4; i += stride) {
        float4 v = reinterpret_cast<const float4*>(in)[i];
        uint2 p = make_uint2(packbf(v.x, v.y), packbf(v.z, v.w));
        reinterpret_cast<uint2*>(o)[i] = p;
    }
}
__global__ void packpairs_k(const float* __restrict__ W, uint32_t* __restrict__ Wp,
                            int Ncols, int total) {
    int idx = blockIdx.x * blockDim.x + threadIdx.x;
    if (idx >= total) return;
    int kp = idx / Ncols, n = idx - kp * Ncols;
    Wp[idx] = packbf(W[(size_t)(2 * kp) * Ncols + n], W[(size_t)(2 * kp + 1) * Ncols + n]);
}
__global__ void prep_evc_k(const float* __restrict__ evc) {
    int c = threadIdx.x;
    int r0 = blockIdx.x * 250;
    int r1 = min(r0 + 250, NN);
    float s = 0.f;
    for (int r = r0; r < r1; r++) {
        float v = evc[(size_t)r * KK + c];
        s += v;
        g_evct[(size_t)r * KK + c] = tf32r(v);
        g_evcb[(size_t)r * KK + c] = __float2bfloat16_rn(v);
    }
    atomicAdd(&g_esum[c], s);
}

// ---------------- bf16 tensor-core GEMM (k64, 2-stage, ldmatrix A) -----------
template <bool BIAS, bool RELU, bool RND, bool OUTBF, bool ADDST>
__global__ void __launch_bounds__(256, 2) bfgemm_k(
    const __nv_bfloat16* __restrict__ A, int lda,
    const uint32_t* __restrict__ Bp, int ldb, long long bTs,
    void* __restrict__ Cv, int ldc, long long cTs,
    const float* __restrict__ bias,
    int M, int Kd,
    const float* __restrict__ Xadd, int bn)
{
    extern __shared__ uint32_t dynb[];
    uint32_t (*AsB)[128][36] = reinterpret_cast<uint32_t(*)[128][36]>(dynb);
    uint32_t (*BsB)[32][136] = reinterpret_cast<uint32_t(*)[32][136]>(dynb + 2 * 128 * 36);

    Bp += (long long)blockIdx.z * bTs;

    const int m0 = blockIdx.y * 128;
    const int n0 = blockIdx.x * 128;
    const int tid = threadIdx.x;
    const int lane = tid & 31;
    const int wid = tid >> 5;
    const int g = lane >> 2, t = lane & 3;
    const int wm0 = (wid & 1) * 64;
    const int wn0 = (wid >> 1) * 32;

    const uint32_t as_base = (uint32_t)__cvta_generic_to_shared(&AsB[0][0][0]);
    const uint32_t lrow = ((lane >> 3) & 1) * 8 + (lane & 7);
    const uint32_t lpo  = (lane >> 4) * 4;

    float acc[4][4][4] = {};
    const int T = Kd >> 6;

    auto load_tiles = [&](int it, int s) {
        int k0 = it * 64;
        #pragma unroll
        for (int l = 0; l < 4; l++) {
            int idx = tid + l * 256;
            int r = idx >> 3, ch = idx & 7;
            bool p = (m0 + r < M);
            int row = p ? (m0 + r) : 0;
            cp16(&AsB[s][r][ch * 4], &A[(size_t)row * lda + k0 + ch * 8], p);
        }
        #pragma unroll
        for (int l = 0; l < 4; l++) {
            int idx = tid + l * 256;
            int r = idx >> 5, c = (idx & 31) * 4;
            cp16(&BsB[s][r][c], &Bp[(size_t)(k0 / 2 + r) * ldb + n0 + c], true);
        }
    };

    load_tiles(0, 0);
    CP_COMMIT();

    for (int i = 0; i < T; i++) {
        int cur = i & 1;
        if (i + 1 < T) { load_tiles(i + 1, cur ^ 1); CP_COMMIT(); CP_WAIT(1); }
        else          { CP_WAIT(0); }
        __syncthreads();
        uint32_t abase = as_base + (uint32_t)cur * (128 * 36 * 4);
        #pragma unroll
        for (int kk = 0; kk < 4; kk++) {
            uint32_t af[4][4], bf[4][2];
            #pragma unroll
            for (int mf = 0; mf < 4; mf++) {
                uint32_t addr = abase
                    + (uint32_t)(wm0 + mf * 16 + lrow) * (36 * 4)
                    + (uint32_t)(kk * 8 + lpo) * 4;
                ldmat_x4(af[mf], addr);
            }
            #pragma unroll
            for (int nf = 0; nf < 4; nf++) {
                bf[nf][0] = BsB[cur][kk * 8 + t    ][wn0 + nf * 8 + g];
                bf[nf][1] = BsB[cur][kk * 8 + t + 4][wn0 + nf * 8 + g];
            }
            #pragma unroll
            for (int mf = 0; mf < 4; mf++)
                #pragma unroll
                for (int nf = 0; nf < 4; nf++)
                    mma_bf16(acc[mf][nf], af[mf], bf[nf]);
        }
        __syncthreads();
    }

    float* C = (float*)Cv + (long long)blockIdx.z * cTs;
    __nv_bfloat16* Cb = (__nv_bfloat16*)Cv + (long long)blockIdx.z * cTs;
    float cs[4][2] = {}, cq[4][2] = {};

    #pragma unroll
    for (int mf = 0; mf < 4; mf++) {
        int row0 = m0 + wm0 + mf * 16 + g;
        int row1 = row0 + 8;
        #pragma unroll
        for (int nf = 0; nf < 4; nf++) {
            int n = n0 + wn0 + nf * 8 + 2 * t;
            float b0 = 0.f, b1 = 0.f;
            if (BIAS) { b0 = bias[n]; b1 = bias[n + 1]; }
            float2 v0 = make_float2(acc[mf][nf][0] + b0, acc[mf][nf][1] + b1);
            float2 v1 = make_float2(acc[mf][nf][2] + b0, acc[mf][nf][3] + b1);
            if (RELU) {
                v0.x = fmaxf(v0.x, 0.f); v0.y = fmaxf(v0.y, 0.f);
                v1.x = fmaxf(v1.x, 0.f); v1.y = fmaxf(v1.y, 0.f);
            }
            if (RND) {
                v0.x = tf32r(v0.x); v0.y = tf32r(v0.y);
                v1.x = tf32r(v1.x); v1.y = tf32r(v1.y);
            }
            if (row0 < M) {
                if (ADDST) {
                    v0.x += Xadd[(size_t)row0 * ldc + n];
                    v0.y += Xadd[(size_t)row0 * ldc + n + 1];
                    cs[nf][0] += v0.x; cq[nf][0] += v0.x * v0.x;
                    cs[nf][1] += v0.y; cq[nf][1] += v0.y * v0.y;
                }
                if (OUTBF) *reinterpret_cast<uint32_t*>(&Cb[(size_t)row0 * ldc + n]) = packbf(v0.x, v0.y);
                else       *reinterpret_cast<float2*>(&C[(size_t)row0 * ldc + n]) = v0;
            }
            if (row1 < M) {
                if (ADDST) {
                    v1.x += Xadd[(size_t)row1 * ldc + n];
                    v1.y += Xadd[(size_t)row1 * ldc + n + 1];
                    cs[nf][0] += v1.x; cq[nf][0] += v1.x * v1.x;
                    cs[nf][1] += v1.y; cq[nf][1] += v1.y * v1.y;
                }
                if (OUTBF) *reinterpret_cast<uint32_t*>(&Cb[(size_t)row1 * ldc + n]) = packbf(v1.x, v1.y);
                else       *reinterpret_cast<float2*>(&C[(size_t)row1 * ldc + n]) = v1;
            }
        }
    }

    if (ADDST) {
        #pragma unroll
        for (int nf = 0; nf < 4; nf++)
            #pragma unroll
            for (int c2 = 0; c2 < 2; c2++) {
                float s = cs[nf][c2], q = cq[nf][c2];
                #pragma unroll
                for (int off = 4; off < 32; off <<= 1) {
                    s += __shfl_xor_sync(0xffffffffu, s, off);
                    q += __shfl_xor_sync(0xffffffffu, q, off);
                }
                if (g == 0) {
                    int n = n0 + wn0 + nf * 8 + 2 * t + c2;
                    atomicAdd(&g_stats[(bn * 2 + 0) * DD + n], s);
                    atomicAdd(&g_stats[(bn * 2 + 1) * DD + n], q);
                }
            }
    }
}

// ---- fused: v_tile = relu(evc@u) in smem, then u2 += fs ⊙ (evc^T @ v_tile) --
__global__ void __launch_bounds__(256, 2) vfused_k(
    const __nv_bfloat16* __restrict__ evcb,
    const uint32_t* __restrict__ ubp,
    const float* __restrict__ fs,
    float* __restrict__ u2)
{
    extern __shared__ uint32_t dynb[];
    uint32_t (*AsB)[128][36] = reinterpret_cast<uint32_t(*)[128][36]>(dynb);
    uint32_t (*BsB)[32][136] = reinterpret_cast<uint32_t(*)[32][136]>(dynb + 2 * 128 * 36);
    __nv_bfloat16* Et = reinterpret_cast<__nv_bfloat16*>(dynb);            // [128][136]
    __nv_bfloat16* Vt = Et + 128 * 136;                                    // [128][136]

    const int m0 = blockIdx.y * 128;
    const int n0 = blockIdx.x * 128;
    const int tb = blockIdx.x;                 // t index (128-col block)
    const int tid = threadIdx.x;
    const int lane = tid & 31;
    const int wid = tid >> 5;
    const int g = lane >> 2, t = lane & 3;
    const int wm0 = (wid & 1) * 64;
    const int wn0 = (wid >> 1) * 32;

    const uint32_t as_base = (uint32_t)__cvta_generic_to_shared(&AsB[0][0][0]);
    const uint32_t lrow = ((lane >> 3) & 1) * 8 + (lane & 7);
    const uint32_t lpo  = (lane >> 4) * 4;

    float acc[4][4][4] = {};

    // phase 1: v_tile = relu(evcb[m0:m0+128, :] @ u[:, n0:n0+128])  (Kd = 128)
    auto load_tiles = [&](int it, int s) {
        int k0 = it * 64;
        #pragma unroll
        for (int l = 0; l < 4; l++) {
            int idx = tid + l * 256;
            int r = idx >> 3, ch = idx & 7;
            bool p = (m0 + r < NN);
            int row = p ? (m0 + r) : 0;
            cp16(&AsB[s][r][ch * 4], &evcb[(size_t)row * KK + k0 + ch * 8], p);
        }
        #pragma unroll
        for (int l = 0; l < 4; l++) {
            int idx = tid + l * 256;
            int r = idx >> 5, c = (idx & 31) * 4;
            cp16(&BsB[s][r][c], &ubp[(size_t)(k0 / 2 + r) * DD + n0 + c], true);
        }
    };

    load_tiles(0, 0);
    CP_COMMIT();
    for (int i = 0; i < 2; i++) {
        int cur = i;
        if (i == 0) { load_tiles(1, 1); CP_COMMIT(); CP_WAIT(1); }
        else        { CP_WAIT(0); }
        __syncthreads();
        uint32_t abase = as_base + (uint32_t)cur * (128 * 36 * 4);
        #pragma unroll
        for (int kk = 0; kk < 4; kk++) {
            uint32_t af[4][4], bf[4][2];
            #pragma unroll
            for (int mf = 0; mf < 4; mf++) {
                uint32_t addr = abase
                    + (uint32_t)(wm0 + mf * 16 + lrow) * (36 * 4)
                    + (uint32_t)(kk * 8 + lpo) * 4;
                ldmat_x4(af[mf], addr);
            }
            #pragma unroll
            for (int nf = 0; nf < 4; nf++) {
                bf[nf][0] = BsB[cur][kk * 8 + t    ][wn0 + nf * 8 + g];
                bf[nf][1] = BsB[cur][kk * 8 + t + 4][wn0 + nf * 8 + g];
            }
            #pragma unroll
            for (int mf = 0; mf < 4; mf++)
                #pragma unroll
                for (int nf = 0; nf < 4; nf++)
                    mma_bf16(acc[mf][nf], af[mf], bf[nf]);
        }
        __syncthreads();
    }

    // store v_tile to smem (rows >= NN hold zeros naturally)
    #pragma unroll
    for (int mf = 0; mf < 4; mf++) {
        int r0 = wm0 + mf * 16 + g;
        int r1 = r0 + 8;
        #pragma unroll
        for (int nf = 0; nf < 4; nf++) {
            int nl = wn0 + nf * 8 + 2 * t;
            float v0x = fmaxf(acc[mf][nf][0], 0.f), v0y = fmaxf(acc[mf][nf][1], 0.f);
            float v1x = fmaxf(acc[mf][nf][2], 0.f), v1y = fmaxf(acc[mf][nf][3], 0.f);
            *reinterpret_cast<uint32_t*>(&Vt[r0 * 136 + nl]) = packbf(v0x, v0y);
            *reinterpret_cast<uint32_t*>(&Vt[r1 * 136 + nl]) = packbf(v1x, v1y);
        }
    }

    // reload this CTA's evc tile (zero-filled past NN) into Et
    #pragma unroll
    for (int l = 0; l < 8; l++) {
        int idx = tid + l * 256;
        int r = idx >> 3, ch = idx & 7;
        bool p = (m0 + r < NN);
        int row = p ? (m0 + r) : 0;
        cp16(&Et[r * 136 + ch * 16], &evcb[(size_t)row * KK + ch * 16], p);
    }
    CP_COMMIT(); CP_WAIT(0);
    __syncthreads();

    // phase 2: u2[k, n0+j] += fs[k,tb] * sum_r evc[r][k] * v[r][j]
    const uint32_t et_base = (uint32_t)__cvta_generic_to_shared(Et);
    const uint32_t vt_base = (uint32_t)__cvta_generic_to_shared(Vt);
    const int I = lane >> 3, rr = lane & 7;
    const uint32_t RS = 136 * 2;

    #pragma unroll
    for (int mf = 0; mf < 4; mf++)
        #pragma unroll
        for (int nf = 0; nf < 4; nf++)
            #pragma unroll
            for (int q = 0; q < 4; q++) acc[mf][nf][q] = 0.f;

    #pragma unroll
    for (int chunk = 0; chunk < 4; chunk++) {
        #pragma unroll
        for (int kk = 0; kk < 2; kk++) {
            uint32_t af[4][4], bf[4][2];
            #pragma unroll
            for (int mf = 0; mf < 4; mf++) {
                uint32_t addr = et_base
                    + (uint32_t)(chunk * 32 + kk * 16 + (I >> 1) * 8 + rr) * RS
                    + (uint32_t)(wm0 + mf * 16 + (I & 1) * 8) * 2;
                ldmat_x4t(af[mf], addr);
            }
            #pragma unroll
            for (int nf2 = 0; nf2 < 2; nf2++) {
                uint32_t tmp[4];
                uint32_t addr = vt_base
                    + (uint32_t)(chunk * 32 + kk * 16 + (I & 1) * 8 + rr) * RS
                    + (uint32_t)(wn0 + nf2 * 16 + (I >> 1) * 8) * 2;
                ldmat_x4t(tmp, addr);
                bf[nf2 * 2    ][0] = tmp[0]; bf[nf2 * 2    ][1] = tmp[1];
                bf[nf2 * 2 + 1][0] = tmp[2]; bf[nf2 * 2 + 1][1] = tmp[3];
            }
            #pragma unroll
            for (int mf = 0; mf < 4; mf++)
                #pragma unroll
                for (int nf = 0; nf < 4; nf++)
                    mma_bf16(acc[mf][nf], af[mf], bf[nf]);
        }
    }

    #pragma unroll
    for (int mf = 0; mf < 4; mf++) {
        int k0 = wm0 + mf * 16 + g;
        int k1 = k0 + 8;
        float s0 = fs[k0 * TJc + tb];
        float s1 = fs[k1 * TJc + tb];
        #pragma unroll
        for (int nf = 0; nf < 4; nf++) {
            int j = n0 + wn0 + nf * 8 + 2 * t;
            float* p0 = &u2[(size_t)k0 * DD + j];
            float* p1 = &u2[(size_t)k1 * DD + j];
            asm volatile("red.global.add.v2.f32 [%0], {%1,%2};"
                         :: "l"(p0), "f"(s0 * acc[mf][nf][0]), "f"(s0 * acc[mf][nf][1]) : "memory");
            asm volatile("red.global.add.v2.f32 [%0], {%1,%2};"
                         :: "l"(p1), "f"(s1 * acc[mf][nf][2]), "f"(s1 * acc[mf][nf][3]) : "memory");
        }
    }
}

// ---------------- tf32 GEMM (tiny 128-row GEMMs) -----------------------------
template <bool CVTA>
__global__ void __launch_bounds__(256, 2) tcgemm_k(
    const float* __restrict__ A, int lda,
    const float* __restrict__ B, int ldb,
    float* __restrict__ C, int ldc,
    int M, int Kd)
{
    extern __shared__ uint32_t dyn[];
    uint32_t (*As)[128][36]  = reinterpret_cast<uint32_t(*)[128][36]>(dyn);
    uint32_t (*Bs)[32][136]  = reinterpret_cast<uint32_t(*)[32][136]>(dyn + 2 * 128 * 36);

    const int m0 = blockIdx.y * 128;
    const int n0 = blockIdx.x * 128;
    const int tid = threadIdx.x;
    const int lane = tid & 31;
    const int wid = tid >> 5;
    const int g = lane >> 2, t = lane & 3;
    const int wm0 = (wid & 1) * 64;
    const int wn0 = (wid >> 1) * 32;

    float acc[4][4][4] = {};
    const int T = Kd >> 5;

    auto load_tiles = [&](int it, int s) {
        int k0 = it * 32;
        #pragma unroll
        for (int l = 0; l < 4; l++) {
            int idx = tid + l * 256;
            int r = idx >> 3, c = (idx & 7) * 4;
            bool p = (m0 + r < M);
            int row = p ? (m0 + r) : 0;
            cp16(&As[s][r][c], &A[(size_t)row * lda + k0 + c], p);
        }
        #pragma unroll
        for (int l = 0; l < 4; l++) {
            int idx = tid + l * 256;
            int r = idx >> 5, c = (idx & 31) * 4;
            cp16(&Bs[s][r][c], &B[(size_t)(k0 + r) * ldb + n0 + c], true);
        }
    };

    load_tiles(0, 0);
    CP_COMMIT();

    for (int i = 0; i < T; i++) {
        int cur = i & 1;
        if (i + 1 < T) { load_tiles(i + 1, cur ^ 1); CP_COMMIT(); CP_WAIT(1); }
        else          { CP_WAIT(0); }
        __syncthreads();
        #pragma unroll
        for (int kk = 0; kk < 4; kk++) {
            uint32_t af[4][4], bf[4][2];
            #pragma unroll
            for (int mf = 0; mf < 4; mf++) {
                int mr = wm0 + mf * 16;
                uint32_t a0 = As[cur][mr + g    ][kk * 8 + t];
                uint32_t a1 = As[cur][mr + g + 8][kk * 8 + t];
                uint32_t a2 = As[cur][mr + g    ][kk * 8 + t + 4];
                uint32_t a3 = As[cur][mr + g + 8][kk * 8 + t + 4];
                if (CVTA) { a0 = cvt_rna(a0); a1 = cvt_rna(a1); a2 = cvt_rna(a2); a3 = cvt_rna(a3); }
                af[mf][0] = a0; af[mf][1] = a1; af[mf][2] = a2; af[mf][3] = a3;
            }
            #pragma unroll
            for (int nf = 0; nf < 4; nf++) {
                bf[nf][0] = Bs[cur][kk * 8 + t    ][wn0 + nf * 8 + g];
                bf[nf][1] = Bs[cur][kk * 8 + t + 4][wn0 + nf * 8 + g];
            }
            #pragma unroll
            for (int mf = 0; mf < 4; mf++)
                #pragma unroll
                for (int nf = 0; nf < 4; nf++)
                    mma_tf32(acc[mf][nf], af[mf], bf[nf]);
        }
        __syncthreads();
    }

    #pragma unroll
    for (int mf = 0; mf < 4; mf++) {
        int row0 = m0 + wm0 + mf * 16 + g;
        int row1 = row0 + 8;
        #pragma unroll
        for (int nf = 0; nf < 4; nf++) {
            int n = n0 + wn0 + nf * 8 + 2 * t;
            float2 v0 = make_float2(acc[mf][nf][0], acc[mf][nf][1]);
            float2 v1 = make_float2(acc[mf][nf][2], acc[mf][nf][3]);
            if (row0 < M) *reinterpret_cast<float2*>(&C[(size_t)row0 * ldc + n]) = v0;
            if (row1 < M) *reinterpret_cast<float2*>(&C[(size_t)row1 * ldc + n]) = v1;
        }
    }
}

// ------- tf32 tall reduction (x path): C[128,cols] += evc^T * B -------------
#define ATB_BLKS 64
template <bool CVTB>
__global__ void __launch_bounds__(256, 2) atb_k(
    const float* __restrict__ evc,
    const float* __restrict__ B, int ldb,
    float* __restrict__ C, int ldc)
{
    extern __shared__ uint32_t dyn[];
    uint32_t (*Es)[32][136] = reinterpret_cast<uint32_t(*)[32][136]>(dyn);
    uint32_t (*Hs)[32][136] = reinterpret_cast<uint32_t(*)[32][136]>(dyn + 2 * 32 * 136);

    const int noff = blockIdx.y * 128;

    const int chunk = (NN + ATB_BLKS - 1) / ATB_BLKS;
    const int nStart = blockIdx.x * chunk;
    const int nEnd = min(nStart + chunk, NN);
    const int iters = (chunk + 31) / 32;
    const int tid = threadIdx.x;
    const int lane = tid & 31;
    const int wid = tid >> 5;
    const int g = lane >> 2, t = lane & 3;
    const int wm0 = (wid & 1) * 64;
    const int wn0 = (wid >> 1) * 32;

    float acc[4][4][4] = {};

    auto load_tiles = [&](int it, int s) {
        int n0 = nStart + it * 32;
        #pragma unroll
        for (int l = 0; l < 4; l++) {
            int idx = tid + l * 256;
            int r = idx >> 5, c = (idx & 31) * 4;
            bool p = (n0 + r < nEnd);
            int row = p ? (n0 + r) : 0;
            cp16(&Es[s][r][c], &evc[(size_t)row * KK + c], p);
            cp16(&Hs[s][r][c], &B[(size_t)row * ldb + noff + c], p);
        }
    };

    load_tiles(0, 0);
    CP_COMMIT();

    for (int i = 0; i < iters; i++) {
        int cur = i & 1;
        if (i + 1 < iters) { load_tiles(i + 1, cur ^ 1); CP_COMMIT(); CP_WAIT(1); }
        else              { CP_WAIT(0); }
        __syncthreads();
        #pragma unroll
        for (int kk = 0; kk < 4; kk++) {
            uint32_t af[4][4], bf[4][2];
            #pragma unroll
            for (int mf = 0; mf < 4; mf++) {
                int mc = wm0 + mf * 16;
                af[mf][0] = Es[cur][kk * 8 + t    ][mc + g];
                af[mf][1] = Es[cur][kk * 8 + t    ][mc + g + 8];
                af[mf][2] = Es[cur][kk * 8 + t + 4][mc + g];
                af[mf][3] = Es[cur][kk * 8 + t + 4][mc + g + 8];
            }
            #pragma unroll
            for (int nf = 0; nf < 4; nf++) {
                uint32_t b0 = Hs[cur][kk * 8 + t    ][wn0 + nf * 8 + g];
                uint32_t b1 = Hs[cur][kk * 8 + t + 4][wn0 + nf * 8 + g];
                if (CVTB) { b0 = cvt_rna(b0); b1 = cvt_rna(b1); }
                bf[nf][0] = b0; bf[nf][1] = b1;
            }
            #pragma unroll
            for (int mf = 0; mf < 4; mf++)
                #pragma unroll
                for (int nf = 0; nf < 4; nf++)
                    mma_tf32(acc[mf][nf], af[mf], bf[nf]);
        }
        __syncthreads();
    }

    #pragma unroll
    for (int mf = 0; mf < 4; mf++) {
        int row0 = wm0 + mf * 16 + g;
        #pragma unroll
        for (int nf = 0; nf < 4; nf++) {
            int n = noff + wn0 + nf * 8 + 2 * t;
            float* p0 = &C[(size_t)row0 * ldc + n];
            float* p1 = &C[(size_t)(row0 + 8) * ldc + n];
            asm volatile("red.global.add.v2.f32 [%0], {%1,%2};"
                         :: "l"(p0), "f"(acc[mf][nf][0]), "f"(acc[mf][nf][1]) : "memory");
            asm volatile("red.global.add.v2.f32 [%0], {%1,%2};"
                         :: "l"(p1), "f"(acc[mf][nf][2]), "f"(acc[mf][nf][3]) : "memory");
        }
    }
}

// ---------------- graph: CSR build + gather ----------------------------------
__global__ void degi_k(const void* __restrict__ ei) {
    int e = blockIdx.x * blockDim.x + threadIdx.x;
    if (e < EE) atomicAdd(&g_degi[edge_at(ei, (long long)EE + e)], 1);
}
__global__ void dinv_k() {
    int n = blockIdx.x * blockDim.x + threadIdx.x;
    if (n < NN) g_deg[n] = rsqrtf((float)g_degi[n] + 1.0f);
}
__global__ void scan_k() {
    __shared__ int s[1024];
    int tid = threadIdx.x;
    const int per = (NN + 1023) / 1024;
    int start = tid * per, end = min(start + per, NN);
    int sum = 0;
    for (int i = start; i < end; i++) sum += g_degi[i];
    s[tid] = sum;
    __syncthreads();
    for (int off = 1; off < 1024; off <<= 1) {
        int v = 0;
        if (tid >= off) v = s[tid - off];
        __syncthreads();
        if (tid >= off) s[tid] += v;
        __syncthreads();
    }
    int base = s[tid] - sum;
    for (int i = start; i < end; i++) {
        g_off[i] = base; g_cur[i] = base;
        base += g_degi[i];
    }
    if (tid == 1023) g_off[NN] = base;
}
__global__ void fill_k(const void* __restrict__ ei) {
    int e = blockIdx.x * blockDim.x + threadIdx.x;
    if (e >= EE) return;
    int src = edge_at(ei, e);
    int dst = edge_at(ei, (long long)EE + e);
    int pos = atomicAdd(&g_cur[dst], 1);
    g_csrc[pos] = src;
}
__global__ void __launch_bounds__(128) gather_k(const float* __restrict__ x,
                                                const float* __restrict__ gcn_b) {
    const int n = blockIdx.x;
    const int c = threadIdx.x * 4;
    const int s0 = g_off[n], s1 = g_off[n + 1];
    const float dv = g_deg[n];
    float4 acc = make_float4(0.f, 0.f, 0.f, 0.f);
    int e = s0;
    #pragma unroll 1
    for (; e + 2 <= s1; e += 2) {
        int srcA = g_csrc[e], srcB = g_csrc[e + 1];
        float nA = dv * g_deg[srcA], nB = dv * g_deg[srcB];
        float4 vA = *reinterpret_cast<const float4*>(&g_xw[(size_t)srcA * DD + c]);
        float4 vB = *reinterpret_cast<const float4*>(&g_xw[(size_t)srcB * DD + c]);
        acc.x += nA * vA.x + nB * vB.x;
        acc.y += nA * vA.y + nB * vB.y;
        acc.z += nA * vA.z + nB * vB.z;
        acc.w += nA * vA.w + nB * vB.w;
    }
    if (e < s1) {
        int src = g_csrc[e];
        float nrm = dv * g_deg[src];
        float4 v = *reinterpret_cast<const float4*>(&g_xw[(size_t)src * DD + c]);
        acc.x += nrm * v.x; acc.y += nrm * v.y; acc.z += nrm * v.z; acc.w += nrm * v.w;
    }
    float4 xw = *reinterpret_cast<const float4*>(&g_xw[(size_t)n * DD + c]);
    float4 xr = *reinterpret_cast<const float4*>(&x[(size_t)n * DD + c]);
    float4 bb = *reinterpret_cast<const float4*>(&gcn_b[c]);
    float d2 = dv * dv;
    float4 o;
    o.x = xr.x + acc.x + d2 * xw.x + bb.x;
    o.y = xr.y + acc.y + d2 * xw.y + bb.y;
    o.z = xr.z + acc.z + d2 * xw.z + bb.z;
    o.w = xr.w + acc.w + d2 * xw.w + bb.w;
    *reinterpret_cast<float4*>(&g_bufL[(size_t)n * DD + c]) = o;
}
__global__ void stats0_k() {
    const int c = threadIdx.x;
    const int r0 = blockIdx.x * 128;
    const int rEnd = min(r0 + 128, NN);
    float s = 0.f, s2 = 0.f;
    for (int r = r0; r < rEnd; r++) {
        float v = g_bufL[(size_t)r * DD + c];
        s += v; s2 += v * v;
    }
    atomicAdd(&g_stats[0 * DD + c], s);
    atomicAdd(&g_stats[1 * DD + c], s2);
}

__global__ void finalize01_k(const float* __restrict__ g0, const float* __restrict__ b0,
                             const float* __restrict__ g1, const float* __restrict__ b1) {
    int bn = blockIdx.x;
    const float* gamma = bn ? g1 : g0;
    const float* beta  = bn ? b1 : b0;
    int c = threadIdx.x;
    float s  = g_stats[(bn * 2 + 0) * DD + c];
    float s2 = g_stats[(bn * 2 + 1) * DD + c];
    float m = s * (1.0f / NN);
    float var = s2 * (1.0f / NN) - m * m;
    float a = gamma[c] * rsqrtf(var + EPSC);
    g_coef[(bn * 2 + 0) * DD + c] = a;
    g_coef[(bn * 2 + 1) * DD + c] = beta[c] - m * a;
}
__global__ void finalize_k(int bn, const float* __restrict__ gamma, const float* __restrict__ beta) {
    int c = threadIdx.x;
    float s  = g_stats[(bn * 2 + 0) * DD + c];
    float s2 = g_stats[(bn * 2 + 1) * DD + c];
    float m = s * (1.0f / NN);
    float var = s2 * (1.0f / NN) - m * m;
    float a = gamma[c] * rsqrtf(var + EPSC);
    g_coef[(bn * 2 + 0) * DD + c] = a;
    g_coef[(bn * 2 + 1) * DD + c] = beta[c] - m * a;
}

__global__ void apply_sum_k() {
    int i = blockIdx.x * blockDim.x + threadIdx.x;
    if (i >= NN * DD / 4) return;
    int base = i * 4;
    int c = base & (DD - 1);
    float4 bl = *reinterpret_cast<const float4*>(&g_bufL[base]);
    float4 ba = *reinterpret_cast<const float4*>(&g_bufA[base]);
    float4 a0 = *reinterpret_cast<const float4*>(&g_coef[c]);
    float4 b0 = *reinterpret_cast<const float4*>(&g_coef[DD + c]);
    float4 a1 = *reinterpret_cast<const float4*>(&g_coef[2 * DD + c]);
    float4 b1 = *reinterpret_cast<const float4*>(&g_coef[3 * DD + c]);
    float4 v;
    v.x = bl.x * a0.x + b0.x + ba.x * a1.x + b1.x;
    v.y = bl.y * a0.y + b0.y + ba.y * a1.y + b1.y;
    v.z = bl.z * a0.z + b0.z + ba.z * a1.z + b1.z;
    v.w = bl.w * a0.w + b0.w + ba.w * a1.w + b1.w;
    *reinterpret_cast<float4*>(&g_h[base]) = v;
    uint2 p = make_uint2(packbf(v.x, v.y), packbf(v.z, v.w));
    *reinterpret_cast<uint2*>(&g_hb[base]) = p;
}
__global__ void bn2_apply_k(float* __restrict__ out) {
    int i = blockIdx.x * blockDim.x + threadIdx.x;
    if (i >= NN * DD / 4) return;
    int base = i * 4;
    int c = base & (DD - 1);
    float4 f = *reinterpret_cast<const float4*>(&g_ff[base]);
    float4 a = *reinterpret_cast<const float4*>(&g_coef[4 * DD + c]);
    float4 b = *reinterpret_cast<const float4*>(&g_coef[5 * DD + c]);
    float4 v;
    v.x = f.x * a.x + b.x;
    v.y = f.y * a.y + b.y;
    v.z = f.z * a.z + b.z;
    v.w = f.w * a.w + b.w;
    *reinterpret_cast<float4*>(&out[base]) = v;
}

// ---------------- wave helpers ----------------------------------------------
__global__ void pack_w_k(const float* __restrict__ linW, const float* __restrict__ fW) {
    int idx = blockIdx.x * blockDim.x + threadIdx.x;
    if (idx >= DD * DD) return;
    int d = idx >> 9, j = idx & 511;
    int t = j >> 7, s = j & 127;
    g_linWp[idx] = tf32r(linW[t * (DD * SSc) + d * SSc + s]);
    g_fWt[idx]   = tf32r(fW[idx]);
}
__global__ void post_u_k(const float* __restrict__ fs, const float* __restrict__ linB) {
    int idx = blockIdx.x * blockDim.x + threadIdx.x;
    if (idx >= (KK / 2) * DD) return;
    int kp = idx >> 9, j = idx & 511;
    int t = j >> 7, s = j & 127;
    float bl = linB[t * SSc + s];
    int k0 = 2 * kp, k1 = 2 * kp + 1;
    float v0 = fs[k0 * TJc + t] * (g_uraw[k0 * DD + j] + g_esum[k0] * bl);
    float v1 = fs[k1 * TJc + t] * (g_uraw[k1 * DD + j] + g_esum[k1] * bl);
    g_ubp[idx] = packbf(v0, v1);
}

// ---------------- streams/events ----------------------------------------------
static cudaStream_t s_gcn = nullptr, s_aux = nullptr;
static cudaEvent_t ev_fork = nullptr, ev_xw = nullptr, ev_join = nullptr, ev_aux = nullptr;
namespace { struct StreamInit {
    StreamInit() {
        cudaStreamCreateWithFlags(&s_gcn, cudaStreamNonBlocking);
        cudaStreamCreateWithFlags(&s_aux, cudaStreamNonBlocking);
        cudaEventCreateWithFlags(&ev_fork, cudaEventDisableTiming);
        cudaEventCreateWithFlags(&ev_xw,   cudaEventDisableTiming);
        cudaEventCreateWithFlags(&ev_join, cudaEventDisableTiming);
        cudaEventCreateWithFlags(&ev_aux,  cudaEventDisableTiming);
    }
} s_init; }

// ---------------- launch -----------------------------------------------------
#define GSYM(p, ty, s) do { void* _t; cudaGetSymbolAddress(&_t, s); (p) = (ty)_t; } while (0)

extern "C" void kernel_launch(void* const* d_in, const int* in_sizes, int n_in,
                              void* d_out, int out_size) {
    const float* x        = (const float*)d_in[0];
    const void*  ei       = d_in[1];
    const float* evc      = (const float*)d_in[2];
    const float* fs       = (const float*)d_in[3];
    const float* gcn_W    = (const float*)d_in[4];
    const float* gcn_b    = (const float*)d_in[5];
    const float* lin_W    = (const float*)d_in[6];
    const float* lin_b    = (const float*)d_in[7];
    const float* fusion_W = (const float*)d_in[8];
    const float* fusion_b = (const float*)d_in[9];
    const float* bn1l_g   = (const float*)d_in[10];
    const float* bn1l_b   = (const float*)d_in[11];
    const float* bn1a_g   = (const float*)d_in[12];
    const float* bn1a_b   = (const float*)d_in[13];
    const float* bn2_g    = (const float*)d_in[14];
    const float* bn2_b    = (const float*)d_in[15];
    const float* ff1_W    = (const float*)d_in[16];
    const float* ff1_b    = (const float*)d_in[17];
    const float* ff2_W    = (const float*)d_in[18];
    const float* ff2_b    = (const float*)d_in[19];
    float* out = (float*)d_out;

    float *p_xw, *p_bufL, *p_bufA, *p_h, *p_ff, *p_evct;
    float *p_xe, *p_uraw, *p_u2, *p_W2, *p_linWp, *p_fWt;
    __nv_bfloat16 *p_xb, *p_evcb, *p_hb, *p_midb;
    uint32_t *p_gWbp, *p_f1Wbp, *p_f2Wbp, *p_W2bp, *p_ubp;
    GSYM(p_xw, float*, g_xw);     GSYM(p_bufL, float*, g_bufL);
    GSYM(p_bufA, float*, g_bufA); GSYM(p_h, float*, g_h);       GSYM(p_ff, float*, g_ff);
    GSYM(p_evct, float*, g_evct);
    GSYM(p_xe, float*, g_xe);     GSYM(p_uraw, float*, g_uraw);
    GSYM(p_u2, float*, g_u2);     GSYM(p_W2, float*, g_W2);
    GSYM(p_linWp, float*, g_linWp); GSYM(p_fWt, float*, g_fWt);
    GSYM(p_xb, __nv_bfloat16*, g_xb);   GSYM(p_evcb, __nv_bfloat16*, g_evcb);
    GSYM(p_hb, __nv_bfloat16*, g_hb);   GSYM(p_midb, __nv_bfloat16*, g_midb);
    GSYM(p_gWbp, uint32_t*, g_gWbp);    GSYM(p_f1Wbp, uint32_t*, g_f1Wbp);
    GSYM(p_f2Wbp, uint32_t*, g_f2Wbp);  GSYM(p_W2bp, uint32_t*, g_W2bp);
    GSYM(p_ubp, uint32_t*, g_ubp);

    const int GEMM_SMEM = (2 * 128 * 36 + 2 * 32 * 136) * 4;   // 71680
    const int BF_SMEM   = GEMM_SMEM;
    const int ATB_SMEM  = (2 * 32 * 136 * 2) * 4;
    cudaFuncSetAttribute(tcgemm_k<false>, cudaFuncAttributeMaxDynamicSharedMemorySize, GEMM_SMEM);
    cudaFuncSetAttribute(tcgemm_k<true>,  cudaFuncAttributeMaxDynamicSharedMemorySize, GEMM_SMEM);
    cudaFuncSetAttribute(atb_k<true>,  cudaFuncAttributeMaxDynamicSharedMemorySize, ATB_SMEM);
    cudaFuncSetAttribute(vfused_k, cudaFuncAttributeMaxDynamicSharedMemorySize, BF_SMEM);
    cudaFuncSetAttribute(bfgemm_k<false, false, false, false, false>, cudaFuncAttributeMaxDynamicSharedMemorySize, BF_SMEM);
    cudaFuncSetAttribute(bfgemm_k<true,  true,  false, false, true >, cudaFuncAttributeMaxDynamicSharedMemorySize, BF_SMEM);
    cudaFuncSetAttribute(bfgemm_k<true,  true,  false, true,  false>, cudaFuncAttributeMaxDynamicSharedMemorySize, BF_SMEM);
    cudaFuncSetAttribute(bfgemm_k<true,  false, false, false, true >, cudaFuncAttributeMaxDynamicSharedMemorySize, BF_SMEM);

    const int MB = (NN + 127) / 128;
    dim3 gD(4, MB);
    dim3 gF(8, MB);
    dim3 gTiny(4, 1);
    dim3 gAtbX(ATB_BLKS, 4, 1);

    detect_k<<<1, 256>>>((const int*)ei);
    zero_scratch_k<<<1024, 256>>>();

    // ---- fork ----
    cudaEventRecord(ev_fork, 0);
    cudaStreamWaitEvent(s_gcn, ev_fork, 0);
    cudaStreamWaitEvent(s_aux, ev_fork, 0);

    // s_gcn: CSR build
    degi_k<<<(EE + 255) / 256, 256, 0, s_gcn>>>(ei);
    dinv_k<<<(NN + 255) / 256, 256, 0, s_gcn>>>();
    scan_k<<<1, 1024, 0, s_gcn>>>();
    fill_k<<<(EE + 255) / 256, 256, 0, s_gcn>>>(ei);

    // s_aux: weight packs
    pack_w_k<<<(DD * DD + 255) / 256, 256, 0, s_aux>>>(lin_W, fusion_W);
    packpairs_k<<<((DD / 2) * DD2 + 255) / 256, 256, 0, s_aux>>>(ff1_W, p_f1Wbp, DD2, (DD / 2) * DD2);
    packpairs_k<<<((DD2 / 2) * DD + 255) / 256, 256, 0, s_aux>>>(ff2_W, p_f2Wbp, DD, (DD2 / 2) * DD);
    cudaEventRecord(ev_aux, s_aux);

    // main: prep + xw GEMM
    packpairs_k<<<((DD / 2) * DD + 255) / 256, 256>>>(gcn_W, p_gWbp, DD, (DD / 2) * DD);
    prep_evc_k<<<(NN + 249) / 250, KK>>>(evc);
    tobf_k<<<1024, 256>>>(x, p_xb, (long long)NN * DD);
    bfgemm_k<false, false, false, false, false><<<gD, 256, BF_SMEM>>>(
        p_xb, DD, p_gWbp, DD, 0, p_xw, DD, 0, nullptr, NN, DD, nullptr, 0);
    cudaEventRecord(ev_xw, 0);

    // s_gcn: gather + BN0 stats
    cudaStreamWaitEvent(s_gcn, ev_xw, 0);
    gather_k<<<NN, 128, 0, s_gcn>>>(x, gcn_b);
    stats0_k<<<MB, DD, 0, s_gcn>>>();
    cudaEventRecord(ev_join, s_gcn);

    // main: wave branch
    atb_k<true><<<gAtbX, 256, ATB_SMEM>>>(p_evct, x, DD, p_xe, DD);
    cudaStreamWaitEvent(0, ev_aux, 0);
    tcgemm_k<true><<<gTiny, 256, GEMM_SMEM>>>(p_xe, DD, p_linWp, DD, p_uraw, DD, KK, DD);
    post_u_k<<<((KK / 2) * DD + 255) / 256, 256>>>(fs, lin_b);
    // fused: v tile in smem, u2 += fs ⊙ evc^T v  (v never hits DRAM)
    vfused_k<<<gD, 256, BF_SMEM>>>(p_evcb, p_ubp, fs, p_u2);
    tcgemm_k<true><<<gTiny, 256, GEMM_SMEM>>>(p_u2, DD, p_fWt, DD, p_W2, DD, KK, DD);
    packpairs_k<<<((KK / 2) * DD + 255) / 256, 256>>>(p_W2, p_W2bp, DD, (KK / 2) * DD);
    bfgemm_k<true, true, false, false, true><<<gD, 256, BF_SMEM>>>(
        p_evcb, KK, p_W2bp, DD, 0, p_bufA, DD, 0, fusion_b, NN, KK, x, 1);

    // ---- join + BN ----
    cudaStreamWaitEvent(0, ev_join, 0);
    finalize01_k<<<2, DD>>>(bn1l_g, bn1l_b, bn1a_g, bn1a_b);
    apply_sum_k<<<(NN * DD / 4 + 255) / 256, 256>>>();

    // ---- feed-forward ----
    bfgemm_k<true, true, false, true, false><<<gF, 256, BF_SMEM>>>(
        p_hb, DD, p_f1Wbp, DD2, 0, p_midb, DD2, 0, ff1_b, NN, DD, nullptr, 0);
    bfgemm_k<true, false, false, false, true><<<gD, 256, BF_SMEM>>>(
        p_midb, DD2, p_f2Wbp, DD, 0, p_ff, DD, 0, ff2_b, NN, DD2, p_h, 2);
    finalize_k<<<1, DD>>>(2, bn2_g, bn2_b);
    bn2_apply_k<<<(NN * DD / 4 + 255) / 256, 256>>>(out);
}

// round 17
// speedup vs baseline: 1.1201x; 1.0473x over previous
#include <cuda_runtime.h>
#include <cuda_bf16.h>
#include <cstdint>

#define NN  50000
#define EE  800000
#define DD  512
#define KK  128
#define TJc 4
#define SSc 128
#define DD2 1024
#define EPSC 1e-5f

// ---------------- scratch (device globals) -----------------------------------
__device__ float g_xw  [(size_t)NN * DD];
__device__ float g_bufL[(size_t)NN * DD];
__device__ float g_bufA[(size_t)NN * DD];
__device__ float g_h   [(size_t)NN * DD];
__device__ float g_ff  [(size_t)NN * DD];
__device__ float g_evct[(size_t)NN * KK];
__device__ __nv_bfloat16 g_xb  [(size_t)NN * DD];
__device__ __nv_bfloat16 g_evcb[(size_t)NN * KK];
__device__ __nv_bfloat16 g_hb  [(size_t)NN * DD];
__device__ __nv_bfloat16 g_midb[(size_t)NN * DD2];
__device__ uint32_t g_gWbp [(DD / 2) * DD];
__device__ uint32_t g_f1Wbp[(DD / 2) * DD2];
__device__ uint32_t g_f2Wbp[(DD2 / 2) * DD];
__device__ uint32_t g_W2bp [(KK / 2) * DD];
__device__ uint32_t g_ubp  [(KK / 2) * DD];
__device__ float g_deg [NN];
__device__ int   g_degi[NN];
__device__ int   g_off [NN + 1];
__device__ int   g_cur [NN];
__device__ int   g_csrc[EE];
__device__ float g_esum[KK];
__device__ float g_xe  [KK * DD];
__device__ float g_uraw[KK * DD];
__device__ float g_u2  [KK * DD];
__device__ float g_W2  [KK * DD];
__device__ float g_stats[6 * DD];
__device__ float g_coef [6 * DD];
__device__ float g_linWp[DD * DD];
__device__ float g_fWt  [DD * DD];
__device__ int   g_is64;

// ---------------- helpers -----------------------------------------------------
__device__ __forceinline__ float tf32r(float f) {
    uint32_t u; asm("cvt.rna.tf32.f32 %0, %1;" : "=r"(u) : "f"(f));
    return __uint_as_float(u);
}
__device__ __forceinline__ uint32_t cvt_rna(uint32_t x) {
    uint32_t u; float f = __uint_as_float(x);
    asm("cvt.rna.tf32.f32 %0, %1;" : "=r"(u) : "f"(f)); return u;
}
__device__ __forceinline__ uint32_t packbf(float lo, float hi) {
    uint32_t r; asm("cvt.rn.bf16x2.f32 %0, %1, %2;" : "=r"(r) : "f"(hi), "f"(lo));
    return r;
}
__device__ __forceinline__ void mma_tf32(float* c, const uint32_t* a, const uint32_t* b) {
    asm volatile("mma.sync.aligned.m16n8k8.row.col.f32.tf32.tf32.f32 "
        "{%0,%1,%2,%3}, {%4,%5,%6,%7}, {%8,%9}, {%0,%1,%2,%3};"
        : "+f"(c[0]), "+f"(c[1]), "+f"(c[2]), "+f"(c[3])
        : "r"(a[0]), "r"(a[1]), "r"(a[2]), "r"(a[3]), "r"(b[0]), "r"(b[1]));
}
__device__ __forceinline__ void mma_bf16(float* c, const uint32_t* a, const uint32_t* b) {
    asm volatile("mma.sync.aligned.m16n8k16.row.col.f32.bf16.bf16.f32 "
        "{%0,%1,%2,%3}, {%4,%5,%6,%7}, {%8,%9}, {%0,%1,%2,%3};"
        : "+f"(c[0]), "+f"(c[1]), "+f"(c[2]), "+f"(c[3])
        : "r"(a[0]), "r"(a[1]), "r"(a[2]), "r"(a[3]), "r"(b[0]), "r"(b[1]));
}
__device__ __forceinline__ void ldmat_x4(uint32_t* r, uint32_t saddr) {
    asm volatile("ldmatrix.sync.aligned.m8n8.x4.shared.b16 {%0,%1,%2,%3}, [%4];"
        : "=r"(r[0]), "=r"(r[1]), "=r"(r[2]), "=r"(r[3]) : "r"(saddr));
}
__device__ __forceinline__ void ldmat_x4t(uint32_t* r, uint32_t saddr) {
    asm volatile("ldmatrix.sync.aligned.m8n8.x4.trans.shared.b16 {%0,%1,%2,%3}, [%4];"
        : "=r"(r[0]), "=r"(r[1]), "=r"(r[2]), "=r"(r[3]) : "r"(saddr));
}
__device__ __forceinline__ void cp16(void* sdst, const void* gsrc, bool pred) {
    uint32_t sa = (uint32_t)__cvta_generic_to_shared(sdst);
    int sz = pred ? 16 : 0;
    asm volatile("cp.async.cg.shared.global [%0], [%1], 16, %2;"
                 :: "r"(sa), "l"(gsrc), "r"(sz));
}
#define CP_COMMIT() asm volatile("cp.async.commit_group;")
#define CP_WAIT(n)  asm volatile("cp.async.wait_group %0;" :: "n"(n))

__device__ __forceinline__ int edge_at(const void* ei, long long pos) {
    return g_is64 ? (int)((const long long*)ei)[pos] : ((const int*)ei)[pos];
}

// ---------------- zero scratch + edge dtype detect (block 0) -----------------
__global__ void zero_scratch_k(const int* __restrict__ ei32) {
    if (blockIdx.x == 0) {
        __shared__ int any;
        if (threadIdx.x == 0) any = 0;
        __syncthreads();
        int v = 0;
        for (int i = threadIdx.x; i < 1024; i += blockDim.x)
            v |= ei32[2 * i + 1];
        if (v) atomicOr(&any, 1);
        __syncthreads();
        if (threadIdx.x == 0) g_is64 = (any == 0) ? 1 : 0;
    }
    int stride = gridDim.x * blockDim.x;
    int i0 = blockIdx.x * blockDim.x + threadIdx.x;
    for (int i = i0; i < NN; i += stride) g_degi[i] = 0;
    for (int i = i0; i < KK * DD; i += stride) { g_xe[i] = 0.f; g_u2[i] = 0.f; }
    for (int i = i0; i < 6 * DD; i += stride) g_stats[i] = 0.f;
    for (int i = i0; i < KK; i += stride) g_esum[i] = 0.f;
}
__global__ void tobf_k(const float* __restrict__ in, __nv_bfloat16* __restrict__ o, long long n) {
    long long i = (long long)blockIdx.x * blockDim.x + threadIdx.x;
    long long stride = (long long)gridDim.x * blockDim.x;
    for (; i < n / 4; i += stride) {
        float4 v = reinterpret_cast<const float4*>(in)[i];
        uint2 p = make_uint2(packbf(v.x, v.y), packbf(v.z, v.w));
        reinterpret_cast<uint2*>(o)[i] = p;
    }
}
__global__ void packpairs_k(const float* __restrict__ W, uint32_t* __restrict__ Wp,
                            int Ncols, int total) {
    int idx = blockIdx.x * blockDim.x + threadIdx.x;
    if (idx >= total) return;
    int kp = idx / Ncols, n = idx - kp * Ncols;
    Wp[idx] = packbf(W[(size_t)(2 * kp) * Ncols + n], W[(size_t)(2 * kp + 1) * Ncols + n]);
}
__global__ void prep_evc_k(const float* __restrict__ evc) {
    int c = threadIdx.x;
    int r0 = blockIdx.x * 250;
    int r1 = min(r0 + 250, NN);
    float s = 0.f;
    for (int r = r0; r < r1; r++) {
        float v = evc[(size_t)r * KK + c];
        s += v;
        g_evct[(size_t)r * KK + c] = tf32r(v);
        g_evcb[(size_t)r * KK + c] = __float2bfloat16_rn(v);
    }
    atomicAdd(&g_esum[c], s);
}

// ---------------- bf16 tensor-core GEMM (k64, 2-stage, ldmatrix A) -----------
template <bool BIAS, bool RELU, bool RND, bool OUTBF, bool ADDST>
__global__ void __launch_bounds__(256, 2) bfgemm_k(
    const __nv_bfloat16* __restrict__ A, int lda,
    const uint32_t* __restrict__ Bp, int ldb, long long bTs,
    void* __restrict__ Cv, int ldc, long long cTs,
    const float* __restrict__ bias,
    int M, int Kd,
    const float* __restrict__ Xadd, int bn)
{
    extern __shared__ uint32_t dynb[];
    uint32_t (*AsB)[128][36] = reinterpret_cast<uint32_t(*)[128][36]>(dynb);
    uint32_t (*BsB)[32][136] = reinterpret_cast<uint32_t(*)[32][136]>(dynb + 2 * 128 * 36);

    Bp += (long long)blockIdx.z * bTs;

    const int m0 = blockIdx.y * 128;
    const int n0 = blockIdx.x * 128;
    const int tid = threadIdx.x;
    const int lane = tid & 31;
    const int wid = tid >> 5;
    const int g = lane >> 2, t = lane & 3;
    const int wm0 = (wid & 1) * 64;
    const int wn0 = (wid >> 1) * 32;

    const uint32_t as_base = (uint32_t)__cvta_generic_to_shared(&AsB[0][0][0]);
    const uint32_t lrow = ((lane >> 3) & 1) * 8 + (lane & 7);
    const uint32_t lpo  = (lane >> 4) * 4;

    float acc[4][4][4] = {};
    const int T = Kd >> 6;

    auto load_tiles = [&](int it, int s) {
        int k0 = it * 64;
        #pragma unroll
        for (int l = 0; l < 4; l++) {
            int idx = tid + l * 256;
            int r = idx >> 3, ch = idx & 7;
            bool p = (m0 + r < M);
            int row = p ? (m0 + r) : 0;
            cp16(&AsB[s][r][ch * 4], &A[(size_t)row * lda + k0 + ch * 8], p);
        }
        #pragma unroll
        for (int l = 0; l < 4; l++) {
            int idx = tid + l * 256;
            int r = idx >> 5, c = (idx & 31) * 4;
            cp16(&BsB[s][r][c], &Bp[(size_t)(k0 / 2 + r) * ldb + n0 + c], true);
        }
    };

    load_tiles(0, 0);
    CP_COMMIT();

    for (int i = 0; i < T; i++) {
        int cur = i & 1;
        if (i + 1 < T) { load_tiles(i + 1, cur ^ 1); CP_COMMIT(); CP_WAIT(1); }
        else          { CP_WAIT(0); }
        __syncthreads();
        uint32_t abase = as_base + (uint32_t)cur * (128 * 36 * 4);
        #pragma unroll
        for (int kk = 0; kk < 4; kk++) {
            uint32_t af[4][4], bf[4][2];
            #pragma unroll
            for (int mf = 0; mf < 4; mf++) {
                uint32_t addr = abase
                    + (uint32_t)(wm0 + mf * 16 + lrow) * (36 * 4)
                    + (uint32_t)(kk * 8 + lpo) * 4;
                ldmat_x4(af[mf], addr);
            }
            #pragma unroll
            for (int nf = 0; nf < 4; nf++) {
                bf[nf][0] = BsB[cur][kk * 8 + t    ][wn0 + nf * 8 + g];
                bf[nf][1] = BsB[cur][kk * 8 + t + 4][wn0 + nf * 8 + g];
            }
            #pragma unroll
            for (int mf = 0; mf < 4; mf++)
                #pragma unroll
                for (int nf = 0; nf < 4; nf++)
                    mma_bf16(acc[mf][nf], af[mf], bf[nf]);
        }
        __syncthreads();
    }

    float* C = (float*)Cv + (long long)blockIdx.z * cTs;
    __nv_bfloat16* Cb = (__nv_bfloat16*)Cv + (long long)blockIdx.z * cTs;
    float cs[4][2] = {}, cq[4][2] = {};

    #pragma unroll
    for (int mf = 0; mf < 4; mf++) {
        int row0 = m0 + wm0 + mf * 16 + g;
        int row1 = row0 + 8;
        #pragma unroll
        for (int nf = 0; nf < 4; nf++) {
            int n = n0 + wn0 + nf * 8 + 2 * t;
            float b0 = 0.f, b1 = 0.f;
            if (BIAS) { b0 = bias[n]; b1 = bias[n + 1]; }
            float2 v0 = make_float2(acc[mf][nf][0] + b0, acc[mf][nf][1] + b1);
            float2 v1 = make_float2(acc[mf][nf][2] + b0, acc[mf][nf][3] + b1);
            if (RELU) {
                v0.x = fmaxf(v0.x, 0.f); v0.y = fmaxf(v0.y, 0.f);
                v1.x = fmaxf(v1.x, 0.f); v1.y = fmaxf(v1.y, 0.f);
            }
            if (RND) {
                v0.x = tf32r(v0.x); v0.y = tf32r(v0.y);
                v1.x = tf32r(v1.x); v1.y = tf32r(v1.y);
            }
            if (row0 < M) {
                if (ADDST) {
                    v0.x += Xadd[(size_t)row0 * ldc + n];
                    v0.y += Xadd[(size_t)row0 * ldc + n + 1];
                    cs[nf][0] += v0.x; cq[nf][0] += v0.x * v0.x;
                    cs[nf][1] += v0.y; cq[nf][1] += v0.y * v0.y;
                }
                if (OUTBF) *reinterpret_cast<uint32_t*>(&Cb[(size_t)row0 * ldc + n]) = packbf(v0.x, v0.y);
                else       *reinterpret_cast<float2*>(&C[(size_t)row0 * ldc + n]) = v0;
            }
            if (row1 < M) {
                if (ADDST) {
                    v1.x += Xadd[(size_t)row1 * ldc + n];
                    v1.y += Xadd[(size_t)row1 * ldc + n + 1];
                    cs[nf][0] += v1.x; cq[nf][0] += v1.x * v1.x;
                    cs[nf][1] += v1.y; cq[nf][1] += v1.y * v1.y;
                }
                if (OUTBF) *reinterpret_cast<uint32_t*>(&Cb[(size_t)row1 * ldc + n]) = packbf(v1.x, v1.y);
                else       *reinterpret_cast<float2*>(&C[(size_t)row1 * ldc + n]) = v1;
            }
        }
    }

    if (ADDST) {
        #pragma unroll
        for (int nf = 0; nf < 4; nf++)
            #pragma unroll
            for (int c2 = 0; c2 < 2; c2++) {
                float s = cs[nf][c2], q = cq[nf][c2];
                #pragma unroll
                for (int off = 4; off < 32; off <<= 1) {
                    s += __shfl_xor_sync(0xffffffffu, s, off);
                    q += __shfl_xor_sync(0xffffffffu, q, off);
                }
                if (g == 0) {
                    int n = n0 + wn0 + nf * 8 + 2 * t + c2;
                    atomicAdd(&g_stats[(bn * 2 + 0) * DD + n], s);
                    atomicAdd(&g_stats[(bn * 2 + 1) * DD + n], q);
                }
            }
    }
}

// ---- fused: v_tile = relu(evc@u) in smem, then u2 += fs ⊙ (evc^T @ v_tile) --
__global__ void __launch_bounds__(256, 2) vfused_k(
    const __nv_bfloat16* __restrict__ evcb,
    const uint32_t* __restrict__ ubp,
    const float* __restrict__ fs,
    float* __restrict__ u2)
{
    extern __shared__ uint32_t dynb[];
    uint32_t (*AsB)[128][36] = reinterpret_cast<uint32_t(*)[128][36]>(dynb);
    uint32_t (*BsB)[32][136] = reinterpret_cast<uint32_t(*)[32][136]>(dynb + 2 * 128 * 36);
    __nv_bfloat16* Et = reinterpret_cast<__nv_bfloat16*>(dynb);
    __nv_bfloat16* Vt = Et + 128 * 136;

    const int m0 = blockIdx.y * 128;
    const int n0 = blockIdx.x * 128;
    const int tb = blockIdx.x;
    const int tid = threadIdx.x;
    const int lane = tid & 31;
    const int wid = tid >> 5;
    const int g = lane >> 2, t = lane & 3;
    const int wm0 = (wid & 1) * 64;
    const int wn0 = (wid >> 1) * 32;

    const uint32_t as_base = (uint32_t)__cvta_generic_to_shared(&AsB[0][0][0]);
    const uint32_t lrow = ((lane >> 3) & 1) * 8 + (lane & 7);
    const uint32_t lpo  = (lane >> 4) * 4;

    float acc[4][4][4] = {};

    auto load_tiles = [&](int it, int s) {
        int k0 = it * 64;
        #pragma unroll
        for (int l = 0; l < 4; l++) {
            int idx = tid + l * 256;
            int r = idx >> 3, ch = idx & 7;
            bool p = (m0 + r < NN);
            int row = p ? (m0 + r) : 0;
            cp16(&AsB[s][r][ch * 4], &evcb[(size_t)row * KK + k0 + ch * 8], p);
        }
        #pragma unroll
        for (int l = 0; l < 4; l++) {
            int idx = tid + l * 256;
            int r = idx >> 5, c = (idx & 31) * 4;
            cp16(&BsB[s][r][c], &ubp[(size_t)(k0 / 2 + r) * DD + n0 + c], true);
        }
    };

    load_tiles(0, 0);
    CP_COMMIT();
    for (int i = 0; i < 2; i++) {
        int cur = i;
        if (i == 0) { load_tiles(1, 1); CP_COMMIT(); CP_WAIT(1); }
        else        { CP_WAIT(0); }
        __syncthreads();
        uint32_t abase = as_base + (uint32_t)cur * (128 * 36 * 4);
        #pragma unroll
        for (int kk = 0; kk < 4; kk++) {
            uint32_t af[4][4], bf[4][2];
            #pragma unroll
            for (int mf = 0; mf < 4; mf++) {
                uint32_t addr = abase
                    + (uint32_t)(wm0 + mf * 16 + lrow) * (36 * 4)
                    + (uint32_t)(kk * 8 + lpo) * 4;
                ldmat_x4(af[mf], addr);
            }
            #pragma unroll
            for (int nf = 0; nf < 4; nf++) {
                bf[nf][0] = BsB[cur][kk * 8 + t    ][wn0 + nf * 8 + g];
                bf[nf][1] = BsB[cur][kk * 8 + t + 4][wn0 + nf * 8 + g];
            }
            #pragma unroll
            for (int mf = 0; mf < 4; mf++)
                #pragma unroll
                for (int nf = 0; nf < 4; nf++)
                    mma_bf16(acc[mf][nf], af[mf], bf[nf]);
        }
        __syncthreads();
    }

    #pragma unroll
    for (int mf = 0; mf < 4; mf++) {
        int r0 = wm0 + mf * 16 + g;
        int r1 = r0 + 8;
        #pragma unroll
        for (int nf = 0; nf < 4; nf++) {
            int nl = wn0 + nf * 8 + 2 * t;
            float v0x = fmaxf(acc[mf][nf][0], 0.f), v0y = fmaxf(acc[mf][nf][1], 0.f);
            float v1x = fmaxf(acc[mf][nf][2], 0.f), v1y = fmaxf(acc[mf][nf][3], 0.f);
            *reinterpret_cast<uint32_t*>(&Vt[r0 * 136 + nl]) = packbf(v0x, v0y);
            *reinterpret_cast<uint32_t*>(&Vt[r1 * 136 + nl]) = packbf(v1x, v1y);
        }
    }

    #pragma unroll
    for (int l = 0; l < 8; l++) {
        int idx = tid + l * 256;
        int r = idx >> 3, ch = idx & 7;
        bool p = (m0 + r < NN);
        int row = p ? (m0 + r) : 0;
        cp16(&Et[r * 136 + ch * 16], &evcb[(size_t)row * KK + ch * 16], p);
    }
    CP_COMMIT(); CP_WAIT(0);
    __syncthreads();

    const uint32_t et_base = (uint32_t)__cvta_generic_to_shared(Et);
    const uint32_t vt_base = (uint32_t)__cvta_generic_to_shared(Vt);
    const int I = lane >> 3, rr = lane & 7;
    const uint32_t RS = 136 * 2;

    #pragma unroll
    for (int mf = 0; mf < 4; mf++)
        #pragma unroll
        for (int nf = 0; nf < 4; nf++)
            #pragma unroll
            for (int q = 0; q < 4; q++) acc[mf][nf][q] = 0.f;

    #pragma unroll
    for (int chunk = 0; chunk < 4; chunk++) {
        #pragma unroll
        for (int kk = 0; kk < 2; kk++) {
            uint32_t af[4][4], bf[4][2];
            #pragma unroll
            for (int mf = 0; mf < 4; mf++) {
                uint32_t addr = et_base
                    + (uint32_t)(chunk * 32 + kk * 16 + (I >> 1) * 8 + rr) * RS
                    + (uint32_t)(wm0 + mf * 16 + (I & 1) * 8) * 2;
                ldmat_x4t(af[mf], addr);
            }
            #pragma unroll
            for (int nf2 = 0; nf2 < 2; nf2++) {
                uint32_t tmp[4];
                uint32_t addr = vt_base
                    + (uint32_t)(chunk * 32 + kk * 16 + (I & 1) * 8 + rr) * RS
                    + (uint32_t)(wn0 + nf2 * 16 + (I >> 1) * 8) * 2;
                ldmat_x4t(tmp, addr);
                bf[nf2 * 2    ][0] = tmp[0]; bf[nf2 * 2    ][1] = tmp[1];
                bf[nf2 * 2 + 1][0] = tmp[2]; bf[nf2 * 2 + 1][1] = tmp[3];
            }
            #pragma unroll
            for (int mf = 0; mf < 4; mf++)
                #pragma unroll
                for (int nf = 0; nf < 4; nf++)
                    mma_bf16(acc[mf][nf], af[mf], bf[nf]);
        }
    }

    #pragma unroll
    for (int mf = 0; mf < 4; mf++) {
        int k0 = wm0 + mf * 16 + g;
        int k1 = k0 + 8;
        float s0 = fs[k0 * TJc + tb];
        float s1 = fs[k1 * TJc + tb];
        #pragma unroll
        for (int nf = 0; nf < 4; nf++) {
            int j = n0 + wn0 + nf * 8 + 2 * t;
            float* p0 = &u2[(size_t)k0 * DD + j];
            float* p1 = &u2[(size_t)k1 * DD + j];
            asm volatile("red.global.add.v2.f32 [%0], {%1,%2};"
                         :: "l"(p0), "f"(s0 * acc[mf][nf][0]), "f"(s0 * acc[mf][nf][1]) : "memory");
            asm volatile("red.global.add.v2.f32 [%0], {%1,%2};"
                         :: "l"(p1), "f"(s1 * acc[mf][nf][2]), "f"(s1 * acc[mf][nf][3]) : "memory");
        }
    }
}

// ---------------- tf32 GEMM (tiny 128-row GEMMs) -----------------------------
template <bool CVTA>
__global__ void __launch_bounds__(256, 2) tcgemm_k(
    const float* __restrict__ A, int lda,
    const float* __restrict__ B, int ldb,
    float* __restrict__ C, int ldc,
    int M, int Kd)
{
    extern __shared__ uint32_t dyn[];
    uint32_t (*As)[128][36]  = reinterpret_cast<uint32_t(*)[128][36]>(dyn);
    uint32_t (*Bs)[32][136]  = reinterpret_cast<uint32_t(*)[32][136]>(dyn + 2 * 128 * 36);

    const int m0 = blockIdx.y * 128;
    const int n0 = blockIdx.x * 128;
    const int tid = threadIdx.x;
    const int lane = tid & 31;
    const int wid = tid >> 5;
    const int g = lane >> 2, t = lane & 3;
    const int wm0 = (wid & 1) * 64;
    const int wn0 = (wid >> 1) * 32;

    float acc[4][4][4] = {};
    const int T = Kd >> 5;

    auto load_tiles = [&](int it, int s) {
        int k0 = it * 32;
        #pragma unroll
        for (int l = 0; l < 4; l++) {
            int idx = tid + l * 256;
            int r = idx >> 3, c = (idx & 7) * 4;
            bool p = (m0 + r < M);
            int row = p ? (m0 + r) : 0;
            cp16(&As[s][r][c], &A[(size_t)row * lda + k0 + c], p);
        }
        #pragma unroll
        for (int l = 0; l < 4; l++) {
            int idx = tid + l * 256;
            int r = idx >> 5, c = (idx & 31) * 4;
            cp16(&Bs[s][r][c], &B[(size_t)(k0 + r) * ldb + n0 + c], true);
        }
    };

    load_tiles(0, 0);
    CP_COMMIT();

    for (int i = 0; i < T; i++) {
        int cur = i & 1;
        if (i + 1 < T) { load_tiles(i + 1, cur ^ 1); CP_COMMIT(); CP_WAIT(1); }
        else          { CP_WAIT(0); }
        __syncthreads();
        #pragma unroll
        for (int kk = 0; kk < 4; kk++) {
            uint32_t af[4][4], bf[4][2];
            #pragma unroll
            for (int mf = 0; mf < 4; mf++) {
                int mr = wm0 + mf * 16;
                uint32_t a0 = As[cur][mr + g    ][kk * 8 + t];
                uint32_t a1 = As[cur][mr + g + 8][kk * 8 + t];
                uint32_t a2 = As[cur][mr + g    ][kk * 8 + t + 4];
                uint32_t a3 = As[cur][mr + g + 8][kk * 8 + t + 4];
                if (CVTA) { a0 = cvt_rna(a0); a1 = cvt_rna(a1); a2 = cvt_rna(a2); a3 = cvt_rna(a3); }
                af[mf][0] = a0; af[mf][1] = a1; af[mf][2] = a2; af[mf][3] = a3;
            }
            #pragma unroll
            for (int nf = 0; nf < 4; nf++) {
                bf[nf][0] = Bs[cur][kk * 8 + t    ][wn0 + nf * 8 + g];
                bf[nf][1] = Bs[cur][kk * 8 + t + 4][wn0 + nf * 8 + g];
            }
            #pragma unroll
            for (int mf = 0; mf < 4; mf++)
                #pragma unroll
                for (int nf = 0; nf < 4; nf++)
                    mma_tf32(acc[mf][nf], af[mf], bf[nf]);
        }
        __syncthreads();
    }

    #pragma unroll
    for (int mf = 0; mf < 4; mf++) {
        int row0 = m0 + wm0 + mf * 16 + g;
        int row1 = row0 + 8;
        #pragma unroll
        for (int nf = 0; nf < 4; nf++) {
            int n = n0 + wn0 + nf * 8 + 2 * t;
            float2 v0 = make_float2(acc[mf][nf][0], acc[mf][nf][1]);
            float2 v1 = make_float2(acc[mf][nf][2], acc[mf][nf][3]);
            if (row0 < M) *reinterpret_cast<float2*>(&C[(size_t)row0 * ldc + n]) = v0;
            if (row1 < M) *reinterpret_cast<float2*>(&C[(size_t)row1 * ldc + n]) = v1;
        }
    }
}

// ------- tf32 tall reduction (x path): C[128,cols] += evc^T * B -------------
#define ATB_BLKS 64
template <bool CVTB>
__global__ void __launch_bounds__(256, 2) atb_k(
    const float* __restrict__ evc,
    const float* __restrict__ B, int ldb,
    float* __restrict__ C, int ldc)
{
    extern __shared__ uint32_t dyn[];
    uint32_t (*Es)[32][136] = reinterpret_cast<uint32_t(*)[32][136]>(dyn);
    uint32_t (*Hs)[32][136] = reinterpret_cast<uint32_t(*)[32][136]>(dyn + 2 * 32 * 136);

    const int noff = blockIdx.y * 128;

    const int chunk = (NN + ATB_BLKS - 1) / ATB_BLKS;
    const int nStart = blockIdx.x * chunk;
    const int nEnd = min(nStart + chunk, NN);
    const int iters = (chunk + 31) / 32;
    const int tid = threadIdx.x;
    const int lane = tid & 31;
    const int wid = tid >> 5;
    const int g = lane >> 2, t = lane & 3;
    const int wm0 = (wid & 1) * 64;
    const int wn0 = (wid >> 1) * 32;

    float acc[4][4][4] = {};

    auto load_tiles = [&](int it, int s) {
        int n0 = nStart + it * 32;
        #pragma unroll
        for (int l = 0; l < 4; l++) {
            int idx = tid + l * 256;
            int r = idx >> 5, c = (idx & 31) * 4;
            bool p = (n0 + r < nEnd);
            int row = p ? (n0 + r) : 0;
            cp16(&Es[s][r][c], &evc[(size_t)row * KK + c], p);
            cp16(&Hs[s][r][c], &B[(size_t)row * ldb + noff + c], p);
        }
    };

    load_tiles(0, 0);
    CP_COMMIT();

    for (int i = 0; i < iters; i++) {
        int cur = i & 1;
        if (i + 1 < iters) { load_tiles(i + 1, cur ^ 1); CP_COMMIT(); CP_WAIT(1); }
        else              { CP_WAIT(0); }
        __syncthreads();
        #pragma unroll
        for (int kk = 0; kk < 4; kk++) {
            uint32_t af[4][4], bf[4][2];
            #pragma unroll
            for (int mf = 0; mf < 4; mf++) {
                int mc = wm0 + mf * 16;
                af[mf][0] = Es[cur][kk * 8 + t    ][mc + g];
                af[mf][1] = Es[cur][kk * 8 + t    ][mc + g + 8];
                af[mf][2] = Es[cur][kk * 8 + t + 4][mc + g];
                af[mf][3] = Es[cur][kk * 8 + t + 4][mc + g + 8];
            }
            #pragma unroll
            for (int nf = 0; nf < 4; nf++) {
                uint32_t b0 = Hs[cur][kk * 8 + t    ][wn0 + nf * 8 + g];
                uint32_t b1 = Hs[cur][kk * 8 + t + 4][wn0 + nf * 8 + g];
                if (CVTB) { b0 = cvt_rna(b0); b1 = cvt_rna(b1); }
                bf[nf][0] = b0; bf[nf][1] = b1;
            }
            #pragma unroll
            for (int mf = 0; mf < 4; mf++)
                #pragma unroll
                for (int nf = 0; nf < 4; nf++)
                    mma_tf32(acc[mf][nf], af[mf], bf[nf]);
        }
        __syncthreads();
    }

    #pragma unroll
    for (int mf = 0; mf < 4; mf++) {
        int row0 = wm0 + mf * 16 + g;
        #pragma unroll
        for (int nf = 0; nf < 4; nf++) {
            int n = noff + wn0 + nf * 8 + 2 * t;
            float* p0 = &C[(size_t)row0 * ldc + n];
            float* p1 = &C[(size_t)(row0 + 8) * ldc + n];
            asm volatile("red.global.add.v2.f32 [%0], {%1,%2};"
                         :: "l"(p0), "f"(acc[mf][nf][0]), "f"(acc[mf][nf][1]) : "memory");
            asm volatile("red.global.add.v2.f32 [%0], {%1,%2};"
                         :: "l"(p1), "f"(acc[mf][nf][2]), "f"(acc[mf][nf][3]) : "memory");
        }
    }
}

// ---------------- graph: CSR build + gather ----------------------------------
__global__ void degi_k(const void* __restrict__ ei) {
    int e = blockIdx.x * blockDim.x + threadIdx.x;
    if (e < EE) atomicAdd(&g_degi[edge_at(ei, (long long)EE + e)], 1);
}
__global__ void dinv_k() {
    int n = blockIdx.x * blockDim.x + threadIdx.x;
    if (n < NN) g_deg[n] = rsqrtf((float)g_degi[n] + 1.0f);
}
__global__ void scan_k() {
    __shared__ int s[1024];
    int tid = threadIdx.x;
    const int per = (NN + 1023) / 1024;
    int start = tid * per, end = min(start + per, NN);
    int sum = 0;
    for (int i = start; i < end; i++) sum += g_degi[i];
    s[tid] = sum;
    __syncthreads();
    for (int off = 1; off < 1024; off <<= 1) {
        int v = 0;
        if (tid >= off) v = s[tid - off];
        __syncthreads();
        if (tid >= off) s[tid] += v;
        __syncthreads();
    }
    int base = s[tid] - sum;
    for (int i = start; i < end; i++) {
        g_off[i] = base; g_cur[i] = base;
        base += g_degi[i];
    }
    if (tid == 1023) g_off[NN] = base;
}
__global__ void fill_k(const void* __restrict__ ei) {
    int e = blockIdx.x * blockDim.x + threadIdx.x;
    if (e >= EE) return;
    int src = edge_at(ei, e);
    int dst = edge_at(ei, (long long)EE + e);
    int pos = atomicAdd(&g_cur[dst], 1);
    g_csrc[pos] = src;
}
__global__ void __launch_bounds__(128) gather_k(const float* __restrict__ x,
                                                const float* __restrict__ gcn_b) {
    const int n = blockIdx.x;
    const int c = threadIdx.x * 4;
    const int s0 = g_off[n], s1 = g_off[n + 1];
    const float dv = g_deg[n];
    float4 acc = make_float4(0.f, 0.f, 0.f, 0.f);
    int e = s0;
    #pragma unroll 1
    for (; e + 2 <= s1; e += 2) {
        int srcA = g_csrc[e], srcB = g_csrc[e + 1];
        float nA = dv * g_deg[srcA], nB = dv * g_deg[srcB];
        float4 vA = *reinterpret_cast<const float4*>(&g_xw[(size_t)srcA * DD + c]);
        float4 vB = *reinterpret_cast<const float4*>(&g_xw[(size_t)srcB * DD + c]);
        acc.x += nA * vA.x + nB * vB.x;
        acc.y += nA * vA.y + nB * vB.y;
        acc.z += nA * vA.z + nB * vB.z;
        acc.w += nA * vA.w + nB * vB.w;
    }
    if (e < s1) {
        int src = g_csrc[e];
        float nrm = dv * g_deg[src];
        float4 v = *reinterpret_cast<const float4*>(&g_xw[(size_t)src * DD + c]);
        acc.x += nrm * v.x; acc.y += nrm * v.y; acc.z += nrm * v.z; acc.w += nrm * v.w;
    }
    float4 xw = *reinterpret_cast<const float4*>(&g_xw[(size_t)n * DD + c]);
    float4 xr = *reinterpret_cast<const float4*>(&x[(size_t)n * DD + c]);
    float4 bb = *reinterpret_cast<const float4*>(&gcn_b[c]);
    float d2 = dv * dv;
    float4 o;
    o.x = xr.x + acc.x + d2 * xw.x + bb.x;
    o.y = xr.y + acc.y + d2 * xw.y + bb.y;
    o.z = xr.z + acc.z + d2 * xw.z + bb.z;
    o.w = xr.w + acc.w + d2 * xw.w + bb.w;
    *reinterpret_cast<float4*>(&g_bufL[(size_t)n * DD + c]) = o;
}
__global__ void stats0_k() {
    const int c = threadIdx.x;
    const int r0 = blockIdx.x * 128;
    const int rEnd = min(r0 + 128, NN);
    float s = 0.f, s2 = 0.f;
    for (int r = r0; r < rEnd; r++) {
        float v = g_bufL[(size_t)r * DD + c];
        s += v; s2 += v * v;
    }
    atomicAdd(&g_stats[0 * DD + c], s);
    atomicAdd(&g_stats[1 * DD + c], s2);
}

__global__ void finalize01_k(const float* __restrict__ g0, const float* __restrict__ b0,
                             const float* __restrict__ g1, const float* __restrict__ b1) {
    int bn = blockIdx.x;
    const float* gamma = bn ? g1 : g0;
    const float* beta  = bn ? b1 : b0;
    int c = threadIdx.x;
    float s  = g_stats[(bn * 2 + 0) * DD + c];
    float s2 = g_stats[(bn * 2 + 1) * DD + c];
    float m = s * (1.0f / NN);
    float var = s2 * (1.0f / NN) - m * m;
    float a = gamma[c] * rsqrtf(var + EPSC);
    g_coef[(bn * 2 + 0) * DD + c] = a;
    g_coef[(bn * 2 + 1) * DD + c] = beta[c] - m * a;
}
__global__ void finalize_k(int bn, const float* __restrict__ gamma, const float* __restrict__ beta) {
    int c = threadIdx.x;
    float s  = g_stats[(bn * 2 + 0) * DD + c];
    float s2 = g_stats[(bn * 2 + 1) * DD + c];
    float m = s * (1.0f / NN);
    float var = s2 * (1.0f / NN) - m * m;
    float a = gamma[c] * rsqrtf(var + EPSC);
    g_coef[(bn * 2 + 0) * DD + c] = a;
    g_coef[(bn * 2 + 1) * DD + c] = beta[c] - m * a;
}

__global__ void apply_sum_k() {
    int i = blockIdx.x * blockDim.x + threadIdx.x;
    if (i >= NN * DD / 4) return;
    int base = i * 4;
    int c = base & (DD - 1);
    float4 bl = *reinterpret_cast<const float4*>(&g_bufL[base]);
    float4 ba = *reinterpret_cast<const float4*>(&g_bufA[base]);
    float4 a0 = *reinterpret_cast<const float4*>(&g_coef[c]);
    float4 b0 = *reinterpret_cast<const float4*>(&g_coef[DD + c]);
    float4 a1 = *reinterpret_cast<const float4*>(&g_coef[2 * DD + c]);
    float4 b1 = *reinterpret_cast<const float4*>(&g_coef[3 * DD + c]);
    float4 v;
    v.x = bl.x * a0.x + b0.x + ba.x * a1.x + b1.x;
    v.y = bl.y * a0.y + b0.y + ba.y * a1.y + b1.y;
    v.z = bl.z * a0.z + b0.z + ba.z * a1.z + b1.z;
    v.w = bl.w * a0.w + b0.w + ba.w * a1.w + b1.w;
    *reinterpret_cast<float4*>(&g_h[base]) = v;
    uint2 p = make_uint2(packbf(v.x, v.y), packbf(v.z, v.w));
    *reinterpret_cast<uint2*>(&g_hb[base]) = p;
}
__global__ void bn2_apply_k(float* __restrict__ out) {
    int i = blockIdx.x * blockDim.x + threadIdx.x;
    if (i >= NN * DD / 4) return;
    int base = i * 4;
    int c = base & (DD - 1);
    float4 f = *reinterpret_cast<const float4*>(&g_ff[base]);
    float4 a = *reinterpret_cast<const float4*>(&g_coef[4 * DD + c]);
    float4 b = *reinterpret_cast<const float4*>(&g_coef[5 * DD + c]);
    float4 v;
    v.x = f.x * a.x + b.x;
    v.y = f.y * a.y + b.y;
    v.z = f.z * a.z + b.z;
    v.w = f.w * a.w + b.w;
    *reinterpret_cast<float4*>(&out[base]) = v;
}

// ---------------- wave helpers ----------------------------------------------
__global__ void pack_w_k(const float* __restrict__ linW, const float* __restrict__ fW) {
    int idx = blockIdx.x * blockDim.x + threadIdx.x;
    if (idx >= DD * DD) return;
    int d = idx >> 9, j = idx & 511;
    int t = j >> 7, s = j & 127;
    g_linWp[idx] = tf32r(linW[t * (DD * SSc) + d * SSc + s]);
    g_fWt[idx]   = tf32r(fW[idx]);
}
__global__ void post_u_k(const float* __restrict__ fs, const float* __restrict__ linB) {
    int idx = blockIdx.x * blockDim.x + threadIdx.x;
    if (idx >= (KK / 2) * DD) return;
    int kp = idx >> 9, j = idx & 511;
    int t = j >> 7, s = j & 127;
    float bl = linB[t * SSc + s];
    int k0 = 2 * kp, k1 = 2 * kp + 1;
    float v0 = fs[k0 * TJc + t] * (g_uraw[k0 * DD + j] + g_esum[k0] * bl);
    float v1 = fs[k1 * TJc + t] * (g_uraw[k1 * DD + j] + g_esum[k1] * bl);
    g_ubp[idx] = packbf(v0, v1);
}

// ---------------- streams/events ----------------------------------------------
static cudaStream_t s_gcn = nullptr, s_aux = nullptr;
static cudaEvent_t ev_fork = nullptr, ev_xw = nullptr, ev_join = nullptr, ev_aux = nullptr;
namespace { struct StreamInit {
    StreamInit() {
        cudaStreamCreateWithFlags(&s_gcn, cudaStreamNonBlocking);
        cudaStreamCreateWithFlags(&s_aux, cudaStreamNonBlocking);
        cudaEventCreateWithFlags(&ev_fork, cudaEventDisableTiming);
        cudaEventCreateWithFlags(&ev_xw,   cudaEventDisableTiming);
        cudaEventCreateWithFlags(&ev_join, cudaEventDisableTiming);
        cudaEventCreateWithFlags(&ev_aux,  cudaEventDisableTiming);
    }
} s_init; }

// ---------------- launch -----------------------------------------------------
#define GSYM(p, ty, s) do { void* _t; cudaGetSymbolAddress(&_t, s); (p) = (ty)_t; } while (0)

extern "C" void kernel_launch(void* const* d_in, const int* in_sizes, int n_in,
                              void* d_out, int out_size) {
    const float* x        = (const float*)d_in[0];
    const void*  ei       = d_in[1];
    const float* evc      = (const float*)d_in[2];
    const float* fs       = (const float*)d_in[3];
    const float* gcn_W    = (const float*)d_in[4];
    const float* gcn_b    = (const float*)d_in[5];
    const float* lin_W    = (const float*)d_in[6];
    const float* lin_b    = (const float*)d_in[7];
    const float* fusion_W = (const float*)d_in[8];
    const float* fusion_b = (const float*)d_in[9];
    const float* bn1l_g   = (const float*)d_in[10];
    const float* bn1l_b   = (const float*)d_in[11];
    const float* bn1a_g   = (const float*)d_in[12];
    const float* bn1a_b   = (const float*)d_in[13];
    const float* bn2_g    = (const float*)d_in[14];
    const float* bn2_b    = (const float*)d_in[15];
    const float* ff1_W    = (const float*)d_in[16];
    const float* ff1_b    = (const float*)d_in[17];
    const float* ff2_W    = (const float*)d_in[18];
    const float* ff2_b    = (const float*)d_in[19];
    float* out = (float*)d_out;

    float *p_xw, *p_bufL, *p_bufA, *p_h, *p_ff, *p_evct;
    float *p_xe, *p_uraw, *p_u2, *p_W2, *p_linWp, *p_fWt;
    __nv_bfloat16 *p_xb, *p_evcb, *p_hb, *p_midb;
    uint32_t *p_gWbp, *p_f1Wbp, *p_f2Wbp, *p_W2bp, *p_ubp;
    GSYM(p_xw, float*, g_xw);     GSYM(p_bufL, float*, g_bufL);
    GSYM(p_bufA, float*, g_bufA); GSYM(p_h, float*, g_h);       GSYM(p_ff, float*, g_ff);
    GSYM(p_evct, float*, g_evct);
    GSYM(p_xe, float*, g_xe);     GSYM(p_uraw, float*, g_uraw);
    GSYM(p_u2, float*, g_u2);     GSYM(p_W2, float*, g_W2);
    GSYM(p_linWp, float*, g_linWp); GSYM(p_fWt, float*, g_fWt);
    GSYM(p_xb, __nv_bfloat16*, g_xb);   GSYM(p_evcb, __nv_bfloat16*, g_evcb);
    GSYM(p_hb, __nv_bfloat16*, g_hb);   GSYM(p_midb, __nv_bfloat16*, g_midb);
    GSYM(p_gWbp, uint32_t*, g_gWbp);    GSYM(p_f1Wbp, uint32_t*, g_f1Wbp);
    GSYM(p_f2Wbp, uint32_t*, g_f2Wbp);  GSYM(p_W2bp, uint32_t*, g_W2bp);
    GSYM(p_ubp, uint32_t*, g_ubp);

    const int GEMM_SMEM = (2 * 128 * 36 + 2 * 32 * 136) * 4;   // 71680
    const int BF_SMEM   = GEMM_SMEM;
    const int ATB_SMEM  = (2 * 32 * 136 * 2) * 4;
    cudaFuncSetAttribute(tcgemm_k<false>, cudaFuncAttributeMaxDynamicSharedMemorySize, GEMM_SMEM);
    cudaFuncSetAttribute(tcgemm_k<true>,  cudaFuncAttributeMaxDynamicSharedMemorySize, GEMM_SMEM);
    cudaFuncSetAttribute(atb_k<true>,  cudaFuncAttributeMaxDynamicSharedMemorySize, ATB_SMEM);
    cudaFuncSetAttribute(vfused_k, cudaFuncAttributeMaxDynamicSharedMemorySize, BF_SMEM);
    cudaFuncSetAttribute(bfgemm_k<false, false, false, false, false>, cudaFuncAttributeMaxDynamicSharedMemorySize, BF_SMEM);
    cudaFuncSetAttribute(bfgemm_k<true,  true,  false, false, true >, cudaFuncAttributeMaxDynamicSharedMemorySize, BF_SMEM);
    cudaFuncSetAttribute(bfgemm_k<true,  true,  false, true,  false>, cudaFuncAttributeMaxDynamicSharedMemorySize, BF_SMEM);
    cudaFuncSetAttribute(bfgemm_k<true,  false, false, false, true >, cudaFuncAttributeMaxDynamicSharedMemorySize, BF_SMEM);

    const int MB = (NN + 127) / 128;
    dim3 gD(4, MB);
    dim3 gF(8, MB);
    dim3 gTiny(4, 1);
    dim3 gAtbX(ATB_BLKS, 4, 1);

    zero_scratch_k<<<1024, 256>>>((const int*)ei);

    // ---- fork ----
    cudaEventRecord(ev_fork, 0);
    cudaStreamWaitEvent(s_gcn, ev_fork, 0);
    cudaStreamWaitEvent(s_aux, ev_fork, 0);

    // s_gcn: CSR build
    degi_k<<<(EE + 255) / 256, 256, 0, s_gcn>>>(ei);
    dinv_k<<<(NN + 255) / 256, 256, 0, s_gcn>>>();
    scan_k<<<1, 1024, 0, s_gcn>>>();
    fill_k<<<(EE + 255) / 256, 256, 0, s_gcn>>>(ei);

    // s_aux: weight packs + evc prep (off the critical path)
    pack_w_k<<<(DD * DD + 255) / 256, 256, 0, s_aux>>>(lin_W, fusion_W);
    packpairs_k<<<((DD / 2) * DD2 + 255) / 256, 256, 0, s_aux>>>(ff1_W, p_f1Wbp, DD2, (DD / 2) * DD2);
    packpairs_k<<<((DD2 / 2) * DD + 255) / 256, 256, 0, s_aux>>>(ff2_W, p_f2Wbp, DD, (DD2 / 2) * DD);
    prep_evc_k<<<(NN + 249) / 250, KK, 0, s_aux>>>(evc);
    cudaEventRecord(ev_aux, s_aux);

    // main: prep + xw GEMM
    packpairs_k<<<((DD / 2) * DD + 255) / 256, 256>>>(gcn_W, p_gWbp, DD, (DD / 2) * DD);
    tobf_k<<<1024, 256>>>(x, p_xb, (long long)NN * DD);
    bfgemm_k<false, false, false, false, false><<<gD, 256, BF_SMEM>>>(
        p_xb, DD, p_gWbp, DD, 0, p_xw, DD, 0, nullptr, NN, DD, nullptr, 0);
    cudaEventRecord(ev_xw, 0);

    // s_gcn: gather + BN0 stats
    cudaStreamWaitEvent(s_gcn, ev_xw, 0);
    gather_k<<<NN, 128, 0, s_gcn>>>(x, gcn_b);
    stats0_k<<<MB, DD, 0, s_gcn>>>();
    cudaEventRecord(ev_join, s_gcn);

    // main: wave branch (waits for evc prep + weight packs)
    cudaStreamWaitEvent(0, ev_aux, 0);
    atb_k<true><<<gAtbX, 256, ATB_SMEM>>>(p_evct, x, DD, p_xe, DD);
    tcgemm_k<true><<<gTiny, 256, GEMM_SMEM>>>(p_xe, DD, p_linWp, DD, p_uraw, DD, KK, DD);
    post_u_k<<<((KK / 2) * DD + 255) / 256, 256>>>(fs, lin_b);
    vfused_k<<<gD, 256, BF_SMEM>>>(p_evcb, p_ubp, fs, p_u2);
    tcgemm_k<true><<<gTiny, 256, GEMM_SMEM>>>(p_u2, DD, p_fWt, DD, p_W2, DD, KK, DD);
    packpairs_k<<<((KK / 2) * DD + 255) / 256, 256>>>(p_W2, p_W2bp, DD, (KK / 2) * DD);
    bfgemm_k<true, true, false, false, true><<<gD, 256, BF_SMEM>>>(
        p_evcb, KK, p_W2bp, DD, 0, p_bufA, DD, 0, fusion_b, NN, KK, x, 1);

    // ---- join + BN ----
    cudaStreamWaitEvent(0, ev_join, 0);
    finalize01_k<<<2, DD>>>(bn1l_g, bn1l_b, bn1a_g, bn1a_b);
    apply_sum_k<<<(NN * DD / 4 + 255) / 256, 256>>>();

    // ---- feed-forward ----
    bfgemm_k<true, true, false, true, false><<<gF, 256, BF_SMEM>>>(
        p_hb, DD, p_f1Wbp, DD2, 0, p_midb, DD2, 0, ff1_b, NN, DD, nullptr, 0);
    bfgemm_k<true, false, false, false, true><<<gD, 256, BF_SMEM>>>(
        p_midb, DD2, p_f2Wbp, DD, 0, p_ff, DD, 0, ff2_b, NN, DD2, p_h, 2);
    finalize_k<<<1, DD>>>(2, bn2_g, bn2_b);
    bn2_apply_k<<<(NN * DD / 4 + 255) / 256, 256>>>(out);
}